// round 13
// baseline (speedup 1.0000x reference)
#include <cuda_runtime.h>
#include <cuda_fp16.h>
#include <cuda_bf16.h>
#include <math.h>

#define Tn 2048
#define Cn 384
#define Hn 6
#define HDn 64
#define Bn 2
#define BHn 12
#define ROWS 4096
#define C1 385
#define KA_LN 416
#define N3 1152
#define N4 1536
#define LOGT 7.62461899f
#define WSCALE 512.f
#define WINV   (1.f / 512.f)
#define GP 512          // persistent grid size

#define WOFF_QKV 0
#define WSZ_QKV  (KA_LN * N3)
#define WOFF_PRJ (WOFF_QKV + WSZ_QKV)
#define WSZ_PRJ  (Cn * Cn)
#define WOFF_FC  (WOFF_PRJ + WSZ_PRJ)
#define WSZ_FC   (KA_LN * N4)
#define WOFF_FC2 (WOFF_FC + WSZ_FC)
#define WSZ_FC2  (N4 * Cn)
#define WTOTAL   (WOFF_FC2 + WSZ_FC2)

// ---------------- scratch ----------------
__device__ __align__(16) float g_qkv[ROWS * N3];
__device__ __align__(16) __half g_e[(size_t)BHn * Tn * Tn];
__device__ __align__(16) __half g_c[(size_t)BHn * Tn * Tn];
__device__ __align__(16) __nv_bfloat16 g_qh[ROWS * Cn];
__device__ __align__(16) __nv_bfloat16 g_ql[ROWS * Cn];
__device__ __align__(16) __nv_bfloat16 g_kh[ROWS * Cn];
__device__ __align__(16) __nv_bfloat16 g_kl[ROWS * Cn];
__device__ __align__(16) __half g_wh[BHn * Tn * HDn];
__device__ __align__(16) __half g_wl[BHn * Tn * HDn];
__device__ float g_rowsum[BHn * Tn];
__device__ float g_eu[BHn * Tn];
__device__ float g_ev[BHn * Tn];
__device__ float g_tots[8 * BHn];
__device__ float g_wtot[BHn * HDn];
__device__ __align__(16) float g_cpart[8 * BHn * Tn];
__device__ __align__(16) float g_h[ROWS * Cn];
__device__ __align__(16) __nv_bfloat16 g_ah[ROWS * N4];
__device__ __align__(16) __nv_bfloat16 g_al[ROWS * N4];
__device__ __align__(16) __nv_bfloat16 g_a2h[ROWS * N4];
__device__ __align__(16) __nv_bfloat16 g_a2l[ROWS * N4];
__device__ __align__(16) __nv_bfloat16 g_bh[WTOTAL];
__device__ __align__(16) __nv_bfloat16 g_bl[WTOTAL];
__device__ int g_barc;
__device__ int g_bars;

// ---------------- helpers ----------------
__device__ __forceinline__ void ldmx4(unsigned addr, unsigned& r0, unsigned& r1, unsigned& r2, unsigned& r3) {
    asm volatile("ldmatrix.sync.aligned.m8n8.x4.shared.b16 {%0,%1,%2,%3},[%4];"
                 : "=r"(r0), "=r"(r1), "=r"(r2), "=r"(r3) : "r"(addr));
}
__device__ __forceinline__ void ldmx4t(unsigned addr, unsigned& r0, unsigned& r1, unsigned& r2, unsigned& r3) {
    asm volatile("ldmatrix.sync.aligned.m8n8.x4.trans.shared.b16 {%0,%1,%2,%3},[%4];"
                 : "=r"(r0), "=r"(r1), "=r"(r2), "=r"(r3) : "r"(addr));
}
__device__ __forceinline__ void mma_bf16(float* c, unsigned a0, unsigned a1, unsigned a2, unsigned a3,
                                         unsigned b0, unsigned b1) {
    asm volatile("mma.sync.aligned.m16n8k16.row.col.f32.bf16.bf16.f32 "
                 "{%0,%1,%2,%3},{%4,%5,%6,%7},{%8,%9},{%0,%1,%2,%3};"
                 : "+f"(c[0]), "+f"(c[1]), "+f"(c[2]), "+f"(c[3])
                 : "r"(a0), "r"(a1), "r"(a2), "r"(a3), "r"(b0), "r"(b1));
}
__device__ __forceinline__ void mma_f16(float* c, unsigned a0, unsigned a1, unsigned a2, unsigned a3,
                                        unsigned b0, unsigned b1) {
    asm volatile("mma.sync.aligned.m16n8k16.row.col.f32.f16.f16.f32 "
                 "{%0,%1,%2,%3},{%4,%5,%6,%7},{%8,%9},{%0,%1,%2,%3};"
                 : "+f"(c[0]), "+f"(c[1]), "+f"(c[2]), "+f"(c[3])
                 : "r"(a0), "r"(a1), "r"(a2), "r"(a3), "r"(b0), "r"(b1));
}
__device__ __forceinline__ void cpa16(unsigned dst, const void* src) {
    asm volatile("cp.async.cg.shared.global [%0],[%1],16;" :: "r"(dst), "l"(src));
}
#define CPA_COMMIT asm volatile("cp.async.commit_group;")
#define CPA_WAIT1  asm volatile("cp.async.wait_group 1;")

__device__ __forceinline__ float em1p(float x) {
    float t = fmaf(x, 0.125f, 1.f);
    t = fmaf(x * 0.14285714f, t, 1.f);
    t = fmaf(x * 0.16666667f, t, 1.f);
    t = fmaf(x * 0.2f,        t, 1.f);
    t = fmaf(x * 0.25f,       t, 1.f);
    t = fmaf(x * 0.33333333f, t, 1.f);
    t = fmaf(x * 0.5f,        t, 1.f);
    return x * t;
}

// global barrier for persistent kernel (monotone counter, all GP blocks resident)
__device__ __forceinline__ void gbar(int target) {
    __syncthreads();
    if (threadIdx.x == 0) {
        __threadfence();
        int arrived = atomicAdd(&g_barc, 1) + 1;
        if (arrived == target * GP) {
            atomicExch(&g_bars, target);
        } else {
            while (atomicAdd(&g_bars, 0) < target) {}
        }
        __threadfence();
    }
    __syncthreads();
}

// ---------------- zero ----------------
__global__ void zero_misc() {
    int i = blockIdx.x * 256 + threadIdx.x;
    if (i < BHn * Tn) g_rowsum[i] = 0.f;
    if (i < BHn * HDn) g_wtot[i] = 0.f;
    if (i < 8 * BHn) g_tots[i] = 0.f;
    if (i == 0) { g_barc = 0; g_bars = 0; }
}

// ---------------- weights -> bf16 hi/lo ----------------
__global__ void conv_w_all(const float* __restrict__ w0, const float* __restrict__ w1,
                           const float* __restrict__ w2, const float* __restrict__ w3) {
    int idx = blockIdx.x * 256 + threadIdx.x;
    int e = idx * 4;
    if (e >= WTOTAL) return;
    const float* src;
    int K, N, local;
    if (e < WOFF_PRJ)       { src = w0; K = C1;  N = N3; local = e - WOFF_QKV; }
    else if (e < WOFF_FC)   { src = w1; K = Cn;  N = Cn; local = e - WOFF_PRJ; }
    else if (e < WOFF_FC2)  { src = w2; K = C1;  N = N4; local = e - WOFF_FC;  }
    else                    { src = w3; K = N4;  N = Cn; local = e - WOFF_FC2; }
    int row = local / N, col = local % N;
    float4 v = (row < K) ? *(const float4*)(src + (size_t)row * N + col)
                         : make_float4(0.f, 0.f, 0.f, 0.f);
    __nv_bfloat16 h0 = __float2bfloat16(v.x), h1 = __float2bfloat16(v.y);
    __nv_bfloat16 h2 = __float2bfloat16(v.z), h3 = __float2bfloat16(v.w);
    __nv_bfloat16 hbuf[4] = {h0, h1, h2, h3};
    __nv_bfloat16 lbuf[4] = {
        __float2bfloat16(v.x - __bfloat162float(h0)), __float2bfloat16(v.y - __bfloat162float(h1)),
        __float2bfloat16(v.z - __bfloat162float(h2)), __float2bfloat16(v.w - __bfloat162float(h3))};
    *(uint2*)(g_bh + e) = *(uint2*)hbuf;
    *(uint2*)(g_bl + e) = *(uint2*)lbuf;
}

// ---------------- LayerNorm -> bf16 hi/lo ----------------
__global__ void ln_bf(const float* __restrict__ x, const float* __restrict__ t,
                      const float* __restrict__ w, const float* __restrict__ bb,
                      __nv_bfloat16* __restrict__ oh, __nv_bfloat16* __restrict__ ol) {
    int row = blockIdx.x;
    int tid = threadIdx.x;
    __shared__ float sx[C1];
    __shared__ float red[256];
    float s1 = 0.f;
    for (int c = tid; c < C1; c += 256) {
        float v = (c < Cn) ? x[(size_t)row * Cn + c] : t[0];
        sx[c] = v;
        s1 += v;
    }
    red[tid] = s1; __syncthreads();
    for (int o = 128; o > 0; o >>= 1) { if (tid < o) red[tid] += red[tid + o]; __syncthreads(); }
    float mean = red[0] * (1.f / C1);
    __syncthreads();
    float s2 = 0.f;
    for (int c = tid; c < C1; c += 256) { float d = sx[c] - mean; s2 += d * d; }
    red[tid] = s2; __syncthreads();
    for (int o = 128; o > 0; o >>= 1) { if (tid < o) red[tid] += red[tid + o]; __syncthreads(); }
    float rs = rsqrtf(red[0] * (1.f / C1) + 1e-5f);
    for (int c = tid; c < C1; c += 256) {
        float v = (sx[c] - mean) * rs * w[c] + bb[c];
        __nv_bfloat16 hi = __float2bfloat16(v);
        oh[(size_t)row * KA_LN + c] = hi;
        ol[(size_t)row * KA_LN + c] = __float2bfloat16(v - __bfloat162float(hi));
    }
    if (tid < KA_LN - C1) {
        oh[(size_t)row * KA_LN + C1 + tid] = __float2bfloat16(0.f);
        ol[(size_t)row * KA_LN + C1 + tid] = __float2bfloat16(0.f);
    }
}

// ---------------- unified pipelined bf16 GEMM, 64x128 tile ----------------
__global__ void __launch_bounds__(256) gemm64u(const __nv_bfloat16* __restrict__ Ah,
                                               const __nv_bfloat16* __restrict__ Al,
                                               const __nv_bfloat16* __restrict__ Bh,
                                               const __nv_bfloat16* __restrict__ Bl,
                                               const float* __restrict__ bias,
                                               float* __restrict__ outF,
                                               __nv_bfloat16* __restrict__ oAh,
                                               __nv_bfloat16* __restrict__ oAl,
                                               int M, int N, int Ka, int act, int obf) {
    extern __shared__ __nv_bfloat16 dyn[];
    __nv_bfloat16* sA = dyn;
    __nv_bfloat16* sB = dyn + 4 * 2560;
    int tid = threadIdx.x;
    int wid = tid >> 5, lane = tid & 31;
    int wm = wid & 1, wn = wid >> 1;
    int bm = blockIdx.y * 64, bn = blockIdx.x * 128;
    float acc[2][4][4] = {};
    unsigned sAu = (unsigned)__cvta_generic_to_shared(sA);
    unsigned sBu = (unsigned)__cvta_generic_to_shared(sB);

    int nk = Ka >> 5;
    auto load_stage = [&](int kt, int st) {
        unsigned aH = sAu + (st * 2 + 0) * 2560 * 2;
        unsigned aL = sAu + (st * 2 + 1) * 2560 * 2;
        unsigned bH = sBu + (st * 2 + 0) * 4352 * 2;
        unsigned bL = sBu + (st * 2 + 1) * 4352 * 2;
        int k0 = kt * 32;
        {
            int row = tid >> 2, cq = (tid & 3) * 8;
            cpa16(aH + (row * 40 + cq) * 2, Ah + (size_t)(bm + row) * Ka + k0 + cq);
            cpa16(aL + (row * 40 + cq) * 2, Al + (size_t)(bm + row) * Ka + k0 + cq);
        }
        #pragma unroll
        for (int z = 0; z < 2; z++) {
            int idx = z * 256 + tid;
            int row = idx >> 4, cq = (idx & 15) * 8;
            cpa16(bH + (row * 136 + cq) * 2, Bh + (size_t)(k0 + row) * N + bn + cq);
            cpa16(bL + (row * 136 + cq) * 2, Bl + (size_t)(k0 + row) * N + bn + cq);
        }
    };

    load_stage(0, 0);
    CPA_COMMIT;
    for (int kt = 0; kt < nk; kt++) {
        int cur = kt & 1;
        if (kt + 1 < nk) load_stage(kt + 1, cur ^ 1);
        CPA_COMMIT;
        CPA_WAIT1;
        __syncthreads();
        unsigned aH = sAu + (cur * 2 + 0) * 2560 * 2;
        unsigned aL = sAu + (cur * 2 + 1) * 2560 * 2;
        unsigned bH = sBu + (cur * 2 + 0) * 4352 * 2;
        unsigned bL = sBu + (cur * 2 + 1) * 4352 * 2;
        #pragma unroll
        for (int kh = 0; kh < 32; kh += 16) {
            unsigned ah[2][4], al[2][4];
            #pragma unroll
            for (int mt = 0; mt < 2; mt++) {
                unsigned off = ((unsigned)((wm * 32 + mt * 16 + (lane & 15)) * 40 + kh + (lane >> 4) * 8)) * 2;
                ldmx4(aH + off, ah[mt][0], ah[mt][1], ah[mt][2], ah[mt][3]);
                ldmx4(aL + off, al[mt][0], al[mt][1], al[mt][2], al[mt][3]);
            }
            #pragma unroll
            for (int np = 0; np < 2; np++) {
                int n0 = wn * 32 + np * 16;
                unsigned boff = ((unsigned)((kh + (lane & 7) + 8 * ((lane >> 3) & 1)) * 136 + n0 + 8 * (lane >> 4))) * 2;
                unsigned bh0, bh1, bh2, bh3, bl0, bl1, bl2, bl3;
                ldmx4t(bH + boff, bh0, bh1, bh2, bh3);
                ldmx4t(bL + boff, bl0, bl1, bl2, bl3);
                #pragma unroll
                for (int mt = 0; mt < 2; mt++) {
                    mma_bf16(acc[mt][2 * np],     ah[mt][0], ah[mt][1], ah[mt][2], ah[mt][3], bh0, bh1);
                    mma_bf16(acc[mt][2 * np],     ah[mt][0], ah[mt][1], ah[mt][2], ah[mt][3], bl0, bl1);
                    mma_bf16(acc[mt][2 * np],     al[mt][0], al[mt][1], al[mt][2], al[mt][3], bh0, bh1);
                    mma_bf16(acc[mt][2 * np + 1], ah[mt][0], ah[mt][1], ah[mt][2], ah[mt][3], bh2, bh3);
                    mma_bf16(acc[mt][2 * np + 1], ah[mt][0], ah[mt][1], ah[mt][2], ah[mt][3], bl2, bl3);
                    mma_bf16(acc[mt][2 * np + 1], al[mt][0], al[mt][1], al[mt][2], al[mt][3], bh2, bh3);
                }
            }
        }
        __syncthreads();
    }
    #pragma unroll
    for (int mt = 0; mt < 2; mt++) {
        #pragma unroll
        for (int nt = 0; nt < 4; nt++) {
            float* cc = acc[mt][nt];
            int r = bm + wm * 32 + mt * 16 + (lane >> 2);
            int cn = bn + wn * 32 + (nt >> 1) * 16 + (nt & 1) * 8 + (lane & 3) * 2;
            float b0 = bias[cn], b1 = bias[cn + 1];
            float v0 = cc[0] + b0, v1 = cc[1] + b1;
            float v2 = cc[2] + b0, v3 = cc[3] + b1;
            if (act == 1) {
                v0 = 0.5f * v0 * (1.f + erff(v0 * 0.70710678f));
                v1 = 0.5f * v1 * (1.f + erff(v1 * 0.70710678f));
                v2 = 0.5f * v2 * (1.f + erff(v2 * 0.70710678f));
                v3 = 0.5f * v3 * (1.f + erff(v3 * 0.70710678f));
            }
            if (obf == 1) {
                __nv_bfloat16 h0 = __float2bfloat16(v0), h1 = __float2bfloat16(v1);
                __nv_bfloat16 h2 = __float2bfloat16(v2), h3 = __float2bfloat16(v3);
                oAh[(size_t)r * N + cn] = h0;
                oAh[(size_t)r * N + cn + 1] = h1;
                oAh[(size_t)(r + 8) * N + cn] = h2;
                oAh[(size_t)(r + 8) * N + cn + 1] = h3;
                oAl[(size_t)r * N + cn] = __float2bfloat16(v0 - __bfloat162float(h0));
                oAl[(size_t)r * N + cn + 1] = __float2bfloat16(v1 - __bfloat162float(h1));
                oAl[(size_t)(r + 8) * N + cn] = __float2bfloat16(v2 - __bfloat162float(h2));
                oAl[(size_t)(r + 8) * N + cn + 1] = __float2bfloat16(v3 - __bfloat162float(h3));
            } else {
                outF[(size_t)r * N + cn] = v0;
                outF[(size_t)r * N + cn + 1] = v1;
                outF[(size_t)(r + 8) * N + cn] = v2;
                outF[(size_t)(r + 8) * N + cn + 1] = v3;
                if (obf == 2 && cn < 2 * Cn) {
                    int isK = cn >= Cn;
                    int c2 = cn - isK * Cn;
                    __nv_bfloat16* H = isK ? g_kh : g_qh;
                    __nv_bfloat16* L = isK ? g_kl : g_ql;
                    __nv_bfloat16 h0 = __float2bfloat16(v0), h1 = __float2bfloat16(v1);
                    __nv_bfloat16 h2 = __float2bfloat16(v2), h3 = __float2bfloat16(v3);
                    H[(size_t)r * Cn + c2] = h0;
                    H[(size_t)r * Cn + c2 + 1] = h1;
                    H[(size_t)(r + 8) * Cn + c2] = h2;
                    H[(size_t)(r + 8) * Cn + c2 + 1] = h3;
                    L[(size_t)r * Cn + c2] = __float2bfloat16(v0 - __bfloat162float(h0));
                    L[(size_t)r * Cn + c2 + 1] = __float2bfloat16(v1 - __bfloat162float(h1));
                    L[(size_t)(r + 8) * Cn + c2] = __float2bfloat16(v2 - __bfloat162float(h2));
                    L[(size_t)(r + 8) * Cn + c2 + 1] = __float2bfloat16(v3 - __bfloat162float(h3));
                }
            }
        }
    }
}

// ---------------- TC scores + fused exp + inline row sums (triangular grid) ----------------
__global__ void __launch_bounds__(256) score_tc() {
    int li = blockIdx.x, bh = blockIdx.y;
    int it = (int)((sqrtf(8.f * li + 1.f) - 1.f) * 0.5f);
    while ((it + 1) * (it + 2) / 2 <= li) it++;
    while (it * (it + 1) / 2 > li) it--;
    int jt = li - it * (it + 1) / 2;
    int b = bh / Hn, h = bh % Hn;
    __shared__ __nv_bfloat16 sQh[128][40], sQl[128][40], sKh[128][40], sKl[128][40];
    int tid = threadIdx.x, wid = tid >> 5, lane = tid & 31;
    int wm = wid & 3, wn = wid >> 2;
    float acc[2][8][4] = {};
    unsigned aQh = (unsigned)__cvta_generic_to_shared(&sQh[0][0]);
    unsigned aQl = (unsigned)__cvta_generic_to_shared(&sQl[0][0]);
    unsigned aKh = (unsigned)__cvta_generic_to_shared(&sKh[0][0]);
    unsigned aKl = (unsigned)__cvta_generic_to_shared(&sKl[0][0]);
    size_t qbase = ((size_t)(b * Tn + it * 128)) * Cn + h * HDn;
    size_t kbase = ((size_t)(b * Tn + jt * 128)) * Cn + h * HDn;

    for (int ks = 0; ks < 2; ks++) {
        if (ks) __syncthreads();
        #pragma unroll
        for (int z = 0; z < 2; z++) {
            int idx = z * 256 + tid;
            int r = idx >> 2, c8 = (idx & 3) * 8;
            *(uint4*)&sQh[r][c8] = *(const uint4*)(g_qh + qbase + (size_t)r * Cn + ks * 32 + c8);
            *(uint4*)&sQl[r][c8] = *(const uint4*)(g_ql + qbase + (size_t)r * Cn + ks * 32 + c8);
            *(uint4*)&sKh[r][c8] = *(const uint4*)(g_kh + kbase + (size_t)r * Cn + ks * 32 + c8);
            *(uint4*)&sKl[r][c8] = *(const uint4*)(g_kl + kbase + (size_t)r * Cn + ks * 32 + c8);
        }
        __syncthreads();
        #pragma unroll
        for (int kh = 0; kh < 32; kh += 16) {
            unsigned qh_[2][4], ql_[2][4];
            #pragma unroll
            for (int mt = 0; mt < 2; mt++) {
                unsigned off = ((unsigned)((wm * 32 + mt * 16 + (lane & 15)) * 40 + kh + 8 * (lane >> 4))) * 2;
                ldmx4(aQh + off, qh_[mt][0], qh_[mt][1], qh_[mt][2], qh_[mt][3]);
                ldmx4(aQl + off, ql_[mt][0], ql_[mt][1], ql_[mt][2], ql_[mt][3]);
            }
            #pragma unroll
            for (int nq = 0; nq < 4; nq++) {
                int n0 = wn * 64 + nq * 16;
                unsigned boff = ((unsigned)((n0 + (lane & 15)) * 40 + kh + 8 * (lane >> 4))) * 2;
                unsigned kh0, kh1, kh2, kh3, kl0, kl1, kl2, kl3;
                ldmx4(aKh + boff, kh0, kh1, kh2, kh3);
                ldmx4(aKl + boff, kl0, kl1, kl2, kl3);
                #pragma unroll
                for (int mt = 0; mt < 2; mt++) {
                    mma_bf16(acc[mt][2 * nq],     qh_[mt][0], qh_[mt][1], qh_[mt][2], qh_[mt][3], kh0, kh2);
                    mma_bf16(acc[mt][2 * nq],     qh_[mt][0], qh_[mt][1], qh_[mt][2], qh_[mt][3], kl0, kl2);
                    mma_bf16(acc[mt][2 * nq],     ql_[mt][0], ql_[mt][1], ql_[mt][2], ql_[mt][3], kh0, kh2);
                    mma_bf16(acc[mt][2 * nq + 1], qh_[mt][0], qh_[mt][1], qh_[mt][2], qh_[mt][3], kh1, kh3);
                    mma_bf16(acc[mt][2 * nq + 1], qh_[mt][0], qh_[mt][1], qh_[mt][2], qh_[mt][3], kl1, kl3);
                    mma_bf16(acc[mt][2 * nq + 1], ql_[mt][0], ql_[mt][1], ql_[mt][2], ql_[mt][3], kh1, kh3);
                }
            }
        }
    }
    __half* erow = g_e + (size_t)bh * Tn * Tn;
    float rsum[2][2] = {};
    int diag = (it == jt);
    #pragma unroll
    for (int mt = 0; mt < 2; mt++) {
        #pragma unroll
        for (int f = 0; f < 8; f++) {
            float* cc = acc[mt][f];
            int gi = it * 128 + wm * 32 + mt * 16 + (lane >> 2);
            int gj = jt * 128 + wn * 64 + (f >> 1) * 16 + (f & 1) * 8 + 2 * (lane & 3);
            float e0 = __expf(fminf(cc[0] * 0.125f, 11.f));
            float e1 = __expf(fminf(cc[1] * 0.125f, 11.f));
            float e2 = __expf(fminf(cc[2] * 0.125f, 11.f));
            float e3 = __expf(fminf(cc[3] * 0.125f, 11.f));
            if (diag) {
                if (gj > gi) e0 = 0.f;
                if (gj + 1 > gi) e1 = 0.f;
                if (gj > gi + 8) e2 = 0.f;
                if (gj + 1 > gi + 8) e3 = 0.f;
            }
            rsum[mt][0] += e0 + e1;
            rsum[mt][1] += e2 + e3;
            *(__half2*)(erow + (size_t)gi * Tn + gj) = __floats2half2_rn(e0, e1);
            *(__half2*)(erow + (size_t)(gi + 8) * Tn + gj) = __floats2half2_rn(e2, e3);
        }
    }
    #pragma unroll
    for (int mt = 0; mt < 2; mt++) {
        #pragma unroll
        for (int hh = 0; hh < 2; hh++) {
            float v = rsum[mt][hh];
            v += __shfl_xor_sync(0xffffffffu, v, 1);
            v += __shfl_xor_sync(0xffffffffu, v, 2);
            if ((lane & 3) == 0) {
                int gi = it * 128 + wm * 32 + mt * 16 + (lane >> 2) + hh * 8;
                atomicAdd(&g_rowsum[bh * Tn + gi], v);
            }
        }
    }
}

// ---------------- fused persistent sinkhorn: em1 + 5 passes + W build ----------------
__global__ void __launch_bounds__(256, 4) sinkhorn_all() {
    __shared__ float sh[Tn];      // sev / seu / reductions
    __shared__ float red8[8];
    int tid = threadIdx.x;
    int lane = tid & 31, w = tid >> 5;

    // ---- P0: em1 per row ----
    for (int u = blockIdx.x; u < BHn * Tn; u += GP) {
        int i = u & (Tn - 1);
        float inv = 1.f / g_rowsum[u];
        const uint4* src = (const uint4*)(g_e + (size_t)u * Tn);
        uint4* dst = (uint4*)(g_c + (size_t)u * Tn);
        int nv = ((i >> 7) + 1) << 4;
        float se = 0.f;
        if (tid < nv) {
            uint4 pk = src[tid];
            const __half2* hp = (const __half2*)&pk;
            uint4 outp;
            __half2* op = (__half2*)&outp;
            #pragma unroll
            for (int z = 0; z < 4; z++) {
                float2 f = __half22float2(hp[z]);
                float a = em1p(f.x * inv);
                float bb = em1p(f.y * inv);
                se += a + bb;
                op[z] = __floats2half2_rn(a, bb);
            }
            dst[tid] = outp;
        }
        se += __shfl_xor_sync(0xffffffffu, se, 16);
        se += __shfl_xor_sync(0xffffffffu, se, 8);
        se += __shfl_xor_sync(0xffffffffu, se, 4);
        se += __shfl_xor_sync(0xffffffffu, se, 2);
        se += __shfl_xor_sync(0xffffffffu, se, 1);
        if (lane == 0) red8[w] = se;
        __syncthreads();
        if (tid == 0) {
            float s = red8[0] + red8[1] + red8[2] + red8[3] + red8[4] + red8[5] + red8[6] + red8[7];
            float eu = __expf(-LOGT - __logf(s + (float)Tn));
            g_eu[u] = eu;
            atomicAdd(&g_tots[u >> 11], eu);   // slot 0
        }
        __syncthreads();
    }
    int ph = 0;

    #pragma unroll 1
    for (int iter = 0; iter < 3; iter++) {
        gbar(++ph);
        // ---- col partials ----
        for (int u = blockIdx.x; u < 4 * 8 * BHn; u += GP) {
            int cb = u & 3, rest = u >> 2;
            int ic = rest & 7, bh = rest >> 3;
            int j0 = cb * 512 + tid * 2;
            int is = ic * 256;
            float* part = g_cpart + (size_t)(ic * BHn + bh) * Tn;
            if (cb * 512 >= is + 256) {
                part[j0] = 0.f;
                part[j0 + 1] = 0.f;
                continue;
            }
            __syncthreads();
            sh[tid] = g_eu[bh * Tn + is + tid];
            __syncthreads();
            const __half* base = g_c + (size_t)bh * Tn * Tn + j0;
            float s0 = 0.f, s1 = 0.f;
            #pragma unroll 4
            for (int r = 0; r < 256; r++) {
                __half2 hh = *(const __half2*)(base + (size_t)(is + r) * Tn);
                float2 f = __half22float2(hh);
                float ui = sh[r];
                s0 += f.x * ui;
                s1 += f.y * ui;
            }
            part[j0] = s0;
            part[j0 + 1] = s1;
        }
        gbar(++ph);
        int slot_in = 2 * iter;
        if (iter < 2) {
            // ---- col finalize -> ev, evtot slot 2*iter+1 ----
            for (int u = blockIdx.x; u < 8 * BHn; u += GP) {
                int jbk = u & 7, bh = u >> 3;
                int j = jbk * 256 + tid;
                float s = 0.f;
                #pragma unroll
                for (int ic = 0; ic < 8; ic++)
                    s += g_cpart[(size_t)(ic * BHn + bh) * Tn + j];
                float ev = __expf(-LOGT - __logf(s + g_tots[slot_in * BHn + bh]));
                g_ev[bh * Tn + j] = ev;
                __syncthreads();
                sh[tid] = ev;
                __syncthreads();
                for (int o = 128; o > 0; o >>= 1) { if (tid < o) sh[tid] += sh[tid + o]; __syncthreads(); }
                if (tid == 0) atomicAdd(&g_tots[(slot_in + 1) * BHn + bh], sh[0]);
                __syncthreads();
            }
            gbar(++ph);
            // ---- row pass: warp-per-row -> eu, eutot slot 2*iter+2 ----
            for (int u = blockIdx.x; u < 256 * BHn; u += GP) {
                int bh = u >> 8;
                int r0 = (u & 255) * 8;
                int jmax = r0 + 8;
                __syncthreads();
                for (int j = tid; j < jmax; j += 256) sh[j] = g_ev[bh * Tn + j];
                float evtot = g_tots[(slot_in + 1) * BHn + bh];
                __syncthreads();
                int i = r0 + w;
                const uint4* cv = (const uint4*)(g_c + ((size_t)bh * Tn + i) * Tn);
                int nv = (i + 8) >> 3;
                float s = 0.f;
                for (int vi = lane; vi < nv; vi += 32) {
                    uint4 pk = cv[vi];
                    const __half2* hp = (const __half2*)&pk;
                    int jb = vi * 8;
                    #pragma unroll
                    for (int z = 0; z < 4; z++) {
                        float2 f = __half22float2(hp[z]);
                        s += f.x * sh[jb + 2 * z] + f.y * sh[jb + 2 * z + 1];
                    }
                }
                s += __shfl_xor_sync(0xffffffffu, s, 16);
                s += __shfl_xor_sync(0xffffffffu, s, 8);
                s += __shfl_xor_sync(0xffffffffu, s, 4);
                s += __shfl_xor_sync(0xffffffffu, s, 2);
                s += __shfl_xor_sync(0xffffffffu, s, 1);
                if (lane == 0) {
                    float eu = __expf(-LOGT - __logf(s + evtot));
                    g_eu[bh * Tn + i] = eu;
                    red8[w] = eu;
                }
                __syncthreads();
                if (tid == 0)
                    atomicAdd(&g_tots[(slot_in + 2) * BHn + bh],
                              red8[0] + red8[1] + red8[2] + red8[3] + red8[4] + red8[5] + red8[6] + red8[7]);
                __syncthreads();
            }
        } else {
            // ---- final col pass fused with W build ----
            for (int u = blockIdx.x; u < 8 * BHn; u += GP) {
                int jbk = u & 7, bh = u >> 3;
                int jb = jbk * 256;
                int j = jb + tid;
                int b = bh / Hn, h = bh % Hn;
                float s = 0.f;
                #pragma unroll
                for (int ic = 0; ic < 8; ic++)
                    s += g_cpart[(size_t)(ic * BHn + bh) * Tn + j];
                float ev = __expf(-LOGT - __logf(s + g_tots[slot_in * BHn + bh]));
                __syncthreads();
                sh[tid] = ev;
                __syncthreads();
                int d = tid & 63, rr = tid >> 6;
                const float* Vbase = g_qkv + (size_t)b * Tn * N3 + 2 * Cn + h * HDn + d;
                float part = 0.f;
                for (int r = rr; r < 256; r += 4) {
                    int jj = jb + r;
                    float wv = sh[r] * Vbase[(size_t)jj * N3];
                    part += wv;
                    float ws = fminf(fmaxf(wv * WSCALE, -32768.f), 32768.f);
                    __half hi = __float2half(ws);
                    g_wh[((size_t)bh * Tn + jj) * HDn + d] = hi;
                    g_wl[((size_t)bh * Tn + jj) * HDn + d] = __float2half(ws - __half2float(hi));
                }
                __syncthreads();
                sh[256 + tid] = part;
                __syncthreads();
                if (tid < 128) sh[256 + tid] += sh[256 + tid + 128];
                __syncthreads();
                if (tid < 64) atomicAdd(&g_wtot[bh * HDn + tid], sh[256 + tid] + sh[256 + tid + 64]);
                __syncthreads();
            }
        }
    }
}

// ---------------- pi@V via fp16 TC; y written as bf16 hi/lo ----------------
__global__ void __launch_bounds__(256) pi_v_tc() {
    int bh = blockIdx.y;
    int b = bh / Hn, h = bh % Hn;
    int it = gridDim.x - 1 - blockIdx.x;
    int i0 = it * 128;
    __shared__ __half sA[128][72];
    __shared__ __half sWh[64][72], sWl[64][72];
    int tid = threadIdx.x, wid = tid >> 5, lane = tid & 31;
    int wm = wid & 3, wn = wid >> 2;
    float acc[2][4][4] = {};
    unsigned aA = (unsigned)__cvta_generic_to_shared(&sA[0][0]);
    unsigned aWh = (unsigned)__cvta_generic_to_shared(&sWh[0][0]);
    unsigned aWl = (unsigned)__cvta_generic_to_shared(&sWl[0][0]);

    for (int jc = 0; jc < i0 + 128; jc += 64) {
        if (jc) __syncthreads();
        #pragma unroll
        for (int z = 0; z < 4; z++) {
            int idx = z * 256 + tid;
            int r = idx >> 3, c8 = (idx & 7) * 8;
            *(uint4*)&sA[r][c8] = *(const uint4*)(g_c + ((size_t)bh * Tn + i0 + r) * Tn + jc + c8);
        }
        #pragma unroll
        for (int z = 0; z < 2; z++) {
            int idx = z * 256 + tid;
            int r = idx >> 3, c8 = (idx & 7) * 8;
            *(uint4*)&sWh[r][c8] = *(const uint4*)(g_wh + ((size_t)bh * Tn + jc + r) * HDn + c8);
            *(uint4*)&sWl[r][c8] = *(const uint4*)(g_wl + ((size_t)bh * Tn + jc + r) * HDn + c8);
        }
        __syncthreads();
        #pragma unroll
        for (int kh = 0; kh < 64; kh += 16) {
            unsigned a_[2][4];
            #pragma unroll
            for (int mt = 0; mt < 2; mt++) {
                unsigned off = ((unsigned)((wm * 32 + mt * 16 + (lane & 15)) * 72 + kh + 8 * (lane >> 4))) * 2;
                ldmx4(aA + off, a_[mt][0], a_[mt][1], a_[mt][2], a_[mt][3]);
            }
            #pragma unroll
            for (int nq = 0; nq < 2; nq++) {
                int n0 = wn * 32 + nq * 16;
                unsigned boff = ((unsigned)((kh + (lane & 7) + 8 * ((lane >> 3) & 1)) * 72 + n0 + 8 * (lane >> 4))) * 2;
                unsigned bh0, bh1, bh2, bh3, bl0, bl1, bl2, bl3;
                ldmx4t(aWh + boff, bh0, bh1, bh2, bh3);
                ldmx4t(aWl + boff, bl0, bl1, bl2, bl3);
                #pragma unroll
                for (int mt = 0; mt < 2; mt++) {
                    mma_f16(acc[mt][2 * nq],     a_[mt][0], a_[mt][1], a_[mt][2], a_[mt][3], bh0, bh1);
                    mma_f16(acc[mt][2 * nq],     a_[mt][0], a_[mt][1], a_[mt][2], a_[mt][3], bl0, bl1);
                    mma_f16(acc[mt][2 * nq + 1], a_[mt][0], a_[mt][1], a_[mt][2], a_[mt][3], bh2, bh3);
                    mma_f16(acc[mt][2 * nq + 1], a_[mt][0], a_[mt][1], a_[mt][2], a_[mt][3], bl2, bl3);
                }
            }
        }
    }
    #pragma unroll
    for (int mt = 0; mt < 2; mt++) {
        #pragma unroll
        for (int f = 0; f < 4; f++) {
            float* cc = acc[mt][f];
            int r = i0 + wm * 32 + mt * 16 + (lane >> 2);
            int d = wn * 32 + f * 8 + 2 * (lane & 3);
            float wt0 = g_wtot[bh * HDn + d], wt1 = g_wtot[bh * HDn + d + 1];
            float eu0 = g_eu[bh * Tn + r] * 2048.f;
            float eu1 = g_eu[bh * Tn + r + 8] * 2048.f;
            float y0 = (cc[0] * WINV + wt0) * eu0;
            float y1 = (cc[1] * WINV + wt1) * eu0;
            float y2 = (cc[2] * WINV + wt0) * eu1;
            float y3 = (cc[3] * WINV + wt1) * eu1;
            size_t base = ((size_t)(b * Tn) + r) * Cn + h * HDn + d;
            __nv_bfloat16 h0 = __float2bfloat16(y0), h1 = __float2bfloat16(y1);
            __nv_bfloat16 h2 = __float2bfloat16(y2), h3 = __float2bfloat16(y3);
            g_ah[base] = h0;
            g_ah[base + 1] = h1;
            g_ah[base + (size_t)8 * Cn] = h2;
            g_ah[base + (size_t)8 * Cn + 1] = h3;
            g_al[base] = __float2bfloat16(y0 - __bfloat162float(h0));
            g_al[base + 1] = __float2bfloat16(y1 - __bfloat162float(h1));
            g_al[base + (size_t)8 * Cn] = __float2bfloat16(y2 - __bfloat162float(h2));
            g_al[base + (size_t)8 * Cn + 1] = __float2bfloat16(y3 - __bfloat162float(h3));
        }
    }
}

// ---------------- launch ----------------
extern "C" void kernel_launch(void* const* d_in, const int* in_sizes, int n_in,
                              void* d_out, int out_size) {
    const float* x      = (const float*)d_in[0];
    const float* t      = (const float*)d_in[1];
    const float* ln1_w  = (const float*)d_in[2];
    const float* ln1_b  = (const float*)d_in[3];
    const float* attn_w = (const float*)d_in[4];
    const float* attn_b = (const float*)d_in[5];
    const float* proj_w = (const float*)d_in[6];
    const float* proj_b = (const float*)d_in[7];
    const float* ln2_w  = (const float*)d_in[8];
    const float* ln2_b  = (const float*)d_in[9];
    const float* fc_w   = (const float*)d_in[10];
    const float* fc_b   = (const float*)d_in[11];
    const float* fc2_w  = (const float*)d_in[12];
    const float* fc2_b  = (const float*)d_in[13];
    float* out = (float*)d_out;

    float *p_qkv, *p_h;
    __nv_bfloat16 *p_ah, *p_al, *p_a2h, *p_a2l, *p_bh, *p_bl;
    cudaGetSymbolAddress((void**)&p_qkv, g_qkv);
    cudaGetSymbolAddress((void**)&p_h,   g_h);
    cudaGetSymbolAddress((void**)&p_ah,  g_ah);
    cudaGetSymbolAddress((void**)&p_al,  g_al);
    cudaGetSymbolAddress((void**)&p_a2h, g_a2h);
    cudaGetSymbolAddress((void**)&p_a2l, g_a2l);
    cudaGetSymbolAddress((void**)&p_bh,  g_bh);
    cudaGetSymbolAddress((void**)&p_bl,  g_bl);

    static int smem_set = 0;
    const int GSM64 = 55296;
    if (!smem_set) {
        cudaFuncSetAttribute(gemm64u, cudaFuncAttributeMaxDynamicSharedMemorySize, GSM64);
        smem_set = 1;
    }

    // ---- setup ----
    zero_misc<<<96, 256>>>();
    conv_w_all<<<(WTOTAL / 4 + 255) / 256, 256>>>(attn_w, proj_w, fc_w, fc2_w);

    // ---- attention sub-block ----
    ln_bf<<<ROWS, 256>>>(x, t, ln1_w, ln1_b, p_ah, p_al);
    gemm64u<<<dim3(N3 / 128, ROWS / 64), 256, GSM64>>>(p_ah, p_al, p_bh + WOFF_QKV, p_bl + WOFF_QKV, attn_b,
                                                       p_qkv, nullptr, nullptr, ROWS, N3, KA_LN, 0, 2);
    score_tc<<<dim3(136, BHn), 256>>>();

    // fused em1 + full sinkhorn + W build (persistent, global barrier)
    sinkhorn_all<<<GP, 256>>>();

    pi_v_tc<<<dim3(Tn / 128, BHn), 256>>>();

    // proj
    gemm64u<<<dim3(Cn / 128, ROWS / 64), 256, GSM64>>>(p_ah, p_al, p_bh + WOFF_PRJ, p_bl + WOFF_PRJ, proj_b,
                                                       p_h, nullptr, nullptr, ROWS, Cn, Cn, 0, 0);

    // ---- MLP sub-block ----
    ln_bf<<<ROWS, 256>>>(p_h, t, ln2_w, ln2_b, p_ah, p_al);
    gemm64u<<<dim3(N4 / 128, ROWS / 64), 256, GSM64>>>(p_ah, p_al, p_bh + WOFF_FC, p_bl + WOFF_FC, fc_b,
                                                       nullptr, p_a2h, p_a2l, ROWS, N4, KA_LN, 1, 1);
    gemm64u<<<dim3(Cn / 128, ROWS / 64), 256, GSM64>>>(p_a2h, p_a2l, p_bh + WOFF_FC2, p_bl + WOFF_FC2, fc2_b,
                                                       out, nullptr, nullptr, ROWS, Cn, N4, 0, 0);
}

// round 14
// speedup vs baseline: 1.0391x; 1.0391x over previous
#include <cuda_runtime.h>
#include <cuda_fp16.h>
#include <cuda_bf16.h>
#include <math.h>

#define Tn 2048
#define Cn 384
#define Hn 6
#define HDn 64
#define Bn 2
#define BHn 12
#define ROWS 4096
#define C1 385
#define KA_LN 416
#define N3 1152
#define N4 1536
#define LOGT 7.62461899f
#define WSCALE 512.f
#define WINV   (1.f / 512.f)

#define WOFF_QKV 0
#define WSZ_QKV  (KA_LN * N3)
#define WOFF_PRJ (WOFF_QKV + WSZ_QKV)
#define WSZ_PRJ  (Cn * Cn)
#define WOFF_FC  (WOFF_PRJ + WSZ_PRJ)
#define WSZ_FC   (KA_LN * N4)
#define WOFF_FC2 (WOFF_FC + WSZ_FC)
#define WSZ_FC2  (N4 * Cn)
#define WTOTAL   (WOFF_FC2 + WSZ_FC2)

// ---------------- scratch ----------------
__device__ __align__(16) float g_qkv[ROWS * N3];
__device__ __align__(16) __half g_e[(size_t)BHn * Tn * Tn];
__device__ __align__(16) __half g_c[(size_t)BHn * Tn * Tn];
__device__ __align__(16) __nv_bfloat16 g_qh[ROWS * Cn];
__device__ __align__(16) __nv_bfloat16 g_ql[ROWS * Cn];
__device__ __align__(16) __nv_bfloat16 g_kh[ROWS * Cn];
__device__ __align__(16) __nv_bfloat16 g_kl[ROWS * Cn];
__device__ __align__(16) __half g_wh[BHn * Tn * HDn];
__device__ __align__(16) __half g_wl[BHn * Tn * HDn];
__device__ float g_rowsum[BHn * Tn];
__device__ float g_eu[BHn * Tn];
__device__ float g_ev[BHn * Tn];
__device__ float g_tots[8 * BHn];
__device__ float g_wtot[BHn * HDn];
__device__ __align__(16) float g_cpart[8 * BHn * Tn];
__device__ __align__(16) float g_h[ROWS * Cn];
__device__ __align__(16) __nv_bfloat16 g_ah[ROWS * N4];
__device__ __align__(16) __nv_bfloat16 g_al[ROWS * N4];
__device__ __align__(16) __nv_bfloat16 g_a2h[ROWS * N4];
__device__ __align__(16) __nv_bfloat16 g_a2l[ROWS * N4];
__device__ __align__(16) __nv_bfloat16 g_bh[WTOTAL];
__device__ __align__(16) __nv_bfloat16 g_bl[WTOTAL];

// ---------------- helpers ----------------
__device__ __forceinline__ void ldmx4(unsigned addr, unsigned& r0, unsigned& r1, unsigned& r2, unsigned& r3) {
    asm volatile("ldmatrix.sync.aligned.m8n8.x4.shared.b16 {%0,%1,%2,%3},[%4];"
                 : "=r"(r0), "=r"(r1), "=r"(r2), "=r"(r3) : "r"(addr));
}
__device__ __forceinline__ void ldmx4t(unsigned addr, unsigned& r0, unsigned& r1, unsigned& r2, unsigned& r3) {
    asm volatile("ldmatrix.sync.aligned.m8n8.x4.trans.shared.b16 {%0,%1,%2,%3},[%4];"
                 : "=r"(r0), "=r"(r1), "=r"(r2), "=r"(r3) : "r"(addr));
}
__device__ __forceinline__ void mma_bf16(float* c, unsigned a0, unsigned a1, unsigned a2, unsigned a3,
                                         unsigned b0, unsigned b1) {
    asm volatile("mma.sync.aligned.m16n8k16.row.col.f32.bf16.bf16.f32 "
                 "{%0,%1,%2,%3},{%4,%5,%6,%7},{%8,%9},{%0,%1,%2,%3};"
                 : "+f"(c[0]), "+f"(c[1]), "+f"(c[2]), "+f"(c[3])
                 : "r"(a0), "r"(a1), "r"(a2), "r"(a3), "r"(b0), "r"(b1));
}
__device__ __forceinline__ void mma_f16(float* c, unsigned a0, unsigned a1, unsigned a2, unsigned a3,
                                        unsigned b0, unsigned b1) {
    asm volatile("mma.sync.aligned.m16n8k16.row.col.f32.f16.f16.f32 "
                 "{%0,%1,%2,%3},{%4,%5,%6,%7},{%8,%9},{%0,%1,%2,%3};"
                 : "+f"(c[0]), "+f"(c[1]), "+f"(c[2]), "+f"(c[3])
                 : "r"(a0), "r"(a1), "r"(a2), "r"(a3), "r"(b0), "r"(b1));
}
__device__ __forceinline__ void cpa16(unsigned dst, const void* src) {
    asm volatile("cp.async.cg.shared.global [%0],[%1],16;" :: "r"(dst), "l"(src));
}
#define CPA_COMMIT asm volatile("cp.async.commit_group;")
#define CPA_WAIT1  asm volatile("cp.async.wait_group 1;")

__device__ __forceinline__ float em1p(float x) {
    float t = fmaf(x, 0.125f, 1.f);
    t = fmaf(x * 0.14285714f, t, 1.f);
    t = fmaf(x * 0.16666667f, t, 1.f);
    t = fmaf(x * 0.2f,        t, 1.f);
    t = fmaf(x * 0.25f,       t, 1.f);
    t = fmaf(x * 0.33333333f, t, 1.f);
    t = fmaf(x * 0.5f,        t, 1.f);
    return x * t;
}

// ---------------- weights -> bf16 hi/lo (+ fused zeroing) ----------------
__global__ void conv_w_all(const float* __restrict__ w0, const float* __restrict__ w1,
                           const float* __restrict__ w2, const float* __restrict__ w3) {
    int idx = blockIdx.x * 256 + threadIdx.x;
    if (idx < BHn * Tn) g_rowsum[idx] = 0.f;
    if (idx < BHn * HDn) g_wtot[idx] = 0.f;
    if (idx < 8 * BHn) g_tots[idx] = 0.f;
    int e = idx * 4;
    if (e >= WTOTAL) return;
    const float* src;
    int K, N, local;
    if (e < WOFF_PRJ)       { src = w0; K = C1;  N = N3; local = e - WOFF_QKV; }
    else if (e < WOFF_FC)   { src = w1; K = Cn;  N = Cn; local = e - WOFF_PRJ; }
    else if (e < WOFF_FC2)  { src = w2; K = C1;  N = N4; local = e - WOFF_FC;  }
    else                    { src = w3; K = N4;  N = Cn; local = e - WOFF_FC2; }
    int row = local / N, col = local % N;
    float4 v = (row < K) ? *(const float4*)(src + (size_t)row * N + col)
                         : make_float4(0.f, 0.f, 0.f, 0.f);
    __nv_bfloat16 h0 = __float2bfloat16(v.x), h1 = __float2bfloat16(v.y);
    __nv_bfloat16 h2 = __float2bfloat16(v.z), h3 = __float2bfloat16(v.w);
    __nv_bfloat16 hbuf[4] = {h0, h1, h2, h3};
    __nv_bfloat16 lbuf[4] = {
        __float2bfloat16(v.x - __bfloat162float(h0)), __float2bfloat16(v.y - __bfloat162float(h1)),
        __float2bfloat16(v.z - __bfloat162float(h2)), __float2bfloat16(v.w - __bfloat162float(h3))};
    *(uint2*)(g_bh + e) = *(uint2*)hbuf;
    *(uint2*)(g_bl + e) = *(uint2*)lbuf;
}

// ---------------- LayerNorm -> bf16 hi/lo ----------------
__global__ void ln_bf(const float* __restrict__ x, const float* __restrict__ t,
                      const float* __restrict__ w, const float* __restrict__ bb,
                      __nv_bfloat16* __restrict__ oh, __nv_bfloat16* __restrict__ ol) {
    int row = blockIdx.x;
    int tid = threadIdx.x;
    __shared__ float sx[C1];
    __shared__ float red[256];
    float s1 = 0.f;
    for (int c = tid; c < C1; c += 256) {
        float v = (c < Cn) ? x[(size_t)row * Cn + c] : t[0];
        sx[c] = v;
        s1 += v;
    }
    red[tid] = s1; __syncthreads();
    for (int o = 128; o > 0; o >>= 1) { if (tid < o) red[tid] += red[tid + o]; __syncthreads(); }
    float mean = red[0] * (1.f / C1);
    __syncthreads();
    float s2 = 0.f;
    for (int c = tid; c < C1; c += 256) { float d = sx[c] - mean; s2 += d * d; }
    red[tid] = s2; __syncthreads();
    for (int o = 128; o > 0; o >>= 1) { if (tid < o) red[tid] += red[tid + o]; __syncthreads(); }
    float rs = rsqrtf(red[0] * (1.f / C1) + 1e-5f);
    for (int c = tid; c < C1; c += 256) {
        float v = (sx[c] - mean) * rs * w[c] + bb[c];
        __nv_bfloat16 hi = __float2bfloat16(v);
        oh[(size_t)row * KA_LN + c] = hi;
        ol[(size_t)row * KA_LN + c] = __float2bfloat16(v - __bfloat162float(hi));
    }
    if (tid < KA_LN - C1) {
        oh[(size_t)row * KA_LN + C1 + tid] = __float2bfloat16(0.f);
        ol[(size_t)row * KA_LN + C1 + tid] = __float2bfloat16(0.f);
    }
}

// ---------------- unified pipelined bf16 GEMM, 64x128 tile ----------------
__global__ void __launch_bounds__(256) gemm64u(const __nv_bfloat16* __restrict__ Ah,
                                               const __nv_bfloat16* __restrict__ Al,
                                               const __nv_bfloat16* __restrict__ Bh,
                                               const __nv_bfloat16* __restrict__ Bl,
                                               const float* __restrict__ bias,
                                               float* __restrict__ outF,
                                               __nv_bfloat16* __restrict__ oAh,
                                               __nv_bfloat16* __restrict__ oAl,
                                               int M, int N, int Ka, int act, int obf) {
    extern __shared__ __nv_bfloat16 dyn[];
    __nv_bfloat16* sA = dyn;
    __nv_bfloat16* sB = dyn + 4 * 2560;
    int tid = threadIdx.x;
    int wid = tid >> 5, lane = tid & 31;
    int wm = wid & 1, wn = wid >> 1;
    int bm = blockIdx.y * 64, bn = blockIdx.x * 128;
    float acc[2][4][4] = {};
    unsigned sAu = (unsigned)__cvta_generic_to_shared(sA);
    unsigned sBu = (unsigned)__cvta_generic_to_shared(sB);

    int nk = Ka >> 5;
    auto load_stage = [&](int kt, int st) {
        unsigned aH = sAu + (st * 2 + 0) * 2560 * 2;
        unsigned aL = sAu + (st * 2 + 1) * 2560 * 2;
        unsigned bH = sBu + (st * 2 + 0) * 4352 * 2;
        unsigned bL = sBu + (st * 2 + 1) * 4352 * 2;
        int k0 = kt * 32;
        {
            int row = tid >> 2, cq = (tid & 3) * 8;
            cpa16(aH + (row * 40 + cq) * 2, Ah + (size_t)(bm + row) * Ka + k0 + cq);
            cpa16(aL + (row * 40 + cq) * 2, Al + (size_t)(bm + row) * Ka + k0 + cq);
        }
        #pragma unroll
        for (int z = 0; z < 2; z++) {
            int idx = z * 256 + tid;
            int row = idx >> 4, cq = (idx & 15) * 8;
            cpa16(bH + (row * 136 + cq) * 2, Bh + (size_t)(k0 + row) * N + bn + cq);
            cpa16(bL + (row * 136 + cq) * 2, Bl + (size_t)(k0 + row) * N + bn + cq);
        }
    };

    load_stage(0, 0);
    CPA_COMMIT;
    for (int kt = 0; kt < nk; kt++) {
        int cur = kt & 1;
        if (kt + 1 < nk) load_stage(kt + 1, cur ^ 1);
        CPA_COMMIT;
        CPA_WAIT1;
        __syncthreads();
        unsigned aH = sAu + (cur * 2 + 0) * 2560 * 2;
        unsigned aL = sAu + (cur * 2 + 1) * 2560 * 2;
        unsigned bH = sBu + (cur * 2 + 0) * 4352 * 2;
        unsigned bL = sBu + (cur * 2 + 1) * 4352 * 2;
        #pragma unroll
        for (int kh = 0; kh < 32; kh += 16) {
            unsigned ah[2][4], al[2][4];
            #pragma unroll
            for (int mt = 0; mt < 2; mt++) {
                unsigned off = ((unsigned)((wm * 32 + mt * 16 + (lane & 15)) * 40 + kh + (lane >> 4) * 8)) * 2;
                ldmx4(aH + off, ah[mt][0], ah[mt][1], ah[mt][2], ah[mt][3]);
                ldmx4(aL + off, al[mt][0], al[mt][1], al[mt][2], al[mt][3]);
            }
            #pragma unroll
            for (int np = 0; np < 2; np++) {
                int n0 = wn * 32 + np * 16;
                unsigned boff = ((unsigned)((kh + (lane & 7) + 8 * ((lane >> 3) & 1)) * 136 + n0 + 8 * (lane >> 4))) * 2;
                unsigned bh0, bh1, bh2, bh3, bl0, bl1, bl2, bl3;
                ldmx4t(bH + boff, bh0, bh1, bh2, bh3);
                ldmx4t(bL + boff, bl0, bl1, bl2, bl3);
                #pragma unroll
                for (int mt = 0; mt < 2; mt++) {
                    mma_bf16(acc[mt][2 * np],     ah[mt][0], ah[mt][1], ah[mt][2], ah[mt][3], bh0, bh1);
                    mma_bf16(acc[mt][2 * np],     ah[mt][0], ah[mt][1], ah[mt][2], ah[mt][3], bl0, bl1);
                    mma_bf16(acc[mt][2 * np],     al[mt][0], al[mt][1], al[mt][2], al[mt][3], bh0, bh1);
                    mma_bf16(acc[mt][2 * np + 1], ah[mt][0], ah[mt][1], ah[mt][2], ah[mt][3], bh2, bh3);
                    mma_bf16(acc[mt][2 * np + 1], ah[mt][0], ah[mt][1], ah[mt][2], ah[mt][3], bl2, bl3);
                    mma_bf16(acc[mt][2 * np + 1], al[mt][0], al[mt][1], al[mt][2], al[mt][3], bh2, bh3);
                }
            }
        }
        __syncthreads();
    }
    #pragma unroll
    for (int mt = 0; mt < 2; mt++) {
        #pragma unroll
        for (int nt = 0; nt < 4; nt++) {
            float* cc = acc[mt][nt];
            int r = bm + wm * 32 + mt * 16 + (lane >> 2);
            int cn = bn + wn * 32 + (nt >> 1) * 16 + (nt & 1) * 8 + (lane & 3) * 2;
            float b0 = bias[cn], b1 = bias[cn + 1];
            float v0 = cc[0] + b0, v1 = cc[1] + b1;
            float v2 = cc[2] + b0, v3 = cc[3] + b1;
            if (act == 1) {
                v0 = 0.5f * v0 * (1.f + erff(v0 * 0.70710678f));
                v1 = 0.5f * v1 * (1.f + erff(v1 * 0.70710678f));
                v2 = 0.5f * v2 * (1.f + erff(v2 * 0.70710678f));
                v3 = 0.5f * v3 * (1.f + erff(v3 * 0.70710678f));
            }
            if (obf == 1) {
                __nv_bfloat16 h0 = __float2bfloat16(v0), h1 = __float2bfloat16(v1);
                __nv_bfloat16 h2 = __float2bfloat16(v2), h3 = __float2bfloat16(v3);
                oAh[(size_t)r * N + cn] = h0;
                oAh[(size_t)r * N + cn + 1] = h1;
                oAh[(size_t)(r + 8) * N + cn] = h2;
                oAh[(size_t)(r + 8) * N + cn + 1] = h3;
                oAl[(size_t)r * N + cn] = __float2bfloat16(v0 - __bfloat162float(h0));
                oAl[(size_t)r * N + cn + 1] = __float2bfloat16(v1 - __bfloat162float(h1));
                oAl[(size_t)(r + 8) * N + cn] = __float2bfloat16(v2 - __bfloat162float(h2));
                oAl[(size_t)(r + 8) * N + cn + 1] = __float2bfloat16(v3 - __bfloat162float(h3));
            } else {
                outF[(size_t)r * N + cn] = v0;
                outF[(size_t)r * N + cn + 1] = v1;
                outF[(size_t)(r + 8) * N + cn] = v2;
                outF[(size_t)(r + 8) * N + cn + 1] = v3;
                if (obf == 2 && cn < 2 * Cn) {
                    int isK = cn >= Cn;
                    int c2 = cn - isK * Cn;
                    __nv_bfloat16* H = isK ? g_kh : g_qh;
                    __nv_bfloat16* L = isK ? g_kl : g_ql;
                    __nv_bfloat16 h0 = __float2bfloat16(v0), h1 = __float2bfloat16(v1);
                    __nv_bfloat16 h2 = __float2bfloat16(v2), h3 = __float2bfloat16(v3);
                    H[(size_t)r * Cn + c2] = h0;
                    H[(size_t)r * Cn + c2 + 1] = h1;
                    H[(size_t)(r + 8) * Cn + c2] = h2;
                    H[(size_t)(r + 8) * Cn + c2 + 1] = h3;
                    L[(size_t)r * Cn + c2] = __float2bfloat16(v0 - __bfloat162float(h0));
                    L[(size_t)r * Cn + c2 + 1] = __float2bfloat16(v1 - __bfloat162float(h1));
                    L[(size_t)(r + 8) * Cn + c2] = __float2bfloat16(v2 - __bfloat162float(h2));
                    L[(size_t)(r + 8) * Cn + c2 + 1] = __float2bfloat16(v3 - __bfloat162float(h3));
                }
            }
        }
    }
}

// ---------------- TC scores + fused exp + inline row sums (triangular grid) ----------------
__global__ void __launch_bounds__(256) score_tc() {
    int li = blockIdx.x, bh = blockIdx.y;
    int it = (int)((sqrtf(8.f * li + 1.f) - 1.f) * 0.5f);
    while ((it + 1) * (it + 2) / 2 <= li) it++;
    while (it * (it + 1) / 2 > li) it--;
    int jt = li - it * (it + 1) / 2;
    int b = bh / Hn, h = bh % Hn;
    __shared__ __nv_bfloat16 sQh[128][40], sQl[128][40], sKh[128][40], sKl[128][40];
    int tid = threadIdx.x, wid = tid >> 5, lane = tid & 31;
    int wm = wid & 3, wn = wid >> 2;
    float acc[2][8][4] = {};
    unsigned aQh = (unsigned)__cvta_generic_to_shared(&sQh[0][0]);
    unsigned aQl = (unsigned)__cvta_generic_to_shared(&sQl[0][0]);
    unsigned aKh = (unsigned)__cvta_generic_to_shared(&sKh[0][0]);
    unsigned aKl = (unsigned)__cvta_generic_to_shared(&sKl[0][0]);
    size_t qbase = ((size_t)(b * Tn + it * 128)) * Cn + h * HDn;
    size_t kbase = ((size_t)(b * Tn + jt * 128)) * Cn + h * HDn;

    for (int ks = 0; ks < 2; ks++) {
        if (ks) __syncthreads();
        #pragma unroll
        for (int z = 0; z < 2; z++) {
            int idx = z * 256 + tid;
            int r = idx >> 2, c8 = (idx & 3) * 8;
            *(uint4*)&sQh[r][c8] = *(const uint4*)(g_qh + qbase + (size_t)r * Cn + ks * 32 + c8);
            *(uint4*)&sQl[r][c8] = *(const uint4*)(g_ql + qbase + (size_t)r * Cn + ks * 32 + c8);
            *(uint4*)&sKh[r][c8] = *(const uint4*)(g_kh + kbase + (size_t)r * Cn + ks * 32 + c8);
            *(uint4*)&sKl[r][c8] = *(const uint4*)(g_kl + kbase + (size_t)r * Cn + ks * 32 + c8);
        }
        __syncthreads();
        #pragma unroll
        for (int kh = 0; kh < 32; kh += 16) {
            unsigned qh_[2][4], ql_[2][4];
            #pragma unroll
            for (int mt = 0; mt < 2; mt++) {
                unsigned off = ((unsigned)((wm * 32 + mt * 16 + (lane & 15)) * 40 + kh + 8 * (lane >> 4))) * 2;
                ldmx4(aQh + off, qh_[mt][0], qh_[mt][1], qh_[mt][2], qh_[mt][3]);
                ldmx4(aQl + off, ql_[mt][0], ql_[mt][1], ql_[mt][2], ql_[mt][3]);
            }
            #pragma unroll
            for (int nq = 0; nq < 4; nq++) {
                int n0 = wn * 64 + nq * 16;
                unsigned boff = ((unsigned)((n0 + (lane & 15)) * 40 + kh + 8 * (lane >> 4))) * 2;
                unsigned kh0, kh1, kh2, kh3, kl0, kl1, kl2, kl3;
                ldmx4(aKh + boff, kh0, kh1, kh2, kh3);
                ldmx4(aKl + boff, kl0, kl1, kl2, kl3);
                #pragma unroll
                for (int mt = 0; mt < 2; mt++) {
                    mma_bf16(acc[mt][2 * nq],     qh_[mt][0], qh_[mt][1], qh_[mt][2], qh_[mt][3], kh0, kh2);
                    mma_bf16(acc[mt][2 * nq],     qh_[mt][0], qh_[mt][1], qh_[mt][2], qh_[mt][3], kl0, kl2);
                    mma_bf16(acc[mt][2 * nq],     ql_[mt][0], ql_[mt][1], ql_[mt][2], ql_[mt][3], kh0, kh2);
                    mma_bf16(acc[mt][2 * nq + 1], qh_[mt][0], qh_[mt][1], qh_[mt][2], qh_[mt][3], kh1, kh3);
                    mma_bf16(acc[mt][2 * nq + 1], qh_[mt][0], qh_[mt][1], qh_[mt][2], qh_[mt][3], kl1, kl3);
                    mma_bf16(acc[mt][2 * nq + 1], ql_[mt][0], ql_[mt][1], ql_[mt][2], ql_[mt][3], kh1, kh3);
                }
            }
        }
    }
    __half* erow = g_e + (size_t)bh * Tn * Tn;
    float rsum[2][2] = {};
    int diag = (it == jt);
    #pragma unroll
    for (int mt = 0; mt < 2; mt++) {
        #pragma unroll
        for (int f = 0; f < 8; f++) {
            float* cc = acc[mt][f];
            int gi = it * 128 + wm * 32 + mt * 16 + (lane >> 2);
            int gj = jt * 128 + wn * 64 + (f >> 1) * 16 + (f & 1) * 8 + 2 * (lane & 3);
            float e0 = __expf(fminf(cc[0] * 0.125f, 11.f));
            float e1 = __expf(fminf(cc[1] * 0.125f, 11.f));
            float e2 = __expf(fminf(cc[2] * 0.125f, 11.f));
            float e3 = __expf(fminf(cc[3] * 0.125f, 11.f));
            if (diag) {
                if (gj > gi) e0 = 0.f;
                if (gj + 1 > gi) e1 = 0.f;
                if (gj > gi + 8) e2 = 0.f;
                if (gj + 1 > gi + 8) e3 = 0.f;
            }
            rsum[mt][0] += e0 + e1;
            rsum[mt][1] += e2 + e3;
            *(__half2*)(erow + (size_t)gi * Tn + gj) = __floats2half2_rn(e0, e1);
            *(__half2*)(erow + (size_t)(gi + 8) * Tn + gj) = __floats2half2_rn(e2, e3);
        }
    }
    #pragma unroll
    for (int mt = 0; mt < 2; mt++) {
        #pragma unroll
        for (int hh = 0; hh < 2; hh++) {
            float v = rsum[mt][hh];
            v += __shfl_xor_sync(0xffffffffu, v, 1);
            v += __shfl_xor_sync(0xffffffffu, v, 2);
            if ((lane & 3) == 0) {
                int gi = it * 128 + wm * 32 + mt * 16 + (lane >> 2) + hh * 8;
                atomicAdd(&g_rowsum[bh * Tn + gi], v);
            }
        }
    }
}

// ---------------- per row: Em1 = expm1(e/rowsum); eu; eutot -> slot0 ----------------
__global__ void em1_row() {
    int i = blockIdx.x, bh = blockIdx.y;
    int tid = threadIdx.x;
    int lane = tid & 31, wid = tid >> 5;
    float inv = 1.f / g_rowsum[bh * Tn + i];
    const uint4* src = (const uint4*)(g_e + ((size_t)bh * Tn + i) * Tn);
    uint4* dst = (uint4*)(g_c + ((size_t)bh * Tn + i) * Tn);
    int nv = ((i >> 7) + 1) << 4;
    float se = 0.f;
    if (tid < nv) {
        uint4 pk = src[tid];
        const __half2* hp = (const __half2*)&pk;
        uint4 outp;
        __half2* op = (__half2*)&outp;
        #pragma unroll
        for (int z = 0; z < 4; z++) {
            float2 f = __half22float2(hp[z]);
            float a = em1p(f.x * inv);
            float bb = em1p(f.y * inv);
            se += a + bb;
            op[z] = __floats2half2_rn(a, bb);
        }
        dst[tid] = outp;
    }
    se += __shfl_xor_sync(0xffffffffu, se, 16);
    se += __shfl_xor_sync(0xffffffffu, se, 8);
    se += __shfl_xor_sync(0xffffffffu, se, 4);
    se += __shfl_xor_sync(0xffffffffu, se, 2);
    se += __shfl_xor_sync(0xffffffffu, se, 1);
    __shared__ float red[8];
    if (lane == 0) red[wid] = se;
    __syncthreads();
    if (tid == 0) {
        float s = red[0] + red[1] + red[2] + red[3] + red[4] + red[5] + red[6] + red[7];
        float eu = __expf(-LOGT - __logf(s + (float)Tn));
        g_eu[bh * Tn + i] = eu;
        atomicAdd(&g_tots[bh], eu);
    }
}

// ---------------- Sinkhorn row pass: warp-per-row ----------------
__global__ void sink_row_f(int slot_in, int slot_out) {
    int r0 = blockIdx.x * 8, bh = blockIdx.y;
    int tid = threadIdx.x, lane = tid & 31, w = tid >> 5;
    __shared__ float sev[Tn];
    __shared__ float sred[8];
    int jmax = r0 + 8;
    for (int j = tid; j < jmax; j += 256) sev[j] = g_ev[bh * Tn + j];
    float evtot = g_tots[slot_in * BHn + bh];
    __syncthreads();
    int i = r0 + w;
    const uint4* cv = (const uint4*)(g_c + ((size_t)bh * Tn + i) * Tn);
    int nv = (i + 8) >> 3;
    float s = 0.f;
    for (int vi = lane; vi < nv; vi += 32) {
        uint4 pk = cv[vi];
        const __half2* hp = (const __half2*)&pk;
        int jb = vi * 8;
        #pragma unroll
        for (int z = 0; z < 4; z++) {
            float2 f = __half22float2(hp[z]);
            s += f.x * sev[jb + 2 * z] + f.y * sev[jb + 2 * z + 1];
        }
    }
    s += __shfl_xor_sync(0xffffffffu, s, 16);
    s += __shfl_xor_sync(0xffffffffu, s, 8);
    s += __shfl_xor_sync(0xffffffffu, s, 4);
    s += __shfl_xor_sync(0xffffffffu, s, 2);
    s += __shfl_xor_sync(0xffffffffu, s, 1);
    if (lane == 0) {
        float eu = __expf(-LOGT - __logf(s + evtot));
        g_eu[bh * Tn + i] = eu;
        sred[w] = eu;
    }
    __syncthreads();
    if (tid == 0)
        atomicAdd(&g_tots[slot_out * BHn + bh],
                  sred[0] + sred[1] + sred[2] + sred[3] + sred[4] + sred[5] + sred[6] + sred[7]);
}

// ---------------- Sinkhorn col pass: partial over i-chunks, 4 cols/thread ----------------
__global__ void sink_col_part() {
    int cb = blockIdx.x;    // 0..1, 1024 cols each
    int ic = blockIdx.y;    // 0..7, 256-row chunk
    int bh = blockIdx.z;
    int tid = threadIdx.x;
    int j0 = cb * 1024 + tid * 4;
    int is = ic * 256;
    float* part = g_cpart + (size_t)(ic * BHn + bh) * Tn;
    if (cb * 1024 >= is + 256) {   // entirely above diagonal (incl. 128-pad): zero
        *(float4*)(part + j0) = make_float4(0.f, 0.f, 0.f, 0.f);
        return;
    }
    __shared__ float seu[256];
    seu[tid] = g_eu[bh * Tn + is + tid];
    __syncthreads();
    const __half* base = g_c + (size_t)bh * Tn * Tn + j0;
    float s0 = 0.f, s1 = 0.f, s2 = 0.f, s3 = 0.f;
    #pragma unroll 4
    for (int r = 0; r < 256; r++) {
        uint2 pk = *(const uint2*)(base + (size_t)(is + r) * Tn);
        float2 fa = __half22float2(*(const __half2*)&pk.x);
        float2 fb = __half22float2(*(const __half2*)&pk.y);
        float ui = seu[r];
        s0 += fa.x * ui;
        s1 += fa.y * ui;
        s2 += fb.x * ui;
        s3 += fb.y * ui;
    }
    part[j0] = s0;
    part[j0 + 1] = s1;
    part[j0 + 2] = s2;
    part[j0 + 3] = s3;
}

// ---------------- mid col finalize ----------------
__global__ void sink_col_fin(int slot_in, int slot_out) {
    int bh = blockIdx.y;
    int tid = threadIdx.x;
    int j = blockIdx.x * 256 + tid;
    float s = 0.f;
    #pragma unroll
    for (int ic = 0; ic < 8; ic++)
        s += g_cpart[(size_t)(ic * BHn + bh) * Tn + j];
    float ev = __expf(-LOGT - __logf(s + g_tots[slot_in * BHn + bh]));
    g_ev[bh * Tn + j] = ev;
    __shared__ float red[256];
    red[tid] = ev; __syncthreads();
    for (int o = 128; o > 0; o >>= 1) { if (tid < o) red[tid] += red[tid + o]; __syncthreads(); }
    if (tid == 0) atomicAdd(&g_tots[slot_out * BHn + bh], red[0]);
}

// ---------------- final col pass fused with W build ----------------
__global__ void sink_col_finw(int slot_in) {
    int bh = blockIdx.y;
    int tid = threadIdx.x;
    int jb = blockIdx.x * 256;
    int j = jb + tid;
    int b = bh / Hn, h = bh % Hn;
    float s = 0.f;
    #pragma unroll
    for (int ic = 0; ic < 8; ic++)
        s += g_cpart[(size_t)(ic * BHn + bh) * Tn + j];
    float ev = __expf(-LOGT - __logf(s + g_tots[slot_in * BHn + bh]));
    __shared__ float sev[256];
    sev[tid] = ev;
    __syncthreads();
    int d = tid & 63, rr = tid >> 6;
    const float* Vbase = g_qkv + (size_t)b * Tn * N3 + 2 * Cn + h * HDn + d;
    float part = 0.f;
    for (int r = rr; r < 256; r += 4) {
        int jj = jb + r;
        float w = sev[r] * Vbase[(size_t)jj * N3];
        part += w;
        float ws = fminf(fmaxf(w * WSCALE, -32768.f), 32768.f);
        __half hi = __float2half(ws);
        g_wh[((size_t)bh * Tn + jj) * HDn + d] = hi;
        g_wl[((size_t)bh * Tn + jj) * HDn + d] = __float2half(ws - __half2float(hi));
    }
    __shared__ float red[256];
    red[tid] = part;
    __syncthreads();
    if (tid < 128) red[tid] += red[tid + 128];
    __syncthreads();
    if (tid < 64) atomicAdd(&g_wtot[bh * HDn + tid], red[tid] + red[tid + 64]);
}

// ---------------- pi@V via fp16 TC, cp.async 2-stage; y as bf16 hi/lo ----------------
#define PVSM 73728
__global__ void __launch_bounds__(256) pi_v_tc() {
    extern __shared__ __half dynp[];
    int bh = blockIdx.y;
    int b = bh / Hn, h = bh % Hn;
    int it = gridDim.x - 1 - blockIdx.x;   // heavy blocks first
    int i0 = it * 128;
    int tid = threadIdx.x, wid = tid >> 5, lane = tid & 31;
    int wm = wid & 3, wn = wid >> 2;
    float acc[2][4][4] = {};
    unsigned base = (unsigned)__cvta_generic_to_shared(dynp);
    // stage s: A at s*9216 halfs (128x72); W at 18432 + s*9216 (hi 64x72, lo 64x72)
    int njc = 2 * (it + 1);
    auto load_stage = [&](int tc, int s) {
        int jc = tc * 64;
        unsigned aA = base + (s * 9216) * 2;
        unsigned aW = base + (18432 + s * 9216) * 2;
        #pragma unroll
        for (int z = 0; z < 4; z++) {
            int idx = z * 256 + tid;
            int r = idx >> 3, c8 = (idx & 7) * 8;
            cpa16(aA + (r * 72 + c8) * 2, g_c + ((size_t)bh * Tn + i0 + r) * Tn + jc + c8);
        }
        #pragma unroll
        for (int z = 0; z < 2; z++) {
            int idx = z * 256 + tid;
            int r = idx >> 3, c8 = (idx & 7) * 8;
            cpa16(aW + (r * 72 + c8) * 2, g_wh + ((size_t)bh * Tn + jc + r) * HDn + c8);
            cpa16(aW + (4608 + r * 72 + c8) * 2, g_wl + ((size_t)bh * Tn + jc + r) * HDn + c8);
        }
    };

    load_stage(0, 0);
    CPA_COMMIT;
    for (int tc = 0; tc < njc; tc++) {
        int cur = tc & 1;
        if (tc + 1 < njc) load_stage(tc + 1, cur ^ 1);
        CPA_COMMIT;
        CPA_WAIT1;
        __syncthreads();
        unsigned aA = base + (cur * 9216) * 2;
        unsigned aWh = base + (18432 + cur * 9216) * 2;
        unsigned aWl = aWh + 4608 * 2;
        #pragma unroll
        for (int kh = 0; kh < 64; kh += 16) {
            unsigned a_[2][4];
            #pragma unroll
            for (int mt = 0; mt < 2; mt++) {
                unsigned off = ((unsigned)((wm * 32 + mt * 16 + (lane & 15)) * 72 + kh + 8 * (lane >> 4))) * 2;
                ldmx4(aA + off, a_[mt][0], a_[mt][1], a_[mt][2], a_[mt][3]);
            }
            #pragma unroll
            for (int nq = 0; nq < 2; nq++) {
                int n0 = wn * 32 + nq * 16;
                unsigned boff = ((unsigned)((kh + (lane & 7) + 8 * ((lane >> 3) & 1)) * 72 + n0 + 8 * (lane >> 4))) * 2;
                unsigned bh0, bh1, bh2, bh3, bl0, bl1, bl2, bl3;
                ldmx4t(aWh + boff, bh0, bh1, bh2, bh3);
                ldmx4t(aWl + boff, bl0, bl1, bl2, bl3);
                #pragma unroll
                for (int mt = 0; mt < 2; mt++) {
                    mma_f16(acc[mt][2 * nq],     a_[mt][0], a_[mt][1], a_[mt][2], a_[mt][3], bh0, bh1);
                    mma_f16(acc[mt][2 * nq],     a_[mt][0], a_[mt][1], a_[mt][2], a_[mt][3], bl0, bl1);
                    mma_f16(acc[mt][2 * nq + 1], a_[mt][0], a_[mt][1], a_[mt][2], a_[mt][3], bh2, bh3);
                    mma_f16(acc[mt][2 * nq + 1], a_[mt][0], a_[mt][1], a_[mt][2], a_[mt][3], bl2, bl3);
                }
            }
        }
        __syncthreads();
    }
    #pragma unroll
    for (int mt = 0; mt < 2; mt++) {
        #pragma unroll
        for (int f = 0; f < 4; f++) {
            float* cc = acc[mt][f];
            int r = i0 + wm * 32 + mt * 16 + (lane >> 2);
            int d = wn * 32 + f * 8 + 2 * (lane & 3);
            float wt0 = g_wtot[bh * HDn + d], wt1 = g_wtot[bh * HDn + d + 1];
            float eu0 = g_eu[bh * Tn + r] * 2048.f;
            float eu1 = g_eu[bh * Tn + r + 8] * 2048.f;
            float y0 = (cc[0] * WINV + wt0) * eu0;
            float y1 = (cc[1] * WINV + wt1) * eu0;
            float y2 = (cc[2] * WINV + wt0) * eu1;
            float y3 = (cc[3] * WINV + wt1) * eu1;
            size_t obase = ((size_t)(b * Tn) + r) * Cn + h * HDn + d;
            __nv_bfloat16 h0 = __float2bfloat16(y0), h1 = __float2bfloat16(y1);
            __nv_bfloat16 h2 = __float2bfloat16(y2), h3 = __float2bfloat16(y3);
            g_ah[obase] = h0;
            g_ah[obase + 1] = h1;
            g_ah[obase + (size_t)8 * Cn] = h2;
            g_ah[obase + (size_t)8 * Cn + 1] = h3;
            g_al[obase] = __float2bfloat16(y0 - __bfloat162float(h0));
            g_al[obase + 1] = __float2bfloat16(y1 - __bfloat162float(h1));
            g_al[obase + (size_t)8 * Cn] = __float2bfloat16(y2 - __bfloat162float(h2));
            g_al[obase + (size_t)8 * Cn + 1] = __float2bfloat16(y3 - __bfloat162float(h3));
        }
    }
}

// ---------------- launch ----------------
extern "C" void kernel_launch(void* const* d_in, const int* in_sizes, int n_in,
                              void* d_out, int out_size) {
    const float* x      = (const float*)d_in[0];
    const float* t      = (const float*)d_in[1];
    const float* ln1_w  = (const float*)d_in[2];
    const float* ln1_b  = (const float*)d_in[3];
    const float* attn_w = (const float*)d_in[4];
    const float* attn_b = (const float*)d_in[5];
    const float* proj_w = (const float*)d_in[6];
    const float* proj_b = (const float*)d_in[7];
    const float* ln2_w  = (const float*)d_in[8];
    const float* ln2_b  = (const float*)d_in[9];
    const float* fc_w   = (const float*)d_in[10];
    const float* fc_b   = (const float*)d_in[11];
    const float* fc2_w  = (const float*)d_in[12];
    const float* fc2_b  = (const float*)d_in[13];
    float* out = (float*)d_out;

    float *p_qkv, *p_h;
    __nv_bfloat16 *p_ah, *p_al, *p_a2h, *p_a2l, *p_bh, *p_bl;
    cudaGetSymbolAddress((void**)&p_qkv, g_qkv);
    cudaGetSymbolAddress((void**)&p_h,   g_h);
    cudaGetSymbolAddress((void**)&p_ah,  g_ah);
    cudaGetSymbolAddress((void**)&p_al,  g_al);
    cudaGetSymbolAddress((void**)&p_a2h, g_a2h);
    cudaGetSymbolAddress((void**)&p_a2l, g_a2l);
    cudaGetSymbolAddress((void**)&p_bh,  g_bh);
    cudaGetSymbolAddress((void**)&p_bl,  g_bl);

    static int smem_set = 0;
    const int GSM64 = 55296;
    if (!smem_set) {
        cudaFuncSetAttribute(gemm64u, cudaFuncAttributeMaxDynamicSharedMemorySize, GSM64);
        cudaFuncSetAttribute(pi_v_tc, cudaFuncAttributeMaxDynamicSharedMemorySize, PVSM);
        smem_set = 1;
    }

    // ---- setup (zeroing fused into conv_w_all) ----
    conv_w_all<<<(WTOTAL / 4 + 255) / 256, 256>>>(attn_w, proj_w, fc_w, fc2_w);

    // ---- attention sub-block ----
    ln_bf<<<ROWS, 256>>>(x, t, ln1_w, ln1_b, p_ah, p_al);
    gemm64u<<<dim3(N3 / 128, ROWS / 64), 256, GSM64>>>(p_ah, p_al, p_bh + WOFF_QKV, p_bl + WOFF_QKV, attn_b,
                                                       p_qkv, nullptr, nullptr, ROWS, N3, KA_LN, 0, 2);
    score_tc<<<dim3(136, BHn), 256>>>();
    em1_row<<<dim3(Tn, BHn), 256>>>();

    // sinkhorn remaining 5 passes
    sink_col_part<<<dim3(2, 8, BHn), 256>>>();
    sink_col_fin<<<dim3(8, BHn), 256>>>(0, 1);
    sink_row_f<<<dim3(Tn / 8, BHn), 256>>>(1, 2);
    sink_col_part<<<dim3(2, 8, BHn), 256>>>();
    sink_col_fin<<<dim3(8, BHn), 256>>>(2, 3);
    sink_row_f<<<dim3(Tn / 8, BHn), 256>>>(3, 4);
    sink_col_part<<<dim3(2, 8, BHn), 256>>>();
    sink_col_finw<<<dim3(8, BHn), 256>>>(4);

    pi_v_tc<<<dim3(Tn / 128, BHn), 256, PVSM>>>();

    // proj
    gemm64u<<<dim3(Cn / 128, ROWS / 64), 256, GSM64>>>(p_ah, p_al, p_bh + WOFF_PRJ, p_bl + WOFF_PRJ, proj_b,
                                                       p_h, nullptr, nullptr, ROWS, Cn, Cn, 0, 0);

    // ---- MLP sub-block ----
    ln_bf<<<ROWS, 256>>>(p_h, t, ln2_w, ln2_b, p_ah, p_al);
    gemm64u<<<dim3(N4 / 128, ROWS / 64), 256, GSM64>>>(p_ah, p_al, p_bh + WOFF_FC, p_bl + WOFF_FC, fc_b,
                                                       nullptr, p_a2h, p_a2l, ROWS, N4, KA_LN, 1, 1);
    gemm64u<<<dim3(Cn / 128, ROWS / 64), 256, GSM64>>>(p_a2h, p_a2l, p_bh + WOFF_FC2, p_bl + WOFF_FC2, fc2_b,
                                                       out, nullptr, nullptr, ROWS, Cn, N4, 0, 0);
}

// round 15
// speedup vs baseline: 1.1047x; 1.0631x over previous
#include <cuda_runtime.h>
#include <cuda_fp16.h>
#include <cuda_bf16.h>
#include <math.h>

#define Tn 2048
#define Cn 384
#define Hn 6
#define HDn 64
#define Bn 2
#define BHn 12
#define ROWS 4096
#define C1 385
#define KA_LN 416
#define N3 1152
#define N4 1536
#define LOGT 7.62461899f
#define WSCALE 512.f
#define WINV   (1.f / 512.f)

#define WOFF_QKV 0
#define WSZ_QKV  (KA_LN * N3)
#define WOFF_PRJ (WOFF_QKV + WSZ_QKV)
#define WSZ_PRJ  (Cn * Cn)
#define WOFF_FC  (WOFF_PRJ + WSZ_PRJ)
#define WSZ_FC   (KA_LN * N4)
#define WOFF_FC2 (WOFF_FC + WSZ_FC)
#define WSZ_FC2  (N4 * Cn)
#define WTOTAL   (WOFF_FC2 + WSZ_FC2)

// ---------------- scratch ----------------
__device__ __align__(16) float g_qkv[ROWS * N3];
__device__ __align__(16) __half g_e[(size_t)BHn * Tn * Tn];
__device__ __align__(16) __half g_c[(size_t)BHn * Tn * Tn];
__device__ __align__(16) __nv_bfloat16 g_qh[ROWS * Cn];
__device__ __align__(16) __nv_bfloat16 g_ql[ROWS * Cn];
__device__ __align__(16) __nv_bfloat16 g_kh[ROWS * Cn];
__device__ __align__(16) __nv_bfloat16 g_kl[ROWS * Cn];
__device__ __align__(16) __half g_wh[BHn * Tn * HDn];
__device__ __align__(16) __half g_wl[BHn * Tn * HDn];
__device__ float g_rowsum[BHn * Tn];
__device__ float g_eu[BHn * Tn];
__device__ float g_ev[BHn * Tn];
__device__ float g_tots[8 * BHn];
__device__ float g_wtot[BHn * HDn];
__device__ __align__(16) float g_cpart[8 * BHn * Tn];
__device__ __align__(16) float g_h[ROWS * Cn];
__device__ __align__(16) __nv_bfloat16 g_ah[ROWS * N4];
__device__ __align__(16) __nv_bfloat16 g_al[ROWS * N4];
__device__ __align__(16) __nv_bfloat16 g_a2h[ROWS * N4];
__device__ __align__(16) __nv_bfloat16 g_a2l[ROWS * N4];
__device__ __align__(16) __nv_bfloat16 g_bh[WTOTAL];
__device__ __align__(16) __nv_bfloat16 g_bl[WTOTAL];

// ---------------- helpers ----------------
__device__ __forceinline__ void ldmx4(unsigned addr, unsigned& r0, unsigned& r1, unsigned& r2, unsigned& r3) {
    asm volatile("ldmatrix.sync.aligned.m8n8.x4.shared.b16 {%0,%1,%2,%3},[%4];"
                 : "=r"(r0), "=r"(r1), "=r"(r2), "=r"(r3) : "r"(addr));
}
__device__ __forceinline__ void ldmx4t(unsigned addr, unsigned& r0, unsigned& r1, unsigned& r2, unsigned& r3) {
    asm volatile("ldmatrix.sync.aligned.m8n8.x4.trans.shared.b16 {%0,%1,%2,%3},[%4];"
                 : "=r"(r0), "=r"(r1), "=r"(r2), "=r"(r3) : "r"(addr));
}
__device__ __forceinline__ void mma_bf16(float* c, unsigned a0, unsigned a1, unsigned a2, unsigned a3,
                                         unsigned b0, unsigned b1) {
    asm volatile("mma.sync.aligned.m16n8k16.row.col.f32.bf16.bf16.f32 "
                 "{%0,%1,%2,%3},{%4,%5,%6,%7},{%8,%9},{%0,%1,%2,%3};"
                 : "+f"(c[0]), "+f"(c[1]), "+f"(c[2]), "+f"(c[3])
                 : "r"(a0), "r"(a1), "r"(a2), "r"(a3), "r"(b0), "r"(b1));
}
__device__ __forceinline__ void mma_f16(float* c, unsigned a0, unsigned a1, unsigned a2, unsigned a3,
                                        unsigned b0, unsigned b1) {
    asm volatile("mma.sync.aligned.m16n8k16.row.col.f32.f16.f16.f32 "
                 "{%0,%1,%2,%3},{%4,%5,%6,%7},{%8,%9},{%0,%1,%2,%3};"
                 : "+f"(c[0]), "+f"(c[1]), "+f"(c[2]), "+f"(c[3])
                 : "r"(a0), "r"(a1), "r"(a2), "r"(a3), "r"(b0), "r"(b1));
}
__device__ __forceinline__ void cpa16(unsigned dst, const void* src) {
    asm volatile("cp.async.cg.shared.global [%0],[%1],16;" :: "r"(dst), "l"(src));
}
#define CPA_COMMIT asm volatile("cp.async.commit_group;")
#define CPA_WAIT1  asm volatile("cp.async.wait_group 1;")

__device__ __forceinline__ float em1p(float x) {
    float t = fmaf(x, 0.125f, 1.f);
    t = fmaf(x * 0.14285714f, t, 1.f);
    t = fmaf(x * 0.16666667f, t, 1.f);
    t = fmaf(x * 0.2f,        t, 1.f);
    t = fmaf(x * 0.25f,       t, 1.f);
    t = fmaf(x * 0.33333333f, t, 1.f);
    t = fmaf(x * 0.5f,        t, 1.f);
    return x * t;
}

// ---------------- weights -> bf16 hi/lo (+ fused zeroing) ----------------
__global__ void conv_w_all(const float* __restrict__ w0, const float* __restrict__ w1,
                           const float* __restrict__ w2, const float* __restrict__ w3) {
    int idx = blockIdx.x * 256 + threadIdx.x;
    if (idx < BHn * Tn) g_rowsum[idx] = 0.f;
    if (idx < BHn * HDn) g_wtot[idx] = 0.f;
    if (idx < 8 * BHn) g_tots[idx] = 0.f;
    int e = idx * 4;
    if (e >= WTOTAL) return;
    const float* src;
    int K, N, local;
    if (e < WOFF_PRJ)       { src = w0; K = C1;  N = N3; local = e - WOFF_QKV; }
    else if (e < WOFF_FC)   { src = w1; K = Cn;  N = Cn; local = e - WOFF_PRJ; }
    else if (e < WOFF_FC2)  { src = w2; K = C1;  N = N4; local = e - WOFF_FC;  }
    else                    { src = w3; K = N4;  N = Cn; local = e - WOFF_FC2; }
    int row = local / N, col = local % N;
    float4 v = (row < K) ? *(const float4*)(src + (size_t)row * N + col)
                         : make_float4(0.f, 0.f, 0.f, 0.f);
    __nv_bfloat16 h0 = __float2bfloat16(v.x), h1 = __float2bfloat16(v.y);
    __nv_bfloat16 h2 = __float2bfloat16(v.z), h3 = __float2bfloat16(v.w);
    __nv_bfloat16 hbuf[4] = {h0, h1, h2, h3};
    __nv_bfloat16 lbuf[4] = {
        __float2bfloat16(v.x - __bfloat162float(h0)), __float2bfloat16(v.y - __bfloat162float(h1)),
        __float2bfloat16(v.z - __bfloat162float(h2)), __float2bfloat16(v.w - __bfloat162float(h3))};
    *(uint2*)(g_bh + e) = *(uint2*)hbuf;
    *(uint2*)(g_bl + e) = *(uint2*)lbuf;
}

// ---------------- LayerNorm -> bf16 hi/lo ----------------
__global__ void ln_bf(const float* __restrict__ x, const float* __restrict__ t,
                      const float* __restrict__ w, const float* __restrict__ bb,
                      __nv_bfloat16* __restrict__ oh, __nv_bfloat16* __restrict__ ol) {
    int row = blockIdx.x;
    int tid = threadIdx.x;
    __shared__ float sx[C1];
    __shared__ float red[256];
    float s1 = 0.f;
    for (int c = tid; c < C1; c += 256) {
        float v = (c < Cn) ? x[(size_t)row * Cn + c] : t[0];
        sx[c] = v;
        s1 += v;
    }
    red[tid] = s1; __syncthreads();
    for (int o = 128; o > 0; o >>= 1) { if (tid < o) red[tid] += red[tid + o]; __syncthreads(); }
    float mean = red[0] * (1.f / C1);
    __syncthreads();
    float s2 = 0.f;
    for (int c = tid; c < C1; c += 256) { float d = sx[c] - mean; s2 += d * d; }
    red[tid] = s2; __syncthreads();
    for (int o = 128; o > 0; o >>= 1) { if (tid < o) red[tid] += red[tid + o]; __syncthreads(); }
    float rs = rsqrtf(red[0] * (1.f / C1) + 1e-5f);
    for (int c = tid; c < C1; c += 256) {
        float v = (sx[c] - mean) * rs * w[c] + bb[c];
        __nv_bfloat16 hi = __float2bfloat16(v);
        oh[(size_t)row * KA_LN + c] = hi;
        ol[(size_t)row * KA_LN + c] = __float2bfloat16(v - __bfloat162float(hi));
    }
    if (tid < KA_LN - C1) {
        oh[(size_t)row * KA_LN + C1 + tid] = __float2bfloat16(0.f);
        ol[(size_t)row * KA_LN + C1 + tid] = __float2bfloat16(0.f);
    }
}

// ---------------- unified pipelined bf16 GEMM, 64x128 tile ----------------
__global__ void __launch_bounds__(256) gemm64u(const __nv_bfloat16* __restrict__ Ah,
                                               const __nv_bfloat16* __restrict__ Al,
                                               const __nv_bfloat16* __restrict__ Bh,
                                               const __nv_bfloat16* __restrict__ Bl,
                                               const float* __restrict__ bias,
                                               float* __restrict__ outF,
                                               __nv_bfloat16* __restrict__ oAh,
                                               __nv_bfloat16* __restrict__ oAl,
                                               int M, int N, int Ka, int act, int obf) {
    extern __shared__ __nv_bfloat16 dyn[];
    __nv_bfloat16* sA = dyn;
    __nv_bfloat16* sB = dyn + 4 * 2560;
    int tid = threadIdx.x;
    int wid = tid >> 5, lane = tid & 31;
    int wm = wid & 1, wn = wid >> 1;
    int bm = blockIdx.y * 64, bn = blockIdx.x * 128;
    float acc[2][4][4] = {};
    unsigned sAu = (unsigned)__cvta_generic_to_shared(sA);
    unsigned sBu = (unsigned)__cvta_generic_to_shared(sB);

    int nk = Ka >> 5;
    auto load_stage = [&](int kt, int st) {
        unsigned aH = sAu + (st * 2 + 0) * 2560 * 2;
        unsigned aL = sAu + (st * 2 + 1) * 2560 * 2;
        unsigned bH = sBu + (st * 2 + 0) * 4352 * 2;
        unsigned bL = sBu + (st * 2 + 1) * 4352 * 2;
        int k0 = kt * 32;
        {
            int row = tid >> 2, cq = (tid & 3) * 8;
            cpa16(aH + (row * 40 + cq) * 2, Ah + (size_t)(bm + row) * Ka + k0 + cq);
            cpa16(aL + (row * 40 + cq) * 2, Al + (size_t)(bm + row) * Ka + k0 + cq);
        }
        #pragma unroll
        for (int z = 0; z < 2; z++) {
            int idx = z * 256 + tid;
            int row = idx >> 4, cq = (idx & 15) * 8;
            cpa16(bH + (row * 136 + cq) * 2, Bh + (size_t)(k0 + row) * N + bn + cq);
            cpa16(bL + (row * 136 + cq) * 2, Bl + (size_t)(k0 + row) * N + bn + cq);
        }
    };

    load_stage(0, 0);
    CPA_COMMIT;
    for (int kt = 0; kt < nk; kt++) {
        int cur = kt & 1;
        if (kt + 1 < nk) load_stage(kt + 1, cur ^ 1);
        CPA_COMMIT;
        CPA_WAIT1;
        __syncthreads();
        unsigned aH = sAu + (cur * 2 + 0) * 2560 * 2;
        unsigned aL = sAu + (cur * 2 + 1) * 2560 * 2;
        unsigned bH = sBu + (cur * 2 + 0) * 4352 * 2;
        unsigned bL = sBu + (cur * 2 + 1) * 4352 * 2;
        #pragma unroll
        for (int kh = 0; kh < 32; kh += 16) {
            unsigned ah[2][4], al[2][4];
            #pragma unroll
            for (int mt = 0; mt < 2; mt++) {
                unsigned off = ((unsigned)((wm * 32 + mt * 16 + (lane & 15)) * 40 + kh + (lane >> 4) * 8)) * 2;
                ldmx4(aH + off, ah[mt][0], ah[mt][1], ah[mt][2], ah[mt][3]);
                ldmx4(aL + off, al[mt][0], al[mt][1], al[mt][2], al[mt][3]);
            }
            #pragma unroll
            for (int np = 0; np < 2; np++) {
                int n0 = wn * 32 + np * 16;
                unsigned boff = ((unsigned)((kh + (lane & 7) + 8 * ((lane >> 3) & 1)) * 136 + n0 + 8 * (lane >> 4))) * 2;
                unsigned bh0, bh1, bh2, bh3, bl0, bl1, bl2, bl3;
                ldmx4t(bH + boff, bh0, bh1, bh2, bh3);
                ldmx4t(bL + boff, bl0, bl1, bl2, bl3);
                #pragma unroll
                for (int mt = 0; mt < 2; mt++) {
                    mma_bf16(acc[mt][2 * np],     ah[mt][0], ah[mt][1], ah[mt][2], ah[mt][3], bh0, bh1);
                    mma_bf16(acc[mt][2 * np],     ah[mt][0], ah[mt][1], ah[mt][2], ah[mt][3], bl0, bl1);
                    mma_bf16(acc[mt][2 * np],     al[mt][0], al[mt][1], al[mt][2], al[mt][3], bh0, bh1);
                    mma_bf16(acc[mt][2 * np + 1], ah[mt][0], ah[mt][1], ah[mt][2], ah[mt][3], bh2, bh3);
                    mma_bf16(acc[mt][2 * np + 1], ah[mt][0], ah[mt][1], ah[mt][2], ah[mt][3], bl2, bl3);
                    mma_bf16(acc[mt][2 * np + 1], al[mt][0], al[mt][1], al[mt][2], al[mt][3], bh2, bh3);
                }
            }
        }
        __syncthreads();
    }
    #pragma unroll
    for (int mt = 0; mt < 2; mt++) {
        #pragma unroll
        for (int nt = 0; nt < 4; nt++) {
            float* cc = acc[mt][nt];
            int r = bm + wm * 32 + mt * 16 + (lane >> 2);
            int cn = bn + wn * 32 + (nt >> 1) * 16 + (nt & 1) * 8 + (lane & 3) * 2;
            float b0 = bias[cn], b1 = bias[cn + 1];
            float v0 = cc[0] + b0, v1 = cc[1] + b1;
            float v2 = cc[2] + b0, v3 = cc[3] + b1;
            if (act == 1) {
                v0 = 0.5f * v0 * (1.f + erff(v0 * 0.70710678f));
                v1 = 0.5f * v1 * (1.f + erff(v1 * 0.70710678f));
                v2 = 0.5f * v2 * (1.f + erff(v2 * 0.70710678f));
                v3 = 0.5f * v3 * (1.f + erff(v3 * 0.70710678f));
            }
            if (obf == 1) {
                __nv_bfloat16 h0 = __float2bfloat16(v0), h1 = __float2bfloat16(v1);
                __nv_bfloat16 h2 = __float2bfloat16(v2), h3 = __float2bfloat16(v3);
                oAh[(size_t)r * N + cn] = h0;
                oAh[(size_t)r * N + cn + 1] = h1;
                oAh[(size_t)(r + 8) * N + cn] = h2;
                oAh[(size_t)(r + 8) * N + cn + 1] = h3;
                oAl[(size_t)r * N + cn] = __float2bfloat16(v0 - __bfloat162float(h0));
                oAl[(size_t)r * N + cn + 1] = __float2bfloat16(v1 - __bfloat162float(h1));
                oAl[(size_t)(r + 8) * N + cn] = __float2bfloat16(v2 - __bfloat162float(h2));
                oAl[(size_t)(r + 8) * N + cn + 1] = __float2bfloat16(v3 - __bfloat162float(h3));
            } else {
                outF[(size_t)r * N + cn] = v0;
                outF[(size_t)r * N + cn + 1] = v1;
                outF[(size_t)(r + 8) * N + cn] = v2;
                outF[(size_t)(r + 8) * N + cn + 1] = v3;
                if (obf == 2 && cn < 2 * Cn) {
                    int isK = cn >= Cn;
                    int c2 = cn - isK * Cn;
                    __nv_bfloat16* H = isK ? g_kh : g_qh;
                    __nv_bfloat16* L = isK ? g_kl : g_ql;
                    __nv_bfloat16 h0 = __float2bfloat16(v0), h1 = __float2bfloat16(v1);
                    __nv_bfloat16 h2 = __float2bfloat16(v2), h3 = __float2bfloat16(v3);
                    H[(size_t)r * Cn + c2] = h0;
                    H[(size_t)r * Cn + c2 + 1] = h1;
                    H[(size_t)(r + 8) * Cn + c2] = h2;
                    H[(size_t)(r + 8) * Cn + c2 + 1] = h3;
                    L[(size_t)r * Cn + c2] = __float2bfloat16(v0 - __bfloat162float(h0));
                    L[(size_t)r * Cn + c2 + 1] = __float2bfloat16(v1 - __bfloat162float(h1));
                    L[(size_t)(r + 8) * Cn + c2] = __float2bfloat16(v2 - __bfloat162float(h2));
                    L[(size_t)(r + 8) * Cn + c2 + 1] = __float2bfloat16(v3 - __bfloat162float(h3));
                }
            }
        }
    }
}

// ---------------- TC scores + fused exp + inline row sums (triangular grid) ----------------
__global__ void __launch_bounds__(256, 2) score_tc() {
    int li = blockIdx.x, bh = blockIdx.y;
    int it = (int)((sqrtf(8.f * li + 1.f) - 1.f) * 0.5f);
    while ((it + 1) * (it + 2) / 2 <= li) it++;
    while (it * (it + 1) / 2 > li) it--;
    int jt = li - it * (it + 1) / 2;
    int b = bh / Hn, h = bh % Hn;
    __shared__ __nv_bfloat16 sQh[128][40], sQl[128][40], sKh[128][40], sKl[128][40];
    int tid = threadIdx.x, wid = tid >> 5, lane = tid & 31;
    int wm = wid & 3, wn = wid >> 2;
    float acc[2][8][4] = {};
    unsigned aQh = (unsigned)__cvta_generic_to_shared(&sQh[0][0]);
    unsigned aQl = (unsigned)__cvta_generic_to_shared(&sQl[0][0]);
    unsigned aKh = (unsigned)__cvta_generic_to_shared(&sKh[0][0]);
    unsigned aKl = (unsigned)__cvta_generic_to_shared(&sKl[0][0]);
    size_t qbase = ((size_t)(b * Tn + it * 128)) * Cn + h * HDn;
    size_t kbase = ((size_t)(b * Tn + jt * 128)) * Cn + h * HDn;

    for (int ks = 0; ks < 2; ks++) {
        if (ks) __syncthreads();
        #pragma unroll
        for (int z = 0; z < 2; z++) {
            int idx = z * 256 + tid;
            int r = idx >> 2, c8 = (idx & 3) * 8;
            *(uint4*)&sQh[r][c8] = *(const uint4*)(g_qh + qbase + (size_t)r * Cn + ks * 32 + c8);
            *(uint4*)&sQl[r][c8] = *(const uint4*)(g_ql + qbase + (size_t)r * Cn + ks * 32 + c8);
            *(uint4*)&sKh[r][c8] = *(const uint4*)(g_kh + kbase + (size_t)r * Cn + ks * 32 + c8);
            *(uint4*)&sKl[r][c8] = *(const uint4*)(g_kl + kbase + (size_t)r * Cn + ks * 32 + c8);
        }
        __syncthreads();
        #pragma unroll
        for (int kh = 0; kh < 32; kh += 16) {
            unsigned qh_[2][4], ql_[2][4];
            #pragma unroll
            for (int mt = 0; mt < 2; mt++) {
                unsigned off = ((unsigned)((wm * 32 + mt * 16 + (lane & 15)) * 40 + kh + 8 * (lane >> 4))) * 2;
                ldmx4(aQh + off, qh_[mt][0], qh_[mt][1], qh_[mt][2], qh_[mt][3]);
                ldmx4(aQl + off, ql_[mt][0], ql_[mt][1], ql_[mt][2], ql_[mt][3]);
            }
            #pragma unroll
            for (int nq = 0; nq < 4; nq++) {
                int n0 = wn * 64 + nq * 16;
                unsigned boff = ((unsigned)((n0 + (lane & 15)) * 40 + kh + 8 * (lane >> 4))) * 2;
                unsigned kh0, kh1, kh2, kh3, kl0, kl1, kl2, kl3;
                ldmx4(aKh + boff, kh0, kh1, kh2, kh3);
                ldmx4(aKl + boff, kl0, kl1, kl2, kl3);
                #pragma unroll
                for (int mt = 0; mt < 2; mt++) {
                    mma_bf16(acc[mt][2 * nq],     qh_[mt][0], qh_[mt][1], qh_[mt][2], qh_[mt][3], kh0, kh2);
                    mma_bf16(acc[mt][2 * nq],     qh_[mt][0], qh_[mt][1], qh_[mt][2], qh_[mt][3], kl0, kl2);
                    mma_bf16(acc[mt][2 * nq],     ql_[mt][0], ql_[mt][1], ql_[mt][2], ql_[mt][3], kh0, kh2);
                    mma_bf16(acc[mt][2 * nq + 1], qh_[mt][0], qh_[mt][1], qh_[mt][2], qh_[mt][3], kh1, kh3);
                    mma_bf16(acc[mt][2 * nq + 1], qh_[mt][0], qh_[mt][1], qh_[mt][2], qh_[mt][3], kl1, kl3);
                    mma_bf16(acc[mt][2 * nq + 1], ql_[mt][0], ql_[mt][1], ql_[mt][2], ql_[mt][3], kh1, kh3);
                }
            }
        }
    }
    __half* erow = g_e + (size_t)bh * Tn * Tn;
    float rsum[2][2] = {};
    int diag = (it == jt);
    #pragma unroll
    for (int mt = 0; mt < 2; mt++) {
        #pragma unroll
        for (int f = 0; f < 8; f++) {
            float* cc = acc[mt][f];
            int gi = it * 128 + wm * 32 + mt * 16 + (lane >> 2);
            int gj = jt * 128 + wn * 64 + (f >> 1) * 16 + (f & 1) * 8 + 2 * (lane & 3);
            float e0 = __expf(fminf(cc[0] * 0.125f, 11.f));
            float e1 = __expf(fminf(cc[1] * 0.125f, 11.f));
            float e2 = __expf(fminf(cc[2] * 0.125f, 11.f));
            float e3 = __expf(fminf(cc[3] * 0.125f, 11.f));
            if (diag) {
                if (gj > gi) e0 = 0.f;
                if (gj + 1 > gi) e1 = 0.f;
                if (gj > gi + 8) e2 = 0.f;
                if (gj + 1 > gi + 8) e3 = 0.f;
            }
            rsum[mt][0] += e0 + e1;
            rsum[mt][1] += e2 + e3;
            *(__half2*)(erow + (size_t)gi * Tn + gj) = __floats2half2_rn(e0, e1);
            *(__half2*)(erow + (size_t)(gi + 8) * Tn + gj) = __floats2half2_rn(e2, e3);
        }
    }
    #pragma unroll
    for (int mt = 0; mt < 2; mt++) {
        #pragma unroll
        for (int hh = 0; hh < 2; hh++) {
            float v = rsum[mt][hh];
            v += __shfl_xor_sync(0xffffffffu, v, 1);
            v += __shfl_xor_sync(0xffffffffu, v, 2);
            if ((lane & 3) == 0) {
                int gi = it * 128 + wm * 32 + mt * 16 + (lane >> 2) + hh * 8;
                atomicAdd(&g_rowsum[bh * Tn + gi], v);
            }
        }
    }
}

// ---------------- per row: Em1 = expm1(e/rowsum); eu; eutot -> slot0 ----------------
__global__ void em1_row() {
    int i = blockIdx.x, bh = blockIdx.y;
    int tid = threadIdx.x;
    int lane = tid & 31, wid = tid >> 5;
    float inv = 1.f / g_rowsum[bh * Tn + i];
    const uint4* src = (const uint4*)(g_e + ((size_t)bh * Tn + i) * Tn);
    uint4* dst = (uint4*)(g_c + ((size_t)bh * Tn + i) * Tn);
    int nv = ((i >> 7) + 1) << 4;
    float se = 0.f;
    if (tid < nv) {
        uint4 pk = src[tid];
        const __half2* hp = (const __half2*)&pk;
        uint4 outp;
        __half2* op = (__half2*)&outp;
        #pragma unroll
        for (int z = 0; z < 4; z++) {
            float2 f = __half22float2(hp[z]);
            float a = em1p(f.x * inv);
            float bb = em1p(f.y * inv);
            se += a + bb;
            op[z] = __floats2half2_rn(a, bb);
        }
        dst[tid] = outp;
    }
    se += __shfl_xor_sync(0xffffffffu, se, 16);
    se += __shfl_xor_sync(0xffffffffu, se, 8);
    se += __shfl_xor_sync(0xffffffffu, se, 4);
    se += __shfl_xor_sync(0xffffffffu, se, 2);
    se += __shfl_xor_sync(0xffffffffu, se, 1);
    __shared__ float red[8];
    if (lane == 0) red[wid] = se;
    __syncthreads();
    if (tid == 0) {
        float s = red[0] + red[1] + red[2] + red[3] + red[4] + red[5] + red[6] + red[7];
        float eu = __expf(-LOGT - __logf(s + (float)Tn));
        g_eu[bh * Tn + i] = eu;
        atomicAdd(&g_tots[bh], eu);
    }
}

// ---------------- Sinkhorn row pass: warp-per-row ----------------
__global__ void sink_row_f(int slot_in, int slot_out) {
    int r0 = blockIdx.x * 8, bh = blockIdx.y;
    int tid = threadIdx.x, lane = tid & 31, w = tid >> 5;
    __shared__ float sev[Tn];
    __shared__ float sred[8];
    int jmax = r0 + 8;
    for (int j = tid; j < jmax; j += 256) sev[j] = g_ev[bh * Tn + j];
    float evtot = g_tots[slot_in * BHn + bh];
    __syncthreads();
    int i = r0 + w;
    const uint4* cv = (const uint4*)(g_c + ((size_t)bh * Tn + i) * Tn);
    int nv = (i + 8) >> 3;
    float s = 0.f;
    for (int vi = lane; vi < nv; vi += 32) {
        uint4 pk = cv[vi];
        const __half2* hp = (const __half2*)&pk;
        int jb = vi * 8;
        #pragma unroll
        for (int z = 0; z < 4; z++) {
            float2 f = __half22float2(hp[z]);
            s += f.x * sev[jb + 2 * z] + f.y * sev[jb + 2 * z + 1];
        }
    }
    s += __shfl_xor_sync(0xffffffffu, s, 16);
    s += __shfl_xor_sync(0xffffffffu, s, 8);
    s += __shfl_xor_sync(0xffffffffu, s, 4);
    s += __shfl_xor_sync(0xffffffffu, s, 2);
    s += __shfl_xor_sync(0xffffffffu, s, 1);
    if (lane == 0) {
        float eu = __expf(-LOGT - __logf(s + evtot));
        g_eu[bh * Tn + i] = eu;
        sred[w] = eu;
    }
    __syncthreads();
    if (tid == 0)
        atomicAdd(&g_tots[slot_out * BHn + bh],
                  sred[0] + sred[1] + sred[2] + sred[3] + sred[4] + sred[5] + sred[6] + sred[7]);
}

// ---------------- Sinkhorn col pass: partial over i-chunks ----------------
__global__ void sink_col_part() {
    int cb = blockIdx.x;
    int ic = blockIdx.y;
    int bh = blockIdx.z;
    int tid = threadIdx.x;
    int j0 = cb * 512 + tid * 2;
    int is = ic * 256;
    float* part = g_cpart + (size_t)(ic * BHn + bh) * Tn;
    if (cb * 512 >= is + 256) {
        part[j0] = 0.f;
        part[j0 + 1] = 0.f;
        return;
    }
    __shared__ float seu[256];
    seu[tid] = g_eu[bh * Tn + is + tid];
    __syncthreads();
    const __half* base = g_c + (size_t)bh * Tn * Tn + j0;
    float s0 = 0.f, s1 = 0.f;
    #pragma unroll 4
    for (int r = 0; r < 256; r++) {
        __half2 hh = *(const __half2*)(base + (size_t)(is + r) * Tn);
        float2 f = __half22float2(hh);
        float ui = seu[r];
        s0 += f.x * ui;
        s1 += f.y * ui;
    }
    part[j0] = s0;
    part[j0 + 1] = s1;
}

// ---------------- mid col finalize ----------------
__global__ void sink_col_fin(int slot_in, int slot_out) {
    int bh = blockIdx.y;
    int tid = threadIdx.x;
    int j = blockIdx.x * 256 + tid;
    float s = 0.f;
    #pragma unroll
    for (int ic = 0; ic < 8; ic++)
        s += g_cpart[(size_t)(ic * BHn + bh) * Tn + j];
    float ev = __expf(-LOGT - __logf(s + g_tots[slot_in * BHn + bh]));
    g_ev[bh * Tn + j] = ev;
    __shared__ float red[256];
    red[tid] = ev; __syncthreads();
    for (int o = 128; o > 0; o >>= 1) { if (tid < o) red[tid] += red[tid + o]; __syncthreads(); }
    if (tid == 0) atomicAdd(&g_tots[slot_out * BHn + bh], red[0]);
}

// ---------------- final col pass fused with W build ----------------
__global__ void sink_col_finw(int slot_in) {
    int bh = blockIdx.y;
    int tid = threadIdx.x;
    int jb = blockIdx.x * 256;
    int j = jb + tid;
    int b = bh / Hn, h = bh % Hn;
    float s = 0.f;
    #pragma unroll
    for (int ic = 0; ic < 8; ic++)
        s += g_cpart[(size_t)(ic * BHn + bh) * Tn + j];
    float ev = __expf(-LOGT - __logf(s + g_tots[slot_in * BHn + bh]));
    __shared__ float sev[256];
    sev[tid] = ev;
    __syncthreads();
    int d = tid & 63, rr = tid >> 6;
    const float* Vbase = g_qkv + (size_t)b * Tn * N3 + 2 * Cn + h * HDn + d;
    float part = 0.f;
    for (int r = rr; r < 256; r += 4) {
        int jj = jb + r;
        float w = sev[r] * Vbase[(size_t)jj * N3];
        part += w;
        float ws = fminf(fmaxf(w * WSCALE, -32768.f), 32768.f);
        __half hi = __float2half(ws);
        g_wh[((size_t)bh * Tn + jj) * HDn + d] = hi;
        g_wl[((size_t)bh * Tn + jj) * HDn + d] = __float2half(ws - __half2float(hi));
    }
    __shared__ float red[256];
    red[tid] = part;
    __syncthreads();
    if (tid < 128) red[tid] += red[tid + 128];
    __syncthreads();
    if (tid < 64) atomicAdd(&g_wtot[bh * HDn + tid], red[tid] + red[tid + 64]);
}

// ---------------- pi@V via fp16 TC (static smem, 2 CTA/SM); y as bf16 hi/lo ----------------
__global__ void __launch_bounds__(256) pi_v_tc() {
    int bh = blockIdx.y;
    int b = bh / Hn, h = bh % Hn;
    int it = gridDim.x - 1 - blockIdx.x;
    int i0 = it * 128;
    __shared__ __half sA[128][72];
    __shared__ __half sWh[64][72], sWl[64][72];
    int tid = threadIdx.x, wid = tid >> 5, lane = tid & 31;
    int wm = wid & 3, wn = wid >> 2;
    float acc[2][4][4] = {};
    unsigned aA = (unsigned)__cvta_generic_to_shared(&sA[0][0]);
    unsigned aWh = (unsigned)__cvta_generic_to_shared(&sWh[0][0]);
    unsigned aWl = (unsigned)__cvta_generic_to_shared(&sWl[0][0]);

    for (int jc = 0; jc < i0 + 128; jc += 64) {
        if (jc) __syncthreads();
        #pragma unroll
        for (int z = 0; z < 4; z++) {
            int idx = z * 256 + tid;
            int r = idx >> 3, c8 = (idx & 7) * 8;
            *(uint4*)&sA[r][c8] = *(const uint4*)(g_c + ((size_t)bh * Tn + i0 + r) * Tn + jc + c8);
        }
        #pragma unroll
        for (int z = 0; z < 2; z++) {
            int idx = z * 256 + tid;
            int r = idx >> 3, c8 = (idx & 7) * 8;
            *(uint4*)&sWh[r][c8] = *(const uint4*)(g_wh + ((size_t)bh * Tn + jc + r) * HDn + c8);
            *(uint4*)&sWl[r][c8] = *(const uint4*)(g_wl + ((size_t)bh * Tn + jc + r) * HDn + c8);
        }
        __syncthreads();
        #pragma unroll
        for (int kh = 0; kh < 64; kh += 16) {
            unsigned a_[2][4];
            #pragma unroll
            for (int mt = 0; mt < 2; mt++) {
                unsigned off = ((unsigned)((wm * 32 + mt * 16 + (lane & 15)) * 72 + kh + 8 * (lane >> 4))) * 2;
                ldmx4(aA + off, a_[mt][0], a_[mt][1], a_[mt][2], a_[mt][3]);
            }
            #pragma unroll
            for (int nq = 0; nq < 2; nq++) {
                int n0 = wn * 32 + nq * 16;
                unsigned boff = ((unsigned)((kh + (lane & 7) + 8 * ((lane >> 3) & 1)) * 72 + n0 + 8 * (lane >> 4))) * 2;
                unsigned bh0, bh1, bh2, bh3, bl0, bl1, bl2, bl3;
                ldmx4t(aWh + boff, bh0, bh1, bh2, bh3);
                ldmx4t(aWl + boff, bl0, bl1, bl2, bl3);
                #pragma unroll
                for (int mt = 0; mt < 2; mt++) {
                    mma_f16(acc[mt][2 * nq],     a_[mt][0], a_[mt][1], a_[mt][2], a_[mt][3], bh0, bh1);
                    mma_f16(acc[mt][2 * nq],     a_[mt][0], a_[mt][1], a_[mt][2], a_[mt][3], bl0, bl1);
                    mma_f16(acc[mt][2 * nq + 1], a_[mt][0], a_[mt][1], a_[mt][2], a_[mt][3], bh2, bh3);
                    mma_f16(acc[mt][2 * nq + 1], a_[mt][0], a_[mt][1], a_[mt][2], a_[mt][3], bl2, bl3);
                }
            }
        }
    }
    #pragma unroll
    for (int mt = 0; mt < 2; mt++) {
        #pragma unroll
        for (int f = 0; f < 4; f++) {
            float* cc = acc[mt][f];
            int r = i0 + wm * 32 + mt * 16 + (lane >> 2);
            int d = wn * 32 + f * 8 + 2 * (lane & 3);
            float wt0 = g_wtot[bh * HDn + d], wt1 = g_wtot[bh * HDn + d + 1];
            float eu0 = g_eu[bh * Tn + r] * 2048.f;
            float eu1 = g_eu[bh * Tn + r + 8] * 2048.f;
            float y0 = (cc[0] * WINV + wt0) * eu0;
            float y1 = (cc[1] * WINV + wt1) * eu0;
            float y2 = (cc[2] * WINV + wt0) * eu1;
            float y3 = (cc[3] * WINV + wt1) * eu1;
            size_t base = ((size_t)(b * Tn) + r) * Cn + h * HDn + d;
            __nv_bfloat16 h0 = __float2bfloat16(y0), h1 = __float2bfloat16(y1);
            __nv_bfloat16 h2 = __float2bfloat16(y2), h3 = __float2bfloat16(y3);
            g_ah[base] = h0;
            g_ah[base + 1] = h1;
            g_ah[base + (size_t)8 * Cn] = h2;
            g_ah[base + (size_t)8 * Cn + 1] = h3;
            g_al[base] = __float2bfloat16(y0 - __bfloat162float(h0));
            g_al[base + 1] = __float2bfloat16(y1 - __bfloat162float(h1));
            g_al[base + (size_t)8 * Cn] = __float2bfloat16(y2 - __bfloat162float(h2));
            g_al[base + (size_t)8 * Cn + 1] = __float2bfloat16(y3 - __bfloat162float(h3));
        }
    }
}

// ---------------- launch ----------------
extern "C" void kernel_launch(void* const* d_in, const int* in_sizes, int n_in,
                              void* d_out, int out_size) {
    const float* x      = (const float*)d_in[0];
    const float* t      = (const float*)d_in[1];
    const float* ln1_w  = (const float*)d_in[2];
    const float* ln1_b  = (const float*)d_in[3];
    const float* attn_w = (const float*)d_in[4];
    const float* attn_b = (const float*)d_in[5];
    const float* proj_w = (const float*)d_in[6];
    const float* proj_b = (const float*)d_in[7];
    const float* ln2_w  = (const float*)d_in[8];
    const float* ln2_b  = (const float*)d_in[9];
    const float* fc_w   = (const float*)d_in[10];
    const float* fc_b   = (const float*)d_in[11];
    const float* fc2_w  = (const float*)d_in[12];
    const float* fc2_b  = (const float*)d_in[13];
    float* out = (float*)d_out;

    float *p_qkv, *p_h;
    __nv_bfloat16 *p_ah, *p_al, *p_a2h, *p_a2l, *p_bh, *p_bl;
    cudaGetSymbolAddress((void**)&p_qkv, g_qkv);
    cudaGetSymbolAddress((void**)&p_h,   g_h);
    cudaGetSymbolAddress((void**)&p_ah,  g_ah);
    cudaGetSymbolAddress((void**)&p_al,  g_al);
    cudaGetSymbolAddress((void**)&p_a2h, g_a2h);
    cudaGetSymbolAddress((void**)&p_a2l, g_a2l);
    cudaGetSymbolAddress((void**)&p_bh,  g_bh);
    cudaGetSymbolAddress((void**)&p_bl,  g_bl);

    static int smem_set = 0;
    const int GSM64 = 55296;
    if (!smem_set) {
        cudaFuncSetAttribute(gemm64u, cudaFuncAttributeMaxDynamicSharedMemorySize, GSM64);
        smem_set = 1;
    }

    // ---- setup (zeroing fused into conv_w_all) ----
    conv_w_all<<<(WTOTAL / 4 + 255) / 256, 256>>>(attn_w, proj_w, fc_w, fc2_w);

    // ---- attention sub-block ----
    ln_bf<<<ROWS, 256>>>(x, t, ln1_w, ln1_b, p_ah, p_al);
    gemm64u<<<dim3(N3 / 128, ROWS / 64), 256, GSM64>>>(p_ah, p_al, p_bh + WOFF_QKV, p_bl + WOFF_QKV, attn_b,
                                                       p_qkv, nullptr, nullptr, ROWS, N3, KA_LN, 0, 2);
    score_tc<<<dim3(136, BHn), 256>>>();
    em1_row<<<dim3(Tn, BHn), 256>>>();

    // sinkhorn remaining 5 passes
    sink_col_part<<<dim3(4, 8, BHn), 256>>>();
    sink_col_fin<<<dim3(8, BHn), 256>>>(0, 1);
    sink_row_f<<<dim3(Tn / 8, BHn), 256>>>(1, 2);
    sink_col_part<<<dim3(4, 8, BHn), 256>>>();
    sink_col_fin<<<dim3(8, BHn), 256>>>(2, 3);
    sink_row_f<<<dim3(Tn / 8, BHn), 256>>>(3, 4);
    sink_col_part<<<dim3(4, 8, BHn), 256>>>();
    sink_col_finw<<<dim3(8, BHn), 256>>>(4);

    pi_v_tc<<<dim3(Tn / 128, BHn), 256>>>();

    // proj
    gemm64u<<<dim3(Cn / 128, ROWS / 64), 256, GSM64>>>(p_ah, p_al, p_bh + WOFF_PRJ, p_bl + WOFF_PRJ, proj_b,
                                                       p_h, nullptr, nullptr, ROWS, Cn, Cn, 0, 0);

    // ---- MLP sub-block ----
    ln_bf<<<ROWS, 256>>>(p_h, t, ln2_w, ln2_b, p_ah, p_al);
    gemm64u<<<dim3(N4 / 128, ROWS / 64), 256, GSM64>>>(p_ah, p_al, p_bh + WOFF_FC, p_bl + WOFF_FC, fc_b,
                                                       nullptr, p_a2h, p_a2l, ROWS, N4, KA_LN, 1, 1);
    gemm64u<<<dim3(Cn / 128, ROWS / 64), 256, GSM64>>>(p_a2h, p_a2l, p_bh + WOFF_FC2, p_bl + WOFF_FC2, fc2_b,
                                                       out, nullptr, nullptr, ROWS, Cn, N4, 0, 0);
}

// round 16
// speedup vs baseline: 1.1553x; 1.0458x over previous
#include <cuda_runtime.h>
#include <cuda_fp16.h>
#include <cuda_bf16.h>
#include <math.h>

#define Tn 2048
#define Cn 384
#define Hn 6
#define HDn 64
#define Bn 2
#define BHn 12
#define ROWS 4096
#define C1 385
#define KA_LN 416
#define N3 1152
#define N4 1536
#define LOGT 7.62461899f
#define WSCALE 512.f
#define WINV   (1.f / 512.f)

#define WOFF_QKV 0
#define WSZ_QKV  (KA_LN * N3)
#define WOFF_PRJ (WOFF_QKV + WSZ_QKV)
#define WSZ_PRJ  (Cn * Cn)
#define WOFF_FC  (WOFF_PRJ + WSZ_PRJ)
#define WSZ_FC   (KA_LN * N4)
#define WOFF_FC2 (WOFF_FC + WSZ_FC)
#define WSZ_FC2  (N4 * Cn)
#define WTOTAL   (WOFF_FC2 + WSZ_FC2)

// ---------------- scratch ----------------
__device__ __align__(16) float g_qkv[ROWS * N3];
__device__ __align__(16) __half g_e[(size_t)BHn * Tn * Tn];
__device__ __align__(16) __half g_c[(size_t)BHn * Tn * Tn];
__device__ __align__(16) __nv_bfloat16 g_qh[ROWS * Cn];
__device__ __align__(16) __nv_bfloat16 g_ql[ROWS * Cn];
__device__ __align__(16) __nv_bfloat16 g_kh[ROWS * Cn];
__device__ __align__(16) __nv_bfloat16 g_kl[ROWS * Cn];
__device__ __align__(16) __half g_wh[BHn * Tn * HDn];
__device__ __align__(16) __half g_wl[BHn * Tn * HDn];
__device__ float g_rowsum[BHn * Tn];
__device__ float g_eu[BHn * Tn];
__device__ float g_ev[BHn * Tn];
__device__ float g_tots[8 * BHn];
__device__ float g_wtot[BHn * HDn];
__device__ __align__(16) float g_cpart[8 * BHn * Tn];
__device__ __align__(16) float g_h[ROWS * Cn];
__device__ __align__(16) __nv_bfloat16 g_ah[ROWS * N4];
__device__ __align__(16) __nv_bfloat16 g_al[ROWS * N4];
__device__ __align__(16) __nv_bfloat16 g_a2h[ROWS * N4];
__device__ __align__(16) __nv_bfloat16 g_a2l[ROWS * N4];
__device__ __align__(16) __nv_bfloat16 g_bh[WTOTAL];
__device__ __align__(16) __nv_bfloat16 g_bl[WTOTAL];

// ---------------- helpers ----------------
__device__ __forceinline__ void ldmx4(unsigned addr, unsigned& r0, unsigned& r1, unsigned& r2, unsigned& r3) {
    asm volatile("ldmatrix.sync.aligned.m8n8.x4.shared.b16 {%0,%1,%2,%3},[%4];"
                 : "=r"(r0), "=r"(r1), "=r"(r2), "=r"(r3) : "r"(addr));
}
__device__ __forceinline__ void ldmx4t(unsigned addr, unsigned& r0, unsigned& r1, unsigned& r2, unsigned& r3) {
    asm volatile("ldmatrix.sync.aligned.m8n8.x4.trans.shared.b16 {%0,%1,%2,%3},[%4];"
                 : "=r"(r0), "=r"(r1), "=r"(r2), "=r"(r3) : "r"(addr));
}
__device__ __forceinline__ void mma_bf16(float* c, unsigned a0, unsigned a1, unsigned a2, unsigned a3,
                                         unsigned b0, unsigned b1) {
    asm volatile("mma.sync.aligned.m16n8k16.row.col.f32.bf16.bf16.f32 "
                 "{%0,%1,%2,%3},{%4,%5,%6,%7},{%8,%9},{%0,%1,%2,%3};"
                 : "+f"(c[0]), "+f"(c[1]), "+f"(c[2]), "+f"(c[3])
                 : "r"(a0), "r"(a1), "r"(a2), "r"(a3), "r"(b0), "r"(b1));
}
__device__ __forceinline__ void mma_f16(float* c, unsigned a0, unsigned a1, unsigned a2, unsigned a3,
                                        unsigned b0, unsigned b1) {
    asm volatile("mma.sync.aligned.m16n8k16.row.col.f32.f16.f16.f32 "
                 "{%0,%1,%2,%3},{%4,%5,%6,%7},{%8,%9},{%0,%1,%2,%3};"
                 : "+f"(c[0]), "+f"(c[1]), "+f"(c[2]), "+f"(c[3])
                 : "r"(a0), "r"(a1), "r"(a2), "r"(a3), "r"(b0), "r"(b1));
}
__device__ __forceinline__ void cpa16(unsigned dst, const void* src) {
    asm volatile("cp.async.cg.shared.global [%0],[%1],16;" :: "r"(dst), "l"(src));
}
#define CPA_COMMIT asm volatile("cp.async.commit_group;")
#define CPA_WAIT1  asm volatile("cp.async.wait_group 1;")

__device__ __forceinline__ float em1p(float x) {
    float t = fmaf(x, 0.125f, 1.f);
    t = fmaf(x * 0.14285714f, t, 1.f);
    t = fmaf(x * 0.16666667f, t, 1.f);
    t = fmaf(x * 0.2f,        t, 1.f);
    t = fmaf(x * 0.25f,       t, 1.f);
    t = fmaf(x * 0.33333333f, t, 1.f);
    t = fmaf(x * 0.5f,        t, 1.f);
    return x * t;
}

// ---------------- weights -> bf16 hi/lo (+ fused zeroing) ----------------
__global__ void conv_w_all(const float* __restrict__ w0, const float* __restrict__ w1,
                           const float* __restrict__ w2, const float* __restrict__ w3) {
    int idx = blockIdx.x * 256 + threadIdx.x;
    if (idx < BHn * Tn) g_rowsum[idx] = 0.f;
    if (idx < BHn * HDn) g_wtot[idx] = 0.f;
    if (idx < 8 * BHn) g_tots[idx] = 0.f;
    int e = idx * 4;
    if (e >= WTOTAL) return;
    const float* src;
    int K, N, local;
    if (e < WOFF_PRJ)       { src = w0; K = C1;  N = N3; local = e - WOFF_QKV; }
    else if (e < WOFF_FC)   { src = w1; K = Cn;  N = Cn; local = e - WOFF_PRJ; }
    else if (e < WOFF_FC2)  { src = w2; K = C1;  N = N4; local = e - WOFF_FC;  }
    else                    { src = w3; K = N4;  N = Cn; local = e - WOFF_FC2; }
    int row = local / N, col = local % N;
    float4 v = (row < K) ? *(const float4*)(src + (size_t)row * N + col)
                         : make_float4(0.f, 0.f, 0.f, 0.f);
    __nv_bfloat16 h0 = __float2bfloat16(v.x), h1 = __float2bfloat16(v.y);
    __nv_bfloat16 h2 = __float2bfloat16(v.z), h3 = __float2bfloat16(v.w);
    __nv_bfloat16 hbuf[4] = {h0, h1, h2, h3};
    __nv_bfloat16 lbuf[4] = {
        __float2bfloat16(v.x - __bfloat162float(h0)), __float2bfloat16(v.y - __bfloat162float(h1)),
        __float2bfloat16(v.z - __bfloat162float(h2)), __float2bfloat16(v.w - __bfloat162float(h3))};
    *(uint2*)(g_bh + e) = *(uint2*)hbuf;
    *(uint2*)(g_bl + e) = *(uint2*)lbuf;
}

// ---------------- LayerNorm -> bf16 hi/lo ----------------
__global__ void ln_bf(const float* __restrict__ x, const float* __restrict__ t,
                      const float* __restrict__ w, const float* __restrict__ bb,
                      __nv_bfloat16* __restrict__ oh, __nv_bfloat16* __restrict__ ol) {
    int row = blockIdx.x;
    int tid = threadIdx.x;
    __shared__ float sx[C1];
    __shared__ float red[256];
    float s1 = 0.f;
    for (int c = tid; c < C1; c += 256) {
        float v = (c < Cn) ? x[(size_t)row * Cn + c] : t[0];
        sx[c] = v;
        s1 += v;
    }
    red[tid] = s1; __syncthreads();
    for (int o = 128; o > 0; o >>= 1) { if (tid < o) red[tid] += red[tid + o]; __syncthreads(); }
    float mean = red[0] * (1.f / C1);
    __syncthreads();
    float s2 = 0.f;
    for (int c = tid; c < C1; c += 256) { float d = sx[c] - mean; s2 += d * d; }
    red[tid] = s2; __syncthreads();
    for (int o = 128; o > 0; o >>= 1) { if (tid < o) red[tid] += red[tid + o]; __syncthreads(); }
    float rs = rsqrtf(red[0] * (1.f / C1) + 1e-5f);
    for (int c = tid; c < C1; c += 256) {
        float v = (sx[c] - mean) * rs * w[c] + bb[c];
        __nv_bfloat16 hi = __float2bfloat16(v);
        oh[(size_t)row * KA_LN + c] = hi;
        ol[(size_t)row * KA_LN + c] = __float2bfloat16(v - __bfloat162float(hi));
    }
    if (tid < KA_LN - C1) {
        oh[(size_t)row * KA_LN + C1 + tid] = __float2bfloat16(0.f);
        ol[(size_t)row * KA_LN + C1 + tid] = __float2bfloat16(0.f);
    }
}

// ---------------- unified pipelined bf16 GEMM, 64x64 tile, 128 threads ----------------
// obf=0: fp32 out. obf=1: gelu(if act) + bf16 hi/lo out. obf=2: fp32 out + q/k bf16 split.
__global__ void __launch_bounds__(128) gemm64s(const __nv_bfloat16* __restrict__ Ah,
                                               const __nv_bfloat16* __restrict__ Al,
                                               const __nv_bfloat16* __restrict__ Bh,
                                               const __nv_bfloat16* __restrict__ Bl,
                                               const float* __restrict__ bias,
                                               float* __restrict__ outF,
                                               __nv_bfloat16* __restrict__ oAh,
                                               __nv_bfloat16* __restrict__ oAl,
                                               int M, int N, int Ka, int act, int obf) {
    extern __shared__ __nv_bfloat16 dyn[];
    __nv_bfloat16* sA = dyn;               // 2 st x 2 hl x 2560 (64x40)
    __nv_bfloat16* sB = dyn + 4 * 2560;    // 2 st x 2 hl x 2304 (32x72)
    int tid = threadIdx.x;
    int wid = tid >> 5, lane = tid & 31;
    int wm = wid & 1, wn = wid >> 1;       // 2 m-warps x 2 n-warps
    int bm = blockIdx.y * 64, bn = blockIdx.x * 64;
    float acc[2][4][4] = {};
    unsigned sAu = (unsigned)__cvta_generic_to_shared(sA);
    unsigned sBu = (unsigned)__cvta_generic_to_shared(sB);

    int nk = Ka >> 5;
    auto load_stage = [&](int kt, int st) {
        unsigned aH = sAu + (st * 2 + 0) * 2560 * 2;
        unsigned aL = sAu + (st * 2 + 1) * 2560 * 2;
        unsigned bH = sBu + (st * 2 + 0) * 2304 * 2;
        unsigned bL = sBu + (st * 2 + 1) * 2304 * 2;
        int k0 = kt * 32;
        #pragma unroll
        for (int z = 0; z < 2; z++) {
            int idx = z * 128 + tid;
            int row = idx >> 2, cq = (idx & 3) * 8;
            cpa16(aH + (row * 40 + cq) * 2, Ah + (size_t)(bm + row) * Ka + k0 + cq);
            cpa16(aL + (row * 40 + cq) * 2, Al + (size_t)(bm + row) * Ka + k0 + cq);
        }
        #pragma unroll
        for (int z = 0; z < 2; z++) {
            int idx = z * 128 + tid;
            int row = idx >> 3, cq = (idx & 7) * 8;
            cpa16(bH + (row * 72 + cq) * 2, Bh + (size_t)(k0 + row) * N + bn + cq);
            cpa16(bL + (row * 72 + cq) * 2, Bl + (size_t)(k0 + row) * N + bn + cq);
        }
    };

    load_stage(0, 0);
    CPA_COMMIT;
    for (int kt = 0; kt < nk; kt++) {
        int cur = kt & 1;
        if (kt + 1 < nk) load_stage(kt + 1, cur ^ 1);
        CPA_COMMIT;
        CPA_WAIT1;
        __syncthreads();
        unsigned aH = sAu + (cur * 2 + 0) * 2560 * 2;
        unsigned aL = sAu + (cur * 2 + 1) * 2560 * 2;
        unsigned bH = sBu + (cur * 2 + 0) * 2304 * 2;
        unsigned bL = sBu + (cur * 2 + 1) * 2304 * 2;
        #pragma unroll
        for (int kh = 0; kh < 32; kh += 16) {
            unsigned ah[2][4], al[2][4];
            #pragma unroll
            for (int mt = 0; mt < 2; mt++) {
                unsigned off = ((unsigned)((wm * 32 + mt * 16 + (lane & 15)) * 40 + kh + (lane >> 4) * 8)) * 2;
                ldmx4(aH + off, ah[mt][0], ah[mt][1], ah[mt][2], ah[mt][3]);
                ldmx4(aL + off, al[mt][0], al[mt][1], al[mt][2], al[mt][3]);
            }
            #pragma unroll
            for (int nq = 0; nq < 2; nq++) {
                int n0 = wn * 32 + nq * 16;
                unsigned boff = ((unsigned)((kh + (lane & 7) + 8 * ((lane >> 3) & 1)) * 72 + n0 + 8 * (lane >> 4))) * 2;
                unsigned bh0, bh1, bh2, bh3, bl0, bl1, bl2, bl3;
                ldmx4t(bH + boff, bh0, bh1, bh2, bh3);
                ldmx4t(bL + boff, bl0, bl1, bl2, bl3);
                #pragma unroll
                for (int mt = 0; mt < 2; mt++) {
                    mma_bf16(acc[mt][2 * nq],     ah[mt][0], ah[mt][1], ah[mt][2], ah[mt][3], bh0, bh1);
                    mma_bf16(acc[mt][2 * nq],     ah[mt][0], ah[mt][1], ah[mt][2], ah[mt][3], bl0, bl1);
                    mma_bf16(acc[mt][2 * nq],     al[mt][0], al[mt][1], al[mt][2], al[mt][3], bh0, bh1);
                    mma_bf16(acc[mt][2 * nq + 1], ah[mt][0], ah[mt][1], ah[mt][2], ah[mt][3], bh2, bh3);
                    mma_bf16(acc[mt][2 * nq + 1], ah[mt][0], ah[mt][1], ah[mt][2], ah[mt][3], bl2, bl3);
                    mma_bf16(acc[mt][2 * nq + 1], al[mt][0], al[mt][1], al[mt][2], al[mt][3], bh2, bh3);
                }
            }
        }
        __syncthreads();
    }
    #pragma unroll
    for (int mt = 0; mt < 2; mt++) {
        #pragma unroll
        for (int nt = 0; nt < 4; nt++) {
            float* cc = acc[mt][nt];
            int r = bm + wm * 32 + mt * 16 + (lane >> 2);
            int cn = bn + wn * 32 + (nt >> 1) * 16 + (nt & 1) * 8 + (lane & 3) * 2;
            float b0 = bias[cn], b1 = bias[cn + 1];
            float v0 = cc[0] + b0, v1 = cc[1] + b1;
            float v2 = cc[2] + b0, v3 = cc[3] + b1;
            if (act == 1) {
                v0 = 0.5f * v0 * (1.f + erff(v0 * 0.70710678f));
                v1 = 0.5f * v1 * (1.f + erff(v1 * 0.70710678f));
                v2 = 0.5f * v2 * (1.f + erff(v2 * 0.70710678f));
                v3 = 0.5f * v3 * (1.f + erff(v3 * 0.70710678f));
            }
            if (obf == 1) {
                __nv_bfloat16 h0 = __float2bfloat16(v0), h1 = __float2bfloat16(v1);
                __nv_bfloat16 h2 = __float2bfloat16(v2), h3 = __float2bfloat16(v3);
                oAh[(size_t)r * N + cn] = h0;
                oAh[(size_t)r * N + cn + 1] = h1;
                oAh[(size_t)(r + 8) * N + cn] = h2;
                oAh[(size_t)(r + 8) * N + cn + 1] = h3;
                oAl[(size_t)r * N + cn] = __float2bfloat16(v0 - __bfloat162float(h0));
                oAl[(size_t)r * N + cn + 1] = __float2bfloat16(v1 - __bfloat162float(h1));
                oAl[(size_t)(r + 8) * N + cn] = __float2bfloat16(v2 - __bfloat162float(h2));
                oAl[(size_t)(r + 8) * N + cn + 1] = __float2bfloat16(v3 - __bfloat162float(h3));
            } else {
                outF[(size_t)r * N + cn] = v0;
                outF[(size_t)r * N + cn + 1] = v1;
                outF[(size_t)(r + 8) * N + cn] = v2;
                outF[(size_t)(r + 8) * N + cn + 1] = v3;
                if (obf == 2 && cn < 2 * Cn) {
                    int isK = cn >= Cn;
                    int c2 = cn - isK * Cn;
                    __nv_bfloat16* H = isK ? g_kh : g_qh;
                    __nv_bfloat16* L = isK ? g_kl : g_ql;
                    __nv_bfloat16 h0 = __float2bfloat16(v0), h1 = __float2bfloat16(v1);
                    __nv_bfloat16 h2 = __float2bfloat16(v2), h3 = __float2bfloat16(v3);
                    H[(size_t)r * Cn + c2] = h0;
                    H[(size_t)r * Cn + c2 + 1] = h1;
                    H[(size_t)(r + 8) * Cn + c2] = h2;
                    H[(size_t)(r + 8) * Cn + c2 + 1] = h3;
                    L[(size_t)r * Cn + c2] = __float2bfloat16(v0 - __bfloat162float(h0));
                    L[(size_t)r * Cn + c2 + 1] = __float2bfloat16(v1 - __bfloat162float(h1));
                    L[(size_t)(r + 8) * Cn + c2] = __float2bfloat16(v2 - __bfloat162float(h2));
                    L[(size_t)(r + 8) * Cn + c2 + 1] = __float2bfloat16(v3 - __bfloat162float(h3));
                }
            }
        }
    }
}

// ---------------- TC scores + fused exp + inline row sums (triangular grid) ----------------
__global__ void __launch_bounds__(256, 2) score_tc() {
    int li = blockIdx.x, bh = blockIdx.y;
    int it = (int)((sqrtf(8.f * li + 1.f) - 1.f) * 0.5f);
    while ((it + 1) * (it + 2) / 2 <= li) it++;
    while (it * (it + 1) / 2 > li) it--;
    int jt = li - it * (it + 1) / 2;
    int b = bh / Hn, h = bh % Hn;
    __shared__ __nv_bfloat16 sQh[128][40], sQl[128][40], sKh[128][40], sKl[128][40];
    int tid = threadIdx.x, wid = tid >> 5, lane = tid & 31;
    int wm = wid & 3, wn = wid >> 2;
    float acc[2][8][4] = {};
    unsigned aQh = (unsigned)__cvta_generic_to_shared(&sQh[0][0]);
    unsigned aQl = (unsigned)__cvta_generic_to_shared(&sQl[0][0]);
    unsigned aKh = (unsigned)__cvta_generic_to_shared(&sKh[0][0]);
    unsigned aKl = (unsigned)__cvta_generic_to_shared(&sKl[0][0]);
    size_t qbase = ((size_t)(b * Tn + it * 128)) * Cn + h * HDn;
    size_t kbase = ((size_t)(b * Tn + jt * 128)) * Cn + h * HDn;

    for (int ks = 0; ks < 2; ks++) {
        if (ks) __syncthreads();
        #pragma unroll
        for (int z = 0; z < 2; z++) {
            int idx = z * 256 + tid;
            int r = idx >> 2, c8 = (idx & 3) * 8;
            *(uint4*)&sQh[r][c8] = *(const uint4*)(g_qh + qbase + (size_t)r * Cn + ks * 32 + c8);
            *(uint4*)&sQl[r][c8] = *(const uint4*)(g_ql + qbase + (size_t)r * Cn + ks * 32 + c8);
            *(uint4*)&sKh[r][c8] = *(const uint4*)(g_kh + kbase + (size_t)r * Cn + ks * 32 + c8);
            *(uint4*)&sKl[r][c8] = *(const uint4*)(g_kl + kbase + (size_t)r * Cn + ks * 32 + c8);
        }
        __syncthreads();
        #pragma unroll
        for (int kh = 0; kh < 32; kh += 16) {
            unsigned qh_[2][4], ql_[2][4];
            #pragma unroll
            for (int mt = 0; mt < 2; mt++) {
                unsigned off = ((unsigned)((wm * 32 + mt * 16 + (lane & 15)) * 40 + kh + 8 * (lane >> 4))) * 2;
                ldmx4(aQh + off, qh_[mt][0], qh_[mt][1], qh_[mt][2], qh_[mt][3]);
                ldmx4(aQl + off, ql_[mt][0], ql_[mt][1], ql_[mt][2], ql_[mt][3]);
            }
            #pragma unroll
            for (int nq = 0; nq < 4; nq++) {
                int n0 = wn * 64 + nq * 16;
                unsigned boff = ((unsigned)((n0 + (lane & 15)) * 40 + kh + 8 * (lane >> 4))) * 2;
                unsigned kh0, kh1, kh2, kh3, kl0, kl1, kl2, kl3;
                ldmx4(aKh + boff, kh0, kh1, kh2, kh3);
                ldmx4(aKl + boff, kl0, kl1, kl2, kl3);
                #pragma unroll
                for (int mt = 0; mt < 2; mt++) {
                    mma_bf16(acc[mt][2 * nq],     qh_[mt][0], qh_[mt][1], qh_[mt][2], qh_[mt][3], kh0, kh2);
                    mma_bf16(acc[mt][2 * nq],     qh_[mt][0], qh_[mt][1], qh_[mt][2], qh_[mt][3], kl0, kl2);
                    mma_bf16(acc[mt][2 * nq],     ql_[mt][0], ql_[mt][1], ql_[mt][2], ql_[mt][3], kh0, kh2);
                    mma_bf16(acc[mt][2 * nq + 1], qh_[mt][0], qh_[mt][1], qh_[mt][2], qh_[mt][3], kh1, kh3);
                    mma_bf16(acc[mt][2 * nq + 1], qh_[mt][0], qh_[mt][1], qh_[mt][2], qh_[mt][3], kl1, kl3);
                    mma_bf16(acc[mt][2 * nq + 1], ql_[mt][0], ql_[mt][1], ql_[mt][2], ql_[mt][3], kh1, kh3);
                }
            }
        }
    }
    __half* erow = g_e + (size_t)bh * Tn * Tn;
    float rsum[2][2] = {};
    int diag = (it == jt);
    #pragma unroll
    for (int mt = 0; mt < 2; mt++) {
        #pragma unroll
        for (int f = 0; f < 8; f++) {
            float* cc = acc[mt][f];
            int gi = it * 128 + wm * 32 + mt * 16 + (lane >> 2);
            int gj = jt * 128 + wn * 64 + (f >> 1) * 16 + (f & 1) * 8 + 2 * (lane & 3);
            float e0 = __expf(fminf(cc[0] * 0.125f, 11.f));
            float e1 = __expf(fminf(cc[1] * 0.125f, 11.f));
            float e2 = __expf(fminf(cc[2] * 0.125f, 11.f));
            float e3 = __expf(fminf(cc[3] * 0.125f, 11.f));
            if (diag) {
                if (gj > gi) e0 = 0.f;
                if (gj + 1 > gi) e1 = 0.f;
                if (gj > gi + 8) e2 = 0.f;
                if (gj + 1 > gi + 8) e3 = 0.f;
            }
            rsum[mt][0] += e0 + e1;
            rsum[mt][1] += e2 + e3;
            *(__half2*)(erow + (size_t)gi * Tn + gj) = __floats2half2_rn(e0, e1);
            *(__half2*)(erow + (size_t)(gi + 8) * Tn + gj) = __floats2half2_rn(e2, e3);
        }
    }
    #pragma unroll
    for (int mt = 0; mt < 2; mt++) {
        #pragma unroll
        for (int hh = 0; hh < 2; hh++) {
            float v = rsum[mt][hh];
            v += __shfl_xor_sync(0xffffffffu, v, 1);
            v += __shfl_xor_sync(0xffffffffu, v, 2);
            if ((lane & 3) == 0) {
                int gi = it * 128 + wm * 32 + mt * 16 + (lane >> 2) + hh * 8;
                atomicAdd(&g_rowsum[bh * Tn + gi], v);
            }
        }
    }
}

// ---------------- per row: Em1 = expm1(e/rowsum); eu; eutot -> slot0 ----------------
__global__ void em1_row() {
    int i = blockIdx.x, bh = blockIdx.y;
    int tid = threadIdx.x;
    int lane = tid & 31, wid = tid >> 5;
    float inv = 1.f / g_rowsum[bh * Tn + i];
    const uint4* src = (const uint4*)(g_e + ((size_t)bh * Tn + i) * Tn);
    uint4* dst = (uint4*)(g_c + ((size_t)bh * Tn + i) * Tn);
    int nv = ((i >> 7) + 1) << 4;
    float se = 0.f;
    if (tid < nv) {
        uint4 pk = src[tid];
        const __half2* hp = (const __half2*)&pk;
        uint4 outp;
        __half2* op = (__half2*)&outp;
        #pragma unroll
        for (int z = 0; z < 4; z++) {
            float2 f = __half22float2(hp[z]);
            float a = em1p(f.x * inv);
            float bb = em1p(f.y * inv);
            se += a + bb;
            op[z] = __floats2half2_rn(a, bb);
        }
        dst[tid] = outp;
    }
    se += __shfl_xor_sync(0xffffffffu, se, 16);
    se += __shfl_xor_sync(0xffffffffu, se, 8);
    se += __shfl_xor_sync(0xffffffffu, se, 4);
    se += __shfl_xor_sync(0xffffffffu, se, 2);
    se += __shfl_xor_sync(0xffffffffu, se, 1);
    __shared__ float red[8];
    if (lane == 0) red[wid] = se;
    __syncthreads();
    if (tid == 0) {
        float s = red[0] + red[1] + red[2] + red[3] + red[4] + red[5] + red[6] + red[7];
        float eu = __expf(-LOGT - __logf(s + (float)Tn));
        g_eu[bh * Tn + i] = eu;
        atomicAdd(&g_tots[bh], eu);
    }
}

// ---------------- Sinkhorn row pass: warp-per-row ----------------
__global__ void sink_row_f(int slot_in, int slot_out) {
    int r0 = blockIdx.x * 8, bh = blockIdx.y;
    int tid = threadIdx.x, lane = tid & 31, w = tid >> 5;
    __shared__ float sev[Tn];
    __shared__ float sred[8];
    int jmax = r0 + 8;
    for (int j = tid; j < jmax; j += 256) sev[j] = g_ev[bh * Tn + j];
    float evtot = g_tots[slot_in * BHn + bh];
    __syncthreads();
    int i = r0 + w;
    const uint4* cv = (const uint4*)(g_c + ((size_t)bh * Tn + i) * Tn);
    int nv = (i + 8) >> 3;
    float s = 0.f;
    for (int vi = lane; vi < nv; vi += 32) {
        uint4 pk = cv[vi];
        const __half2* hp = (const __half2*)&pk;
        int jb = vi * 8;
        #pragma unroll
        for (int z = 0; z < 4; z++) {
            float2 f = __half22float2(hp[z]);
            s += f.x * sev[jb + 2 * z] + f.y * sev[jb + 2 * z + 1];
        }
    }
    s += __shfl_xor_sync(0xffffffffu, s, 16);
    s += __shfl_xor_sync(0xffffffffu, s, 8);
    s += __shfl_xor_sync(0xffffffffu, s, 4);
    s += __shfl_xor_sync(0xffffffffu, s, 2);
    s += __shfl_xor_sync(0xffffffffu, s, 1);
    if (lane == 0) {
        float eu = __expf(-LOGT - __logf(s + evtot));
        g_eu[bh * Tn + i] = eu;
        sred[w] = eu;
    }
    __syncthreads();
    if (tid == 0)
        atomicAdd(&g_tots[slot_out * BHn + bh],
                  sred[0] + sred[1] + sred[2] + sred[3] + sred[4] + sred[5] + sred[6] + sred[7]);
}

// ---------------- Sinkhorn col pass: partial over i-chunks ----------------
__global__ void sink_col_part() {
    int cb = blockIdx.x;
    int ic = blockIdx.y;
    int bh = blockIdx.z;
    int tid = threadIdx.x;
    int j0 = cb * 512 + tid * 2;
    int is = ic * 256;
    float* part = g_cpart + (size_t)(ic * BHn + bh) * Tn;
    if (cb * 512 >= is + 256) {
        part[j0] = 0.f;
        part[j0 + 1] = 0.f;
        return;
    }
    __shared__ float seu[256];
    seu[tid] = g_eu[bh * Tn + is + tid];
    __syncthreads();
    const __half* base = g_c + (size_t)bh * Tn * Tn + j0;
    float s0 = 0.f, s1 = 0.f;
    #pragma unroll 4
    for (int r = 0; r < 256; r++) {
        __half2 hh = *(const __half2*)(base + (size_t)(is + r) * Tn);
        float2 f = __half22float2(hh);
        float ui = seu[r];
        s0 += f.x * ui;
        s1 += f.y * ui;
    }
    part[j0] = s0;
    part[j0 + 1] = s1;
}

// ---------------- mid col finalize ----------------
__global__ void sink_col_fin(int slot_in, int slot_out) {
    int bh = blockIdx.y;
    int tid = threadIdx.x;
    int j = blockIdx.x * 256 + tid;
    float s = 0.f;
    #pragma unroll
    for (int ic = 0; ic < 8; ic++)
        s += g_cpart[(size_t)(ic * BHn + bh) * Tn + j];
    float ev = __expf(-LOGT - __logf(s + g_tots[slot_in * BHn + bh]));
    g_ev[bh * Tn + j] = ev;
    __shared__ float red[256];
    red[tid] = ev; __syncthreads();
    for (int o = 128; o > 0; o >>= 1) { if (tid < o) red[tid] += red[tid + o]; __syncthreads(); }
    if (tid == 0) atomicAdd(&g_tots[slot_out * BHn + bh], red[0]);
}

// ---------------- final col pass fused with W build ----------------
__global__ void sink_col_finw(int slot_in) {
    int bh = blockIdx.y;
    int tid = threadIdx.x;
    int jb = blockIdx.x * 256;
    int j = jb + tid;
    int b = bh / Hn, h = bh % Hn;
    float s = 0.f;
    #pragma unroll
    for (int ic = 0; ic < 8; ic++)
        s += g_cpart[(size_t)(ic * BHn + bh) * Tn + j];
    float ev = __expf(-LOGT - __logf(s + g_tots[slot_in * BHn + bh]));
    __shared__ float sev[256];
    sev[tid] = ev;
    __syncthreads();
    int d = tid & 63, rr = tid >> 6;
    const float* Vbase = g_qkv + (size_t)b * Tn * N3 + 2 * Cn + h * HDn + d;
    float part = 0.f;
    for (int r = rr; r < 256; r += 4) {
        int jj = jb + r;
        float w = sev[r] * Vbase[(size_t)jj * N3];
        part += w;
        float ws = fminf(fmaxf(w * WSCALE, -32768.f), 32768.f);
        __half hi = __float2half(ws);
        g_wh[((size_t)bh * Tn + jj) * HDn + d] = hi;
        g_wl[((size_t)bh * Tn + jj) * HDn + d] = __float2half(ws - __half2float(hi));
    }
    __shared__ float red[256];
    red[tid] = part;
    __syncthreads();
    if (tid < 128) red[tid] += red[tid + 128];
    __syncthreads();
    if (tid < 64) atomicAdd(&g_wtot[bh * HDn + tid], red[tid] + red[tid + 64]);
}

// ---------------- pi@V via fp16 TC (static smem, 2 CTA/SM); y as bf16 hi/lo ----------------
__global__ void __launch_bounds__(256) pi_v_tc() {
    int bh = blockIdx.y;
    int b = bh / Hn, h = bh % Hn;
    int it = gridDim.x - 1 - blockIdx.x;
    int i0 = it * 128;
    __shared__ __half sA[128][72];
    __shared__ __half sWh[64][72], sWl[64][72];
    int tid = threadIdx.x, wid = tid >> 5, lane = tid & 31;
    int wm = wid & 3, wn = wid >> 2;
    float acc[2][4][4] = {};
    unsigned aA = (unsigned)__cvta_generic_to_shared(&sA[0][0]);
    unsigned aWh = (unsigned)__cvta_generic_to_shared(&sWh[0][0]);
    unsigned aWl = (unsigned)__cvta_generic_to_shared(&sWl[0][0]);

    for (int jc = 0; jc < i0 + 128; jc += 64) {
        if (jc) __syncthreads();
        #pragma unroll
        for (int z = 0; z < 4; z++) {
            int idx = z * 256 + tid;
            int r = idx >> 3, c8 = (idx & 7) * 8;
            *(uint4*)&sA[r][c8] = *(const uint4*)(g_c + ((size_t)bh * Tn + i0 + r) * Tn + jc + c8);
        }
        #pragma unroll
        for (int z = 0; z < 2; z++) {
            int idx = z * 256 + tid;
            int r = idx >> 3, c8 = (idx & 7) * 8;
            *(uint4*)&sWh[r][c8] = *(const uint4*)(g_wh + ((size_t)bh * Tn + jc + r) * HDn + c8);
            *(uint4*)&sWl[r][c8] = *(const uint4*)(g_wl + ((size_t)bh * Tn + jc + r) * HDn + c8);
        }
        __syncthreads();
        #pragma unroll
        for (int kh = 0; kh < 64; kh += 16) {
            unsigned a_[2][4];
            #pragma unroll
            for (int mt = 0; mt < 2; mt++) {
                unsigned off = ((unsigned)((wm * 32 + mt * 16 + (lane & 15)) * 72 + kh + 8 * (lane >> 4))) * 2;
                ldmx4(aA + off, a_[mt][0], a_[mt][1], a_[mt][2], a_[mt][3]);
            }
            #pragma unroll
            for (int nq = 0; nq < 2; nq++) {
                int n0 = wn * 32 + nq * 16;
                unsigned boff = ((unsigned)((kh + (lane & 7) + 8 * ((lane >> 3) & 1)) * 72 + n0 + 8 * (lane >> 4))) * 2;
                unsigned bh0, bh1, bh2, bh3, bl0, bl1, bl2, bl3;
                ldmx4t(aWh + boff, bh0, bh1, bh2, bh3);
                ldmx4t(aWl + boff, bl0, bl1, bl2, bl3);
                #pragma unroll
                for (int mt = 0; mt < 2; mt++) {
                    mma_f16(acc[mt][2 * nq],     a_[mt][0], a_[mt][1], a_[mt][2], a_[mt][3], bh0, bh1);
                    mma_f16(acc[mt][2 * nq],     a_[mt][0], a_[mt][1], a_[mt][2], a_[mt][3], bl0, bl1);
                    mma_f16(acc[mt][2 * nq + 1], a_[mt][0], a_[mt][1], a_[mt][2], a_[mt][3], bh2, bh3);
                    mma_f16(acc[mt][2 * nq + 1], a_[mt][0], a_[mt][1], a_[mt][2], a_[mt][3], bl2, bl3);
                }
            }
        }
    }
    #pragma unroll
    for (int mt = 0; mt < 2; mt++) {
        #pragma unroll
        for (int f = 0; f < 4; f++) {
            float* cc = acc[mt][f];
            int r = i0 + wm * 32 + mt * 16 + (lane >> 2);
            int d = wn * 32 + f * 8 + 2 * (lane & 3);
            float wt0 = g_wtot[bh * HDn + d], wt1 = g_wtot[bh * HDn + d + 1];
            float eu0 = g_eu[bh * Tn + r] * 2048.f;
            float eu1 = g_eu[bh * Tn + r + 8] * 2048.f;
            float y0 = (cc[0] * WINV + wt0) * eu0;
            float y1 = (cc[1] * WINV + wt1) * eu0;
            float y2 = (cc[2] * WINV + wt0) * eu1;
            float y3 = (cc[3] * WINV + wt1) * eu1;
            size_t base = ((size_t)(b * Tn) + r) * Cn + h * HDn + d;
            __nv_bfloat16 h0 = __float2bfloat16(y0), h1 = __float2bfloat16(y1);
            __nv_bfloat16 h2 = __float2bfloat16(y2), h3 = __float2bfloat16(y3);
            g_ah[base] = h0;
            g_ah[base + 1] = h1;
            g_ah[base + (size_t)8 * Cn] = h2;
            g_ah[base + (size_t)8 * Cn + 1] = h3;
            g_al[base] = __float2bfloat16(y0 - __bfloat162float(h0));
            g_al[base + 1] = __float2bfloat16(y1 - __bfloat162float(h1));
            g_al[base + (size_t)8 * Cn] = __float2bfloat16(y2 - __bfloat162float(h2));
            g_al[base + (size_t)8 * Cn + 1] = __float2bfloat16(y3 - __bfloat162float(h3));
        }
    }
}

// ---------------- launch ----------------
extern "C" void kernel_launch(void* const* d_in, const int* in_sizes, int n_in,
                              void* d_out, int out_size) {
    const float* x      = (const float*)d_in[0];
    const float* t      = (const float*)d_in[1];
    const float* ln1_w  = (const float*)d_in[2];
    const float* ln1_b  = (const float*)d_in[3];
    const float* attn_w = (const float*)d_in[4];
    const float* attn_b = (const float*)d_in[5];
    const float* proj_w = (const float*)d_in[6];
    const float* proj_b = (const float*)d_in[7];
    const float* ln2_w  = (const float*)d_in[8];
    const float* ln2_b  = (const float*)d_in[9];
    const float* fc_w   = (const float*)d_in[10];
    const float* fc_b   = (const float*)d_in[11];
    const float* fc2_w  = (const float*)d_in[12];
    const float* fc2_b  = (const float*)d_in[13];
    float* out = (float*)d_out;

    float *p_qkv, *p_h;
    __nv_bfloat16 *p_ah, *p_al, *p_a2h, *p_a2l, *p_bh, *p_bl;
    cudaGetSymbolAddress((void**)&p_qkv, g_qkv);
    cudaGetSymbolAddress((void**)&p_h,   g_h);
    cudaGetSymbolAddress((void**)&p_ah,  g_ah);
    cudaGetSymbolAddress((void**)&p_al,  g_al);
    cudaGetSymbolAddress((void**)&p_a2h, g_a2h);
    cudaGetSymbolAddress((void**)&p_a2l, g_a2l);
    cudaGetSymbolAddress((void**)&p_bh,  g_bh);
    cudaGetSymbolAddress((void**)&p_bl,  g_bl);

    static int smem_set = 0;
    const int GSM = 38912;
    if (!smem_set) {
        cudaFuncSetAttribute(gemm64s, cudaFuncAttributeMaxDynamicSharedMemorySize, GSM);
        smem_set = 1;
    }

    // ---- setup (zeroing fused into conv_w_all) ----
    conv_w_all<<<(WTOTAL / 4 + 255) / 256, 256>>>(attn_w, proj_w, fc_w, fc2_w);

    // ---- attention sub-block ----
    ln_bf<<<ROWS, 256>>>(x, t, ln1_w, ln1_b, p_ah, p_al);
    gemm64s<<<dim3(N3 / 64, ROWS / 64), 128, GSM>>>(p_ah, p_al, p_bh + WOFF_QKV, p_bl + WOFF_QKV, attn_b,
                                                    p_qkv, nullptr, nullptr, ROWS, N3, KA_LN, 0, 2);
    score_tc<<<dim3(136, BHn), 256>>>();
    em1_row<<<dim3(Tn, BHn), 256>>>();

    // sinkhorn remaining 5 passes
    sink_col_part<<<dim3(4, 8, BHn), 256>>>();
    sink_col_fin<<<dim3(8, BHn), 256>>>(0, 1);
    sink_row_f<<<dim3(Tn / 8, BHn), 256>>>(1, 2);
    sink_col_part<<<dim3(4, 8, BHn), 256>>>();
    sink_col_fin<<<dim3(8, BHn), 256>>>(2, 3);
    sink_row_f<<<dim3(Tn / 8, BHn), 256>>>(3, 4);
    sink_col_part<<<dim3(4, 8, BHn), 256>>>();
    sink_col_finw<<<dim3(8, BHn), 256>>>(4);

    pi_v_tc<<<dim3(Tn / 128, BHn), 256>>>();

    // proj
    gemm64s<<<dim3(Cn / 64, ROWS / 64), 128, GSM>>>(p_ah, p_al, p_bh + WOFF_PRJ, p_bl + WOFF_PRJ, proj_b,
                                                    p_h, nullptr, nullptr, ROWS, Cn, Cn, 0, 0);

    // ---- MLP sub-block ----
    ln_bf<<<ROWS, 256>>>(p_h, t, ln2_w, ln2_b, p_ah, p_al);
    gemm64s<<<dim3(N4 / 64, ROWS / 64), 128, GSM>>>(p_ah, p_al, p_bh + WOFF_FC, p_bl + WOFF_FC, fc_b,
                                                    nullptr, p_a2h, p_a2l, ROWS, N4, KA_LN, 1, 1);
    gemm64s<<<dim3(Cn / 64, ROWS / 64), 128, GSM>>>(p_a2h, p_a2l, p_bh + WOFF_FC2, p_bl + WOFF_FC2, fc2_b,
                                                    out, nullptr, nullptr, ROWS, Cn, N4, 0, 0);
}

// round 17
// speedup vs baseline: 1.1680x; 1.0110x over previous
#include <cuda_runtime.h>
#include <cuda_fp16.h>
#include <cuda_bf16.h>
#include <math.h>

#define Tn 2048
#define Cn 384
#define Hn 6
#define HDn 64
#define Bn 2
#define BHn 12
#define ROWS 4096
#define C1 385
#define KA_LN 416
#define N3 1152
#define N4 1536
#define LOGT 7.62461899f
#define WSCALE 512.f
#define WINV   (1.f / 512.f)

#define WOFF_QKV 0
#define WSZ_QKV  (KA_LN * N3)
#define WOFF_PRJ (WOFF_QKV + WSZ_QKV)
#define WSZ_PRJ  (Cn * Cn)
#define WOFF_FC  (WOFF_PRJ + WSZ_PRJ)
#define WSZ_FC   (KA_LN * N4)
#define WOFF_FC2 (WOFF_FC + WSZ_FC)
#define WSZ_FC2  (N4 * Cn)
#define WTOTAL   (WOFF_FC2 + WSZ_FC2)

// ---------------- scratch ----------------
__device__ __align__(16) float g_qkv[ROWS * N3];
__device__ __align__(16) __half g_e[(size_t)BHn * Tn * Tn];
__device__ __align__(16) __half g_c[(size_t)BHn * Tn * Tn];
__device__ __align__(16) __nv_bfloat16 g_qh[ROWS * Cn];
__device__ __align__(16) __nv_bfloat16 g_ql[ROWS * Cn];
__device__ __align__(16) __nv_bfloat16 g_kh[ROWS * Cn];
__device__ __align__(16) __nv_bfloat16 g_kl[ROWS * Cn];
__device__ __align__(16) __half g_wh[BHn * Tn * HDn];
__device__ __align__(16) __half g_wl[BHn * Tn * HDn];
__device__ float g_rowsum[BHn * Tn];
__device__ float g_eu[BHn * Tn];
__device__ float g_ev[BHn * Tn];
__device__ float g_tots[8 * BHn];
__device__ float g_wtot[BHn * HDn];
__device__ __align__(16) float g_cpart[8 * BHn * Tn];
__device__ __align__(16) float g_h[ROWS * Cn];
__device__ __align__(16) __nv_bfloat16 g_ah[ROWS * N4];
__device__ __align__(16) __nv_bfloat16 g_al[ROWS * N4];
__device__ __align__(16) __nv_bfloat16 g_a2h[ROWS * N4];
__device__ __align__(16) __nv_bfloat16 g_a2l[ROWS * N4];
__device__ __align__(16) __nv_bfloat16 g_bh[WTOTAL];
__device__ __align__(16) __nv_bfloat16 g_bl[WTOTAL];

// ---------------- helpers ----------------
__device__ __forceinline__ void ldmx4(unsigned addr, unsigned& r0, unsigned& r1, unsigned& r2, unsigned& r3) {
    asm volatile("ldmatrix.sync.aligned.m8n8.x4.shared.b16 {%0,%1,%2,%3},[%4];"
                 : "=r"(r0), "=r"(r1), "=r"(r2), "=r"(r3) : "r"(addr));
}
__device__ __forceinline__ void ldmx4t(unsigned addr, unsigned& r0, unsigned& r1, unsigned& r2, unsigned& r3) {
    asm volatile("ldmatrix.sync.aligned.m8n8.x4.trans.shared.b16 {%0,%1,%2,%3},[%4];"
                 : "=r"(r0), "=r"(r1), "=r"(r2), "=r"(r3) : "r"(addr));
}
__device__ __forceinline__ void mma_bf16(float* c, unsigned a0, unsigned a1, unsigned a2, unsigned a3,
                                         unsigned b0, unsigned b1) {
    asm volatile("mma.sync.aligned.m16n8k16.row.col.f32.bf16.bf16.f32 "
                 "{%0,%1,%2,%3},{%4,%5,%6,%7},{%8,%9},{%0,%1,%2,%3};"
                 : "+f"(c[0]), "+f"(c[1]), "+f"(c[2]), "+f"(c[3])
                 : "r"(a0), "r"(a1), "r"(a2), "r"(a3), "r"(b0), "r"(b1));
}
__device__ __forceinline__ void mma_f16(float* c, unsigned a0, unsigned a1, unsigned a2, unsigned a3,
                                        unsigned b0, unsigned b1) {
    asm volatile("mma.sync.aligned.m16n8k16.row.col.f32.f16.f16.f32 "
                 "{%0,%1,%2,%3},{%4,%5,%6,%7},{%8,%9},{%0,%1,%2,%3};"
                 : "+f"(c[0]), "+f"(c[1]), "+f"(c[2]), "+f"(c[3])
                 : "r"(a0), "r"(a1), "r"(a2), "r"(a3), "r"(b0), "r"(b1));
}
__device__ __forceinline__ void cpa16(unsigned dst, const void* src) {
    asm volatile("cp.async.cg.shared.global [%0],[%1],16;" :: "r"(dst), "l"(src));
}
#define CPA_COMMIT asm volatile("cp.async.commit_group;")
#define CPA_WAIT1  asm volatile("cp.async.wait_group 1;")

__device__ __forceinline__ float em1p(float x) {
    float t = fmaf(x, 0.125f, 1.f);
    t = fmaf(x * 0.14285714f, t, 1.f);
    t = fmaf(x * 0.16666667f, t, 1.f);
    t = fmaf(x * 0.2f,        t, 1.f);
    t = fmaf(x * 0.25f,       t, 1.f);
    t = fmaf(x * 0.33333333f, t, 1.f);
    t = fmaf(x * 0.5f,        t, 1.f);
    return x * t;
}

// ---------------- weights -> bf16 hi/lo (+ fused zeroing) ----------------
__global__ void conv_w_all(const float* __restrict__ w0, const float* __restrict__ w1,
                           const float* __restrict__ w2, const float* __restrict__ w3) {
    int idx = blockIdx.x * 256 + threadIdx.x;
    if (idx < BHn * Tn) g_rowsum[idx] = 0.f;
    if (idx < BHn * HDn) g_wtot[idx] = 0.f;
    if (idx < 8 * BHn) g_tots[idx] = 0.f;
    int e = idx * 4;
    if (e >= WTOTAL) return;
    const float* src;
    int K, N, local;
    if (e < WOFF_PRJ)       { src = w0; K = C1;  N = N3; local = e - WOFF_QKV; }
    else if (e < WOFF_FC)   { src = w1; K = Cn;  N = Cn; local = e - WOFF_PRJ; }
    else if (e < WOFF_FC2)  { src = w2; K = C1;  N = N4; local = e - WOFF_FC;  }
    else                    { src = w3; K = N4;  N = Cn; local = e - WOFF_FC2; }
    int row = local / N, col = local % N;
    float4 v = (row < K) ? *(const float4*)(src + (size_t)row * N + col)
                         : make_float4(0.f, 0.f, 0.f, 0.f);
    __nv_bfloat16 h0 = __float2bfloat16(v.x), h1 = __float2bfloat16(v.y);
    __nv_bfloat16 h2 = __float2bfloat16(v.z), h3 = __float2bfloat16(v.w);
    __nv_bfloat16 hbuf[4] = {h0, h1, h2, h3};
    __nv_bfloat16 lbuf[4] = {
        __float2bfloat16(v.x - __bfloat162float(h0)), __float2bfloat16(v.y - __bfloat162float(h1)),
        __float2bfloat16(v.z - __bfloat162float(h2)), __float2bfloat16(v.w - __bfloat162float(h3))};
    *(uint2*)(g_bh + e) = *(uint2*)hbuf;
    *(uint2*)(g_bl + e) = *(uint2*)lbuf;
}

// ---------------- LayerNorm -> bf16 hi/lo ----------------
__global__ void ln_bf(const float* __restrict__ x, const float* __restrict__ t,
                      const float* __restrict__ w, const float* __restrict__ bb,
                      __nv_bfloat16* __restrict__ oh, __nv_bfloat16* __restrict__ ol) {
    int row = blockIdx.x;
    int tid = threadIdx.x;
    __shared__ float sx[C1];
    __shared__ float red[256];
    float s1 = 0.f;
    for (int c = tid; c < C1; c += 256) {
        float v = (c < Cn) ? x[(size_t)row * Cn + c] : t[0];
        sx[c] = v;
        s1 += v;
    }
    red[tid] = s1; __syncthreads();
    for (int o = 128; o > 0; o >>= 1) { if (tid < o) red[tid] += red[tid + o]; __syncthreads(); }
    float mean = red[0] * (1.f / C1);
    __syncthreads();
    float s2 = 0.f;
    for (int c = tid; c < C1; c += 256) { float d = sx[c] - mean; s2 += d * d; }
    red[tid] = s2; __syncthreads();
    for (int o = 128; o > 0; o >>= 1) { if (tid < o) red[tid] += red[tid + o]; __syncthreads(); }
    float rs = rsqrtf(red[0] * (1.f / C1) + 1e-5f);
    for (int c = tid; c < C1; c += 256) {
        float v = (sx[c] - mean) * rs * w[c] + bb[c];
        __nv_bfloat16 hi = __float2bfloat16(v);
        oh[(size_t)row * KA_LN + c] = hi;
        ol[(size_t)row * KA_LN + c] = __float2bfloat16(v - __bfloat162float(hi));
    }
    if (tid < KA_LN - C1) {
        oh[(size_t)row * KA_LN + C1 + tid] = __float2bfloat16(0.f);
        ol[(size_t)row * KA_LN + C1 + tid] = __float2bfloat16(0.f);
    }
}

// ---------------- unified pipelined bf16 GEMM, 64x64 tile, 128 threads ----------------
__global__ void __launch_bounds__(128) gemm64s(const __nv_bfloat16* __restrict__ Ah,
                                               const __nv_bfloat16* __restrict__ Al,
                                               const __nv_bfloat16* __restrict__ Bh,
                                               const __nv_bfloat16* __restrict__ Bl,
                                               const float* __restrict__ bias,
                                               float* __restrict__ outF,
                                               __nv_bfloat16* __restrict__ oAh,
                                               __nv_bfloat16* __restrict__ oAl,
                                               int M, int N, int Ka, int act, int obf) {
    extern __shared__ __nv_bfloat16 dyn[];
    __nv_bfloat16* sA = dyn;
    __nv_bfloat16* sB = dyn + 4 * 2560;
    int tid = threadIdx.x;
    int wid = tid >> 5, lane = tid & 31;
    int wm = wid & 1, wn = wid >> 1;
    int bm = blockIdx.y * 64, bn = blockIdx.x * 64;
    float acc[2][4][4] = {};
    unsigned sAu = (unsigned)__cvta_generic_to_shared(sA);
    unsigned sBu = (unsigned)__cvta_generic_to_shared(sB);

    int nk = Ka >> 5;
    auto load_stage = [&](int kt, int st) {
        unsigned aH = sAu + (st * 2 + 0) * 2560 * 2;
        unsigned aL = sAu + (st * 2 + 1) * 2560 * 2;
        unsigned bH = sBu + (st * 2 + 0) * 2304 * 2;
        unsigned bL = sBu + (st * 2 + 1) * 2304 * 2;
        int k0 = kt * 32;
        #pragma unroll
        for (int z = 0; z < 2; z++) {
            int idx = z * 128 + tid;
            int row = idx >> 2, cq = (idx & 3) * 8;
            cpa16(aH + (row * 40 + cq) * 2, Ah + (size_t)(bm + row) * Ka + k0 + cq);
            cpa16(aL + (row * 40 + cq) * 2, Al + (size_t)(bm + row) * Ka + k0 + cq);
        }
        #pragma unroll
        for (int z = 0; z < 2; z++) {
            int idx = z * 128 + tid;
            int row = idx >> 3, cq = (idx & 7) * 8;
            cpa16(bH + (row * 72 + cq) * 2, Bh + (size_t)(k0 + row) * N + bn + cq);
            cpa16(bL + (row * 72 + cq) * 2, Bl + (size_t)(k0 + row) * N + bn + cq);
        }
    };

    load_stage(0, 0);
    CPA_COMMIT;
    for (int kt = 0; kt < nk; kt++) {
        int cur = kt & 1;
        if (kt + 1 < nk) load_stage(kt + 1, cur ^ 1);
        CPA_COMMIT;
        CPA_WAIT1;
        __syncthreads();
        unsigned aH = sAu + (cur * 2 + 0) * 2560 * 2;
        unsigned aL = sAu + (cur * 2 + 1) * 2560 * 2;
        unsigned bH = sBu + (cur * 2 + 0) * 2304 * 2;
        unsigned bL = sBu + (cur * 2 + 1) * 2304 * 2;
        #pragma unroll
        for (int kh = 0; kh < 32; kh += 16) {
            unsigned ah[2][4], al[2][4];
            #pragma unroll
            for (int mt = 0; mt < 2; mt++) {
                unsigned off = ((unsigned)((wm * 32 + mt * 16 + (lane & 15)) * 40 + kh + (lane >> 4) * 8)) * 2;
                ldmx4(aH + off, ah[mt][0], ah[mt][1], ah[mt][2], ah[mt][3]);
                ldmx4(aL + off, al[mt][0], al[mt][1], al[mt][2], al[mt][3]);
            }
            #pragma unroll
            for (int nq = 0; nq < 2; nq++) {
                int n0 = wn * 32 + nq * 16;
                unsigned boff = ((unsigned)((kh + (lane & 7) + 8 * ((lane >> 3) & 1)) * 72 + n0 + 8 * (lane >> 4))) * 2;
                unsigned bh0, bh1, bh2, bh3, bl0, bl1, bl2, bl3;
                ldmx4t(bH + boff, bh0, bh1, bh2, bh3);
                ldmx4t(bL + boff, bl0, bl1, bl2, bl3);
                #pragma unroll
                for (int mt = 0; mt < 2; mt++) {
                    mma_bf16(acc[mt][2 * nq],     ah[mt][0], ah[mt][1], ah[mt][2], ah[mt][3], bh0, bh1);
                    mma_bf16(acc[mt][2 * nq],     ah[mt][0], ah[mt][1], ah[mt][2], ah[mt][3], bl0, bl1);
                    mma_bf16(acc[mt][2 * nq],     al[mt][0], al[mt][1], al[mt][2], al[mt][3], bh0, bh1);
                    mma_bf16(acc[mt][2 * nq + 1], ah[mt][0], ah[mt][1], ah[mt][2], ah[mt][3], bh2, bh3);
                    mma_bf16(acc[mt][2 * nq + 1], ah[mt][0], ah[mt][1], ah[mt][2], ah[mt][3], bl2, bl3);
                    mma_bf16(acc[mt][2 * nq + 1], al[mt][0], al[mt][1], al[mt][2], al[mt][3], bh2, bh3);
                }
            }
        }
        __syncthreads();
    }
    #pragma unroll
    for (int mt = 0; mt < 2; mt++) {
        #pragma unroll
        for (int nt = 0; nt < 4; nt++) {
            float* cc = acc[mt][nt];
            int r = bm + wm * 32 + mt * 16 + (lane >> 2);
            int cn = bn + wn * 32 + (nt >> 1) * 16 + (nt & 1) * 8 + (lane & 3) * 2;
            float b0 = bias[cn], b1 = bias[cn + 1];
            float v0 = cc[0] + b0, v1 = cc[1] + b1;
            float v2 = cc[2] + b0, v3 = cc[3] + b1;
            if (act == 1) {
                v0 = 0.5f * v0 * (1.f + erff(v0 * 0.70710678f));
                v1 = 0.5f * v1 * (1.f + erff(v1 * 0.70710678f));
                v2 = 0.5f * v2 * (1.f + erff(v2 * 0.70710678f));
                v3 = 0.5f * v3 * (1.f + erff(v3 * 0.70710678f));
            }
            if (obf == 1) {
                __nv_bfloat16 h0 = __float2bfloat16(v0), h1 = __float2bfloat16(v1);
                __nv_bfloat16 h2 = __float2bfloat16(v2), h3 = __float2bfloat16(v3);
                oAh[(size_t)r * N + cn] = h0;
                oAh[(size_t)r * N + cn + 1] = h1;
                oAh[(size_t)(r + 8) * N + cn] = h2;
                oAh[(size_t)(r + 8) * N + cn + 1] = h3;
                oAl[(size_t)r * N + cn] = __float2bfloat16(v0 - __bfloat162float(h0));
                oAl[(size_t)r * N + cn + 1] = __float2bfloat16(v1 - __bfloat162float(h1));
                oAl[(size_t)(r + 8) * N + cn] = __float2bfloat16(v2 - __bfloat162float(h2));
                oAl[(size_t)(r + 8) * N + cn + 1] = __float2bfloat16(v3 - __bfloat162float(h3));
            } else {
                outF[(size_t)r * N + cn] = v0;
                outF[(size_t)r * N + cn + 1] = v1;
                outF[(size_t)(r + 8) * N + cn] = v2;
                outF[(size_t)(r + 8) * N + cn + 1] = v3;
                if (obf == 2 && cn < 2 * Cn) {
                    int isK = cn >= Cn;
                    int c2 = cn - isK * Cn;
                    __nv_bfloat16* H = isK ? g_kh : g_qh;
                    __nv_bfloat16* L = isK ? g_kl : g_ql;
                    __nv_bfloat16 h0 = __float2bfloat16(v0), h1 = __float2bfloat16(v1);
                    __nv_bfloat16 h2 = __float2bfloat16(v2), h3 = __float2bfloat16(v3);
                    H[(size_t)r * Cn + c2] = h0;
                    H[(size_t)r * Cn + c2 + 1] = h1;
                    H[(size_t)(r + 8) * Cn + c2] = h2;
                    H[(size_t)(r + 8) * Cn + c2 + 1] = h3;
                    L[(size_t)r * Cn + c2] = __float2bfloat16(v0 - __bfloat162float(h0));
                    L[(size_t)r * Cn + c2 + 1] = __float2bfloat16(v1 - __bfloat162float(h1));
                    L[(size_t)(r + 8) * Cn + c2] = __float2bfloat16(v2 - __bfloat162float(h2));
                    L[(size_t)(r + 8) * Cn + c2 + 1] = __float2bfloat16(v3 - __bfloat162float(h3));
                }
            }
        }
    }
}

// ---------------- TC scores + fused exp + inline row sums (triangular grid) ----------------
__global__ void __launch_bounds__(256, 2) score_tc() {
    int li = blockIdx.x, bh = blockIdx.y;
    int it = (int)((sqrtf(8.f * li + 1.f) - 1.f) * 0.5f);
    while ((it + 1) * (it + 2) / 2 <= li) it++;
    while (it * (it + 1) / 2 > li) it--;
    int jt = li - it * (it + 1) / 2;
    int b = bh / Hn, h = bh % Hn;
    __shared__ __nv_bfloat16 sQh[128][40], sQl[128][40], sKh[128][40], sKl[128][40];
    int tid = threadIdx.x, wid = tid >> 5, lane = tid & 31;
    int wm = wid & 3, wn = wid >> 2;
    float acc[2][8][4] = {};
    unsigned aQh = (unsigned)__cvta_generic_to_shared(&sQh[0][0]);
    unsigned aQl = (unsigned)__cvta_generic_to_shared(&sQl[0][0]);
    unsigned aKh = (unsigned)__cvta_generic_to_shared(&sKh[0][0]);
    unsigned aKl = (unsigned)__cvta_generic_to_shared(&sKl[0][0]);
    size_t qbase = ((size_t)(b * Tn + it * 128)) * Cn + h * HDn;
    size_t kbase = ((size_t)(b * Tn + jt * 128)) * Cn + h * HDn;

    for (int ks = 0; ks < 2; ks++) {
        if (ks) __syncthreads();
        #pragma unroll
        for (int z = 0; z < 2; z++) {
            int idx = z * 256 + tid;
            int r = idx >> 2, c8 = (idx & 3) * 8;
            *(uint4*)&sQh[r][c8] = *(const uint4*)(g_qh + qbase + (size_t)r * Cn + ks * 32 + c8);
            *(uint4*)&sQl[r][c8] = *(const uint4*)(g_ql + qbase + (size_t)r * Cn + ks * 32 + c8);
            *(uint4*)&sKh[r][c8] = *(const uint4*)(g_kh + kbase + (size_t)r * Cn + ks * 32 + c8);
            *(uint4*)&sKl[r][c8] = *(const uint4*)(g_kl + kbase + (size_t)r * Cn + ks * 32 + c8);
        }
        __syncthreads();
        #pragma unroll
        for (int kh = 0; kh < 32; kh += 16) {
            unsigned qh_[2][4], ql_[2][4];
            #pragma unroll
            for (int mt = 0; mt < 2; mt++) {
                unsigned off = ((unsigned)((wm * 32 + mt * 16 + (lane & 15)) * 40 + kh + 8 * (lane >> 4))) * 2;
                ldmx4(aQh + off, qh_[mt][0], qh_[mt][1], qh_[mt][2], qh_[mt][3]);
                ldmx4(aQl + off, ql_[mt][0], ql_[mt][1], ql_[mt][2], ql_[mt][3]);
            }
            #pragma unroll
            for (int nq = 0; nq < 4; nq++) {
                int n0 = wn * 64 + nq * 16;
                unsigned boff = ((unsigned)((n0 + (lane & 15)) * 40 + kh + 8 * (lane >> 4))) * 2;
                unsigned kh0, kh1, kh2, kh3, kl0, kl1, kl2, kl3;
                ldmx4(aKh + boff, kh0, kh1, kh2, kh3);
                ldmx4(aKl + boff, kl0, kl1, kl2, kl3);
                #pragma unroll
                for (int mt = 0; mt < 2; mt++) {
                    mma_bf16(acc[mt][2 * nq],     qh_[mt][0], qh_[mt][1], qh_[mt][2], qh_[mt][3], kh0, kh2);
                    mma_bf16(acc[mt][2 * nq],     qh_[mt][0], qh_[mt][1], qh_[mt][2], qh_[mt][3], kl0, kl2);
                    mma_bf16(acc[mt][2 * nq],     ql_[mt][0], ql_[mt][1], ql_[mt][2], ql_[mt][3], kh0, kh2);
                    mma_bf16(acc[mt][2 * nq + 1], qh_[mt][0], qh_[mt][1], qh_[mt][2], qh_[mt][3], kh1, kh3);
                    mma_bf16(acc[mt][2 * nq + 1], qh_[mt][0], qh_[mt][1], qh_[mt][2], qh_[mt][3], kl1, kl3);
                    mma_bf16(acc[mt][2 * nq + 1], ql_[mt][0], ql_[mt][1], ql_[mt][2], ql_[mt][3], kh1, kh3);
                }
            }
        }
    }
    __half* erow = g_e + (size_t)bh * Tn * Tn;
    float rsum[2][2] = {};
    int diag = (it == jt);
    #pragma unroll
    for (int mt = 0; mt < 2; mt++) {
        #pragma unroll
        for (int f = 0; f < 8; f++) {
            float* cc = acc[mt][f];
            int gi = it * 128 + wm * 32 + mt * 16 + (lane >> 2);
            int gj = jt * 128 + wn * 64 + (f >> 1) * 16 + (f & 1) * 8 + 2 * (lane & 3);
            float e0 = __expf(fminf(cc[0] * 0.125f, 11.f));
            float e1 = __expf(fminf(cc[1] * 0.125f, 11.f));
            float e2 = __expf(fminf(cc[2] * 0.125f, 11.f));
            float e3 = __expf(fminf(cc[3] * 0.125f, 11.f));
            if (diag) {
                if (gj > gi) e0 = 0.f;
                if (gj + 1 > gi) e1 = 0.f;
                if (gj > gi + 8) e2 = 0.f;
                if (gj + 1 > gi + 8) e3 = 0.f;
            }
            rsum[mt][0] += e0 + e1;
            rsum[mt][1] += e2 + e3;
            *(__half2*)(erow + (size_t)gi * Tn + gj) = __floats2half2_rn(e0, e1);
            *(__half2*)(erow + (size_t)(gi + 8) * Tn + gj) = __floats2half2_rn(e2, e3);
        }
    }
    #pragma unroll
    for (int mt = 0; mt < 2; mt++) {
        #pragma unroll
        for (int hh = 0; hh < 2; hh++) {
            float v = rsum[mt][hh];
            v += __shfl_xor_sync(0xffffffffu, v, 1);
            v += __shfl_xor_sync(0xffffffffu, v, 2);
            if ((lane & 3) == 0) {
                int gi = it * 128 + wm * 32 + mt * 16 + (lane >> 2) + hh * 8;
                atomicAdd(&g_rowsum[bh * Tn + gi], v);
            }
        }
    }
}

// ---------------- per row: Em1 = expm1(e/rowsum); eu; eutot -> slot0 ----------------
__global__ void em1_row() {
    int i = blockIdx.x, bh = blockIdx.y;
    int tid = threadIdx.x;
    int lane = tid & 31, wid = tid >> 5;
    float inv = 1.f / g_rowsum[bh * Tn + i];
    const uint4* src = (const uint4*)(g_e + ((size_t)bh * Tn + i) * Tn);
    uint4* dst = (uint4*)(g_c + ((size_t)bh * Tn + i) * Tn);
    int nv = ((i >> 7) + 1) << 4;
    float se = 0.f;
    if (tid < nv) {
        uint4 pk = src[tid];
        const __half2* hp = (const __half2*)&pk;
        uint4 outp;
        __half2* op = (__half2*)&outp;
        #pragma unroll
        for (int z = 0; z < 4; z++) {
            float2 f = __half22float2(hp[z]);
            float a = em1p(f.x * inv);
            float bb = em1p(f.y * inv);
            se += a + bb;
            op[z] = __floats2half2_rn(a, bb);
        }
        dst[tid] = outp;
    }
    se += __shfl_xor_sync(0xffffffffu, se, 16);
    se += __shfl_xor_sync(0xffffffffu, se, 8);
    se += __shfl_xor_sync(0xffffffffu, se, 4);
    se += __shfl_xor_sync(0xffffffffu, se, 2);
    se += __shfl_xor_sync(0xffffffffu, se, 1);
    __shared__ float red[8];
    if (lane == 0) red[wid] = se;
    __syncthreads();
    if (tid == 0) {
        float s = red[0] + red[1] + red[2] + red[3] + red[4] + red[5] + red[6] + red[7];
        float eu = __expf(-LOGT - __logf(s + (float)Tn));
        g_eu[bh * Tn + i] = eu;
        atomicAdd(&g_tots[bh], eu);
    }
}

// ---------------- Sinkhorn row pass: warp-per-row ----------------
__global__ void sink_row_f(int slot_in, int slot_out) {
    int r0 = blockIdx.x * 8, bh = blockIdx.y;
    int tid = threadIdx.x, lane = tid & 31, w = tid >> 5;
    __shared__ float sev[Tn];
    __shared__ float sred[8];
    int jmax = r0 + 8;
    for (int j = tid; j < jmax; j += 256) sev[j] = g_ev[bh * Tn + j];
    float evtot = g_tots[slot_in * BHn + bh];
    __syncthreads();
    int i = r0 + w;
    const uint4* cv = (const uint4*)(g_c + ((size_t)bh * Tn + i) * Tn);
    int nv = (i + 8) >> 3;
    float s = 0.f;
    for (int vi = lane; vi < nv; vi += 32) {
        uint4 pk = cv[vi];
        const __half2* hp = (const __half2*)&pk;
        int jb = vi * 8;
        #pragma unroll
        for (int z = 0; z < 4; z++) {
            float2 f = __half22float2(hp[z]);
            s += f.x * sev[jb + 2 * z] + f.y * sev[jb + 2 * z + 1];
        }
    }
    s += __shfl_xor_sync(0xffffffffu, s, 16);
    s += __shfl_xor_sync(0xffffffffu, s, 8);
    s += __shfl_xor_sync(0xffffffffu, s, 4);
    s += __shfl_xor_sync(0xffffffffu, s, 2);
    s += __shfl_xor_sync(0xffffffffu, s, 1);
    if (lane == 0) {
        float eu = __expf(-LOGT - __logf(s + evtot));
        g_eu[bh * Tn + i] = eu;
        sred[w] = eu;
    }
    __syncthreads();
    if (tid == 0)
        atomicAdd(&g_tots[slot_out * BHn + bh],
                  sred[0] + sred[1] + sred[2] + sred[3] + sred[4] + sred[5] + sred[6] + sred[7]);
}

// ---------------- Sinkhorn col pass: partial over i-chunks ----------------
__global__ void sink_col_part() {
    int cb = blockIdx.x;
    int ic = blockIdx.y;
    int bh = blockIdx.z;
    int tid = threadIdx.x;
    int j0 = cb * 512 + tid * 2;
    int is = ic * 256;
    float* part = g_cpart + (size_t)(ic * BHn + bh) * Tn;
    if (cb * 512 >= is + 256) {
        part[j0] = 0.f;
        part[j0 + 1] = 0.f;
        return;
    }
    __shared__ float seu[256];
    seu[tid] = g_eu[bh * Tn + is + tid];
    __syncthreads();
    const __half* base = g_c + (size_t)bh * Tn * Tn + j0;
    float s0 = 0.f, s1 = 0.f;
    #pragma unroll 4
    for (int r = 0; r < 256; r++) {
        __half2 hh = *(const __half2*)(base + (size_t)(is + r) * Tn);
        float2 f = __half22float2(hh);
        float ui = seu[r];
        s0 += f.x * ui;
        s1 += f.y * ui;
    }
    part[j0] = s0;
    part[j0 + 1] = s1;
}

// ---------------- mid col finalize ----------------
__global__ void sink_col_fin(int slot_in, int slot_out) {
    int bh = blockIdx.y;
    int tid = threadIdx.x;
    int j = blockIdx.x * 256 + tid;
    float s = 0.f;
    #pragma unroll
    for (int ic = 0; ic < 8; ic++)
        s += g_cpart[(size_t)(ic * BHn + bh) * Tn + j];
    float ev = __expf(-LOGT - __logf(s + g_tots[slot_in * BHn + bh]));
    g_ev[bh * Tn + j] = ev;
    __shared__ float red[256];
    red[tid] = ev; __syncthreads();
    for (int o = 128; o > 0; o >>= 1) { if (tid < o) red[tid] += red[tid + o]; __syncthreads(); }
    if (tid == 0) atomicAdd(&g_tots[slot_out * BHn + bh], red[0]);
}

// ---------------- final col pass fused with W build ----------------
__global__ void sink_col_finw(int slot_in) {
    int bh = blockIdx.y;
    int tid = threadIdx.x;
    int jb = blockIdx.x * 256;
    int j = jb + tid;
    int b = bh / Hn, h = bh % Hn;
    float s = 0.f;
    #pragma unroll
    for (int ic = 0; ic < 8; ic++)
        s += g_cpart[(size_t)(ic * BHn + bh) * Tn + j];
    float ev = __expf(-LOGT - __logf(s + g_tots[slot_in * BHn + bh]));
    __shared__ float sev[256];
    sev[tid] = ev;
    __syncthreads();
    int d = tid & 63, rr = tid >> 6;
    const float* Vbase = g_qkv + (size_t)b * Tn * N3 + 2 * Cn + h * HDn + d;
    float part = 0.f;
    for (int r = rr; r < 256; r += 4) {
        int jj = jb + r;
        float w = sev[r] * Vbase[(size_t)jj * N3];
        part += w;
        float ws = fminf(fmaxf(w * WSCALE, -32768.f), 32768.f);
        __half hi = __float2half(ws);
        g_wh[((size_t)bh * Tn + jj) * HDn + d] = hi;
        g_wl[((size_t)bh * Tn + jj) * HDn + d] = __float2half(ws - __half2float(hi));
    }
    __shared__ float red[256];
    red[tid] = part;
    __syncthreads();
    if (tid < 128) red[tid] += red[tid + 128];
    __syncthreads();
    if (tid < 64) atomicAdd(&g_wtot[bh * HDn + tid], red[tid] + red[tid + 64]);
}

// ---------------- pi@V via fp16 TC, 64-row tiles, 128 threads ----------------
__global__ void __launch_bounds__(128) pi_v_tc() {
    int bh = blockIdx.y;
    int b = bh / Hn, h = bh % Hn;
    int it = gridDim.x - 1 - blockIdx.x;   // heavy tiles first
    int i0 = it * 64;
    __shared__ __half sA[64][72];
    __shared__ __half sWh[64][72], sWl[64][72];
    int tid = threadIdx.x, wid = tid >> 5, lane = tid & 31;
    int wm = wid & 1, wn = wid >> 1;       // 2 m-warps x 2 n-warps
    float acc[2][4][4] = {};
    unsigned aA = (unsigned)__cvta_generic_to_shared(&sA[0][0]);
    unsigned aWh = (unsigned)__cvta_generic_to_shared(&sWh[0][0]);
    unsigned aWl = (unsigned)__cvta_generic_to_shared(&sWl[0][0]);

    for (int jc = 0; jc < i0 + 64; jc += 64) {
        if (jc) __syncthreads();
        #pragma unroll
        for (int z = 0; z < 4; z++) {
            int idx = z * 128 + tid;
            int r = idx >> 3, c8 = (idx & 7) * 8;
            *(uint4*)&sA[r][c8] = *(const uint4*)(g_c + ((size_t)bh * Tn + i0 + r) * Tn + jc + c8);
        }
        #pragma unroll
        for (int z = 0; z < 4; z++) {
            int idx = z * 128 + tid;
            int r = idx >> 3, c8 = (idx & 7) * 8;
            *(uint4*)&sWh[r][c8] = *(const uint4*)(g_wh + ((size_t)bh * Tn + jc + r) * HDn + c8);
            *(uint4*)&sWl[r][c8] = *(const uint4*)(g_wl + ((size_t)bh * Tn + jc + r) * HDn + c8);
        }
        __syncthreads();
        #pragma unroll
        for (int kh = 0; kh < 64; kh += 16) {
            unsigned a_[2][4];
            #pragma unroll
            for (int mt = 0; mt < 2; mt++) {
                unsigned off = ((unsigned)((wm * 32 + mt * 16 + (lane & 15)) * 72 + kh + 8 * (lane >> 4))) * 2;
                ldmx4(aA + off, a_[mt][0], a_[mt][1], a_[mt][2], a_[mt][3]);
            }
            #pragma unroll
            for (int nq = 0; nq < 2; nq++) {
                int n0 = wn * 32 + nq * 16;
                unsigned boff = ((unsigned)((kh + (lane & 7) + 8 * ((lane >> 3) & 1)) * 72 + n0 + 8 * (lane >> 4))) * 2;
                unsigned bh0, bh1, bh2, bh3, bl0, bl1, bl2, bl3;
                ldmx4t(aWh + boff, bh0, bh1, bh2, bh3);
                ldmx4t(aWl + boff, bl0, bl1, bl2, bl3);
                #pragma unroll
                for (int mt = 0; mt < 2; mt++) {
                    mma_f16(acc[mt][2 * nq],     a_[mt][0], a_[mt][1], a_[mt][2], a_[mt][3], bh0, bh1);
                    mma_f16(acc[mt][2 * nq],     a_[mt][0], a_[mt][1], a_[mt][2], a_[mt][3], bl0, bl1);
                    mma_f16(acc[mt][2 * nq + 1], a_[mt][0], a_[mt][1], a_[mt][2], a_[mt][3], bh2, bh3);
                    mma_f16(acc[mt][2 * nq + 1], a_[mt][0], a_[mt][1], a_[mt][2], a_[mt][3], bl2, bl3);
                }
            }
        }
    }
    #pragma unroll
    for (int mt = 0; mt < 2; mt++) {
        #pragma unroll
        for (int f = 0; f < 4; f++) {
            float* cc = acc[mt][f];
            int r = i0 + wm * 32 + mt * 16 + (lane >> 2);
            int d = wn * 32 + (f >> 1) * 16 + (f & 1) * 8 + 2 * (lane & 3);
            float wt0 = g_wtot[bh * HDn + d], wt1 = g_wtot[bh * HDn + d + 1];
            float eu0 = g_eu[bh * Tn + r] * 2048.f;
            float eu1 = g_eu[bh * Tn + r + 8] * 2048.f;
            float y0 = (cc[0] * WINV + wt0) * eu0;
            float y1 = (cc[1] * WINV + wt1) * eu0;
            float y2 = (cc[2] * WINV + wt0) * eu1;
            float y3 = (cc[3] * WINV + wt1) * eu1;
            size_t base = ((size_t)(b * Tn) + r) * Cn + h * HDn + d;
            __nv_bfloat16 h0 = __float2bfloat16(y0), h1 = __float2bfloat16(y1);
            __nv_bfloat16 h2 = __float2bfloat16(y2), h3 = __float2bfloat16(y3);
            g_ah[base] = h0;
            g_ah[base + 1] = h1;
            g_ah[base + (size_t)8 * Cn] = h2;
            g_ah[base + (size_t)8 * Cn + 1] = h3;
            g_al[base] = __float2bfloat16(y0 - __bfloat162float(h0));
            g_al[base + 1] = __float2bfloat16(y1 - __bfloat162float(h1));
            g_al[base + (size_t)8 * Cn] = __float2bfloat16(y2 - __bfloat162float(h2));
            g_al[base + (size_t)8 * Cn + 1] = __float2bfloat16(y3 - __bfloat162float(h3));
        }
    }
}

// ---------------- launch ----------------
extern "C" void kernel_launch(void* const* d_in, const int* in_sizes, int n_in,
                              void* d_out, int out_size) {
    const float* x      = (const float*)d_in[0];
    const float* t      = (const float*)d_in[1];
    const float* ln1_w  = (const float*)d_in[2];
    const float* ln1_b  = (const float*)d_in[3];
    const float* attn_w = (const float*)d_in[4];
    const float* attn_b = (const float*)d_in[5];
    const float* proj_w = (const float*)d_in[6];
    const float* proj_b = (const float*)d_in[7];
    const float* ln2_w  = (const float*)d_in[8];
    const float* ln2_b  = (const float*)d_in[9];
    const float* fc_w   = (const float*)d_in[10];
    const float* fc_b   = (const float*)d_in[11];
    const float* fc2_w  = (const float*)d_in[12];
    const float* fc2_b  = (const float*)d_in[13];
    float* out = (float*)d_out;

    float *p_qkv, *p_h;
    __nv_bfloat16 *p_ah, *p_al, *p_a2h, *p_a2l, *p_bh, *p_bl;
    cudaGetSymbolAddress((void**)&p_qkv, g_qkv);
    cudaGetSymbolAddress((void**)&p_h,   g_h);
    cudaGetSymbolAddress((void**)&p_ah,  g_ah);
    cudaGetSymbolAddress((void**)&p_al,  g_al);
    cudaGetSymbolAddress((void**)&p_a2h, g_a2h);
    cudaGetSymbolAddress((void**)&p_a2l, g_a2l);
    cudaGetSymbolAddress((void**)&p_bh,  g_bh);
    cudaGetSymbolAddress((void**)&p_bl,  g_bl);

    static int smem_set = 0;
    const int GSM = 38912;
    if (!smem_set) {
        cudaFuncSetAttribute(gemm64s, cudaFuncAttributeMaxDynamicSharedMemorySize, GSM);
        smem_set = 1;
    }

    // ---- setup (zeroing fused into conv_w_all) ----
    conv_w_all<<<(WTOTAL / 4 + 255) / 256, 256>>>(attn_w, proj_w, fc_w, fc2_w);

    // ---- attention sub-block ----
    ln_bf<<<ROWS, 256>>>(x, t, ln1_w, ln1_b, p_ah, p_al);
    gemm64s<<<dim3(N3 / 64, ROWS / 64), 128, GSM>>>(p_ah, p_al, p_bh + WOFF_QKV, p_bl + WOFF_QKV, attn_b,
                                                    p_qkv, nullptr, nullptr, ROWS, N3, KA_LN, 0, 2);
    score_tc<<<dim3(136, BHn), 256>>>();
    em1_row<<<dim3(Tn, BHn), 256>>>();

    // sinkhorn remaining 5 passes
    sink_col_part<<<dim3(4, 8, BHn), 256>>>();
    sink_col_fin<<<dim3(8, BHn), 256>>>(0, 1);
    sink_row_f<<<dim3(Tn / 8, BHn), 256>>>(1, 2);
    sink_col_part<<<dim3(4, 8, BHn), 256>>>();
    sink_col_fin<<<dim3(8, BHn), 256>>>(2, 3);
    sink_row_f<<<dim3(Tn / 8, BHn), 256>>>(3, 4);
    sink_col_part<<<dim3(4, 8, BHn), 256>>>();
    sink_col_finw<<<dim3(8, BHn), 256>>>(4);

    pi_v_tc<<<dim3(Tn / 64, BHn), 128>>>();

    // proj
    gemm64s<<<dim3(Cn / 64, ROWS / 64), 128, GSM>>>(p_ah, p_al, p_bh + WOFF_PRJ, p_bl + WOFF_PRJ, proj_b,
                                                    p_h, nullptr, nullptr, ROWS, Cn, Cn, 0, 0);

    // ---- MLP sub-block ----
    ln_bf<<<ROWS, 256>>>(p_h, t, ln2_w, ln2_b, p_ah, p_al);
    gemm64s<<<dim3(N4 / 64, ROWS / 64), 128, GSM>>>(p_ah, p_al, p_bh + WOFF_FC, p_bl + WOFF_FC, fc_b,
                                                    nullptr, p_a2h, p_a2l, ROWS, N4, KA_LN, 1, 1);
    gemm64s<<<dim3(Cn / 64, ROWS / 64), 128, GSM>>>(p_a2h, p_a2l, p_bh + WOFF_FC2, p_bl + WOFF_FC2, fc2_b,
                                                    out, nullptr, nullptr, ROWS, Cn, N4, 0, 0);
}